// round 4
// baseline (speedup 1.0000x reference)
#include <cuda_runtime.h>
#include <math.h>
#include <stdint.h>

#define B_SZ 4
#define L_SEQ 2048
#define D_MODEL 258
#define N_LAYERS 4
#define D_STATE 16
#define D_INNER 516
#define DT_RANK 17
#define TWO_DI 1032
#define XW 56            // padded xdbl stride (49 real cols)
#define NTOK 8192
#define EPS 1e-5f
#define KM 288           // 258 padded to 32-float chunks
#define KI 544           // 516 padded
#define WIN_R 1088       // 17 * 64
#define WOUT_R 320       // 5 * 64
#define WXP_R 64

// -------- device scratch (zero-initialized; pads never written) --------
__device__ __align__(256) float g_x[NTOK * D_MODEL];
__device__ __align__(256) float g_xn[NTOK * KM];
__device__ __align__(256) float g_xz[NTOK * TWO_DI];
__device__ __align__(256) float g_xc[NTOK * KI];
__device__ __align__(256) float g_xdbl[NTOK * XW];
__device__ __align__(256) float g_dt[NTOK * D_INNER];
__device__ __align__(256) float g_y2[NTOK * KI];
__device__ __align__(256) float g_win[N_LAYERS * WIN_R * KM];
__device__ __align__(256) float g_wout[N_LAYERS * WOUT_R * KI];
__device__ __align__(256) float g_wxp[N_LAYERS * WXP_R * KI];

// -------- tf32 helpers --------
__device__ __forceinline__ uint32_t f2tf32(float f) {
    uint32_t r;
    asm("cvt.rna.tf32.f32 %0, %1;" : "=r"(r) : "f"(f));
    return r;
}
__device__ __forceinline__ void mma_tf32(float& d0, float& d1, float& d2, float& d3,
                                         uint32_t a0, uint32_t a1, uint32_t a2, uint32_t a3,
                                         uint32_t b0, uint32_t b1) {
    asm volatile(
        "mma.sync.aligned.m16n8k8.row.col.f32.tf32.tf32.f32 "
        "{%0,%1,%2,%3}, {%4,%5,%6,%7}, {%8,%9}, {%0,%1,%2,%3};"
        : "+f"(d0), "+f"(d1), "+f"(d2), "+f"(d3)
        : "r"(a0), "r"(a1), "r"(a2), "r"(a3), "r"(b0), "r"(b1));
}

// -------- tf32 mma GEMM: C[8192,N] = A[8192,K] @ W[N,K]^T (+C) --------
// CTA tile 128x64, 8 warps in 4(M) x 2(N), warp tile 32x32, K chunk 32.
#define SPAD 36
__global__ __launch_bounds__(256) void gemm_mma(
    const float* __restrict__ A, const float* __restrict__ W,
    float* __restrict__ C, int N_store, int K, int lda, int ldc, int doAdd) {
    __shared__ uint32_t sA[128][SPAD];
    __shared__ uint32_t sB[64][SPAD];
    const int tid = threadIdx.x, wid = tid >> 5, lane = tid & 31;
    const int warpM = wid & 3, warpN = wid >> 2;
    const int quad = lane >> 2, qk = lane & 3;
    const int bm = blockIdx.y * 128, bn = blockIdx.x * 64;

    float acc[2][4][4];
    #pragma unroll
    for (int i = 0; i < 2; ++i)
        #pragma unroll
        for (int j = 0; j < 4; ++j)
            #pragma unroll
            for (int k = 0; k < 4; ++k) acc[i][j][k] = 0.f;

    const float* Ab = A + (size_t)bm * lda;
    const float* Wb = W + (size_t)bn * K;
    const int nch = K >> 5;

    for (int c = 0; c < nch; ++c) {
        // stage A: 128 rows x 32 k (tf32-converted)
        const float* Ac = Ab + c * 32;
        #pragma unroll
        for (int i = 0; i < 4; ++i) {
            int fi = tid + i * 256;            // 0..1023 float4s
            int r = fi >> 3, c4 = fi & 7;
            float4 v = *(const float4*)(Ac + (size_t)r * lda + c4 * 4);
            sA[r][c4 * 4 + 0] = f2tf32(v.x);
            sA[r][c4 * 4 + 1] = f2tf32(v.y);
            sA[r][c4 * 4 + 2] = f2tf32(v.z);
            sA[r][c4 * 4 + 3] = f2tf32(v.w);
        }
        // stage B: 64 rows x 32 k
        const float* Wc = Wb + c * 32;
        #pragma unroll
        for (int i = 0; i < 2; ++i) {
            int fi = tid + i * 256;            // 0..511 float4s
            int r = fi >> 3, c4 = fi & 7;
            float4 v = *(const float4*)(Wc + (size_t)r * K + c4 * 4);
            sB[r][c4 * 4 + 0] = f2tf32(v.x);
            sB[r][c4 * 4 + 1] = f2tf32(v.y);
            sB[r][c4 * 4 + 2] = f2tf32(v.z);
            sB[r][c4 * 4 + 3] = f2tf32(v.w);
        }
        __syncthreads();
        #pragma unroll
        for (int k0 = 0; k0 < 32; k0 += 8) {
            uint32_t a[2][4], b[4][2];
            #pragma unroll
            for (int mt = 0; mt < 2; ++mt) {
                int rb = warpM * 32 + mt * 16 + quad;
                a[mt][0] = sA[rb][k0 + qk];
                a[mt][1] = sA[rb + 8][k0 + qk];
                a[mt][2] = sA[rb][k0 + qk + 4];
                a[mt][3] = sA[rb + 8][k0 + qk + 4];
            }
            #pragma unroll
            for (int nt = 0; nt < 4; ++nt) {
                int nb = warpN * 32 + nt * 8 + quad;
                b[nt][0] = sB[nb][k0 + qk];
                b[nt][1] = sB[nb][k0 + qk + 4];
            }
            #pragma unroll
            for (int mt = 0; mt < 2; ++mt)
                #pragma unroll
                for (int nt = 0; nt < 4; ++nt)
                    mma_tf32(acc[mt][nt][0], acc[mt][nt][1], acc[mt][nt][2], acc[mt][nt][3],
                             a[mt][0], a[mt][1], a[mt][2], a[mt][3], b[nt][0], b[nt][1]);
        }
        __syncthreads();
    }

    // epilogue: c0:(quad, qk*2) c1:(quad, qk*2+1) c2:(quad+8,...) c3
    #pragma unroll
    for (int mt = 0; mt < 2; ++mt) {
        int r0 = bm + warpM * 32 + mt * 16 + quad;
        #pragma unroll
        for (int nt = 0; nt < 4; ++nt) {
            int gc = bn + warpN * 32 + nt * 8 + qk * 2;
            #pragma unroll
            for (int half = 0; half < 2; ++half) {
                int row = r0 + half * 8;
                float v0 = acc[mt][nt][half * 2 + 0];
                float v1 = acc[mt][nt][half * 2 + 1];
                size_t gi = (size_t)row * ldc + gc;
                if (gc < N_store) {
                    if (doAdd) v0 += C[gi];
                    C[gi] = v0;
                }
                if (gc + 1 < N_store) {
                    if (doAdd) v1 += C[gi + 1];
                    C[gi + 1] = v1;
                }
            }
        }
    }
}

// -------- rmsnorm / final --------
__device__ __forceinline__ float block_sum(float v) {
    __shared__ float sh[9];
    int lane = threadIdx.x & 31, w = threadIdx.x >> 5;
    #pragma unroll
    for (int o = 16; o; o >>= 1) v += __shfl_xor_sync(~0u, v, o);
    if (lane == 0) sh[w] = v;
    __syncthreads();
    if (w == 0) {
        v = (lane < 8) ? sh[lane] : 0.f;
        #pragma unroll
        for (int o = 4; o; o >>= 1) v += __shfl_xor_sync(~0u, v, o);
        if (lane == 0) sh[8] = v;
    }
    __syncthreads();
    return sh[8];
}
__global__ void rmsnorm_kernel(const float* __restrict__ x, const float* __restrict__ w,
                               float* __restrict__ o, int ldo) {
    int row = blockIdx.x;
    const float* xr = x + (size_t)row * D_MODEL;
    float ss = 0.f;
    for (int i = threadIdx.x; i < D_MODEL; i += 256) { float v = xr[i]; ss += v * v; }
    ss = block_sum(ss);
    float inv = rsqrtf(ss * (1.f / D_MODEL) + EPS);
    for (int i = threadIdx.x; i < D_MODEL; i += 256)
        o[(size_t)row * ldo + i] = xr[i] * inv * w[i];
}
__global__ void final_kernel(const float* __restrict__ f, const float* __restrict__ x,
                             const float* __restrict__ w, float* __restrict__ o) {
    int row = blockIdx.x;
    const float* xr = x + (size_t)row * D_MODEL;
    float ss = 0.f;
    for (int i = threadIdx.x; i < D_MODEL; i += 256) { float v = xr[i]; ss += v * v; }
    ss = block_sum(ss);
    float inv = rsqrtf(ss * (1.f / D_MODEL) + EPS);
    for (int i = threadIdx.x; i < D_MODEL; i += 256)
        o[(size_t)row * D_MODEL + i] = f[(size_t)row * D_MODEL + i] + xr[i] * inv * w[i];
}

// -------- conv(k=4, causal) + silu --------
__global__ void conv_silu_kernel(const float* __restrict__ xz, const float* __restrict__ cw,
                                 const float* __restrict__ cb, float* __restrict__ xc) {
    int d = blockIdx.x * 128 + threadIdx.x;
    if (d >= D_INNER) return;
    int l = blockIdx.y, b = blockIdx.z;
    size_t rb = (size_t)b * L_SEQ + l;
    const float* base = xz + rb * TWO_DI + d;
    float acc = cb[d];
    if (l >= 3) acc += cw[d * 4 + 0] * base[-3 * TWO_DI];
    if (l >= 2) acc += cw[d * 4 + 1] * base[-2 * TWO_DI];
    if (l >= 1) acc += cw[d * 4 + 2] * base[-1 * TWO_DI];
    acc += cw[d * 4 + 3] * base[0];
    xc[rb * KI + d] = acc / (1.f + __expf(-acc));
}

// -------- dt = softplus(dt_lo @ dtw^T + dtb), dtw cached in smem --------
#define DT_TB 16
__global__ __launch_bounds__(256) void dt_kernel(
    const float* __restrict__ xdbl, const float* __restrict__ dtw,
    const float* __restrict__ dtb, float* __restrict__ dt) {
    __shared__ float sw[D_INNER * DT_RANK];
    __shared__ float slo[DT_TB][DT_RANK];
    int m0 = blockIdx.x * DT_TB;
    for (int i = threadIdx.x; i < D_INNER * DT_RANK; i += 256) sw[i] = dtw[i];
    for (int i = threadIdx.x; i < DT_TB * DT_RANK; i += 256)
        slo[i / DT_RANK][i % DT_RANK] = xdbl[(size_t)(m0 + i / DT_RANK) * XW + i % DT_RANK];
    __syncthreads();
    for (int idx = threadIdx.x; idx < DT_TB * D_INNER; idx += 256) {
        int t = idx / D_INNER, d = idx - t * D_INNER;
        float acc = dtb[d];
        #pragma unroll
        for (int r = 0; r < DT_RANK; ++r) acc += slo[t][r] * sw[d * DT_RANK + r];
        dt[(size_t)(m0 + t) * D_INNER + d] = (acc > 20.f) ? acc : log1pf(__expf(acc));
    }
}

// -------- selective scan + fused gate --------
#define SCH 8
#define ST 128
__global__ __launch_bounds__(128) void scan_kernel(
    const float* __restrict__ dt, const float* __restrict__ u,
    const float* __restrict__ xdbl, const float* __restrict__ xz,
    const float* __restrict__ A_log, const float* __restrict__ Dp,
    float* __restrict__ y2) {
    __shared__ float s_dt[SCH][ST], s_u[SCH][ST], s_z[SCH][ST];
    __shared__ float s_B[ST][16], s_C[ST][16];
    int b = blockIdx.y, d0 = blockIdx.x * SCH;
    int tid = threadIdx.x, lane = tid & 31, warp = tid >> 5;
    int s = lane & 15, dloc = warp * 2 + (lane >> 4), d = d0 + dloc;
    int dc = (d < D_INNER) ? d : (D_INNER - 1);
    float Av = -__expf(A_log[(size_t)dc * 16 + s]);
    float Dv = Dp[dc];
    float h = 0.f;
    size_t bl = (size_t)b * L_SEQ;
    for (int l0 = 0; l0 < L_SEQ; l0 += ST) {
        for (int idx = tid; idx < SCH * ST; idx += 128) {
            int ch = idx & 7, t = idx >> 3;
            int dd = d0 + ch; if (dd >= D_INNER) dd = D_INNER - 1;
            size_t row = bl + l0 + t;
            s_dt[ch][t] = dt[row * D_INNER + dd];
            s_u[ch][t] = u[row * KI + dd];
            s_z[ch][t] = xz[row * TWO_DI + D_INNER + dd];
        }
        for (int idx = tid; idx < ST * 16; idx += 128) {
            int ss = idx & 15, t = idx >> 4;
            const float* g = xdbl + (bl + l0 + t) * XW + DT_RANK;
            s_B[t][ss] = g[ss];
            s_C[t][ss] = g[16 + ss];
        }
        __syncthreads();
        #pragma unroll 4
        for (int t = 0; t < ST; ++t) {
            float dtv = s_dt[dloc][t], uv = s_u[dloc][t];
            float dA = __expf(dtv * Av);
            h = dA * h + (dtv * uv) * s_B[t][s];
            float p = h * s_C[t][s];
            p += __shfl_xor_sync(~0u, p, 8);
            p += __shfl_xor_sync(~0u, p, 4);
            p += __shfl_xor_sync(~0u, p, 2);
            p += __shfl_xor_sync(~0u, p, 1);
            if (s == 0 && d < D_INNER) {
                float z = s_z[dloc][t];
                y2[(bl + l0 + t) * KI + d] = (p + uv * Dv) * (z / (1.f + __expf(-z)));
            }
        }
        __syncthreads();
    }
}

// -------- weight pack into padded layout --------
__global__ void pack_kernel(const float* __restrict__ src, float* __restrict__ dst,
                            int N, int K, int NP, int KP, int total) {
    int i = blockIdx.x * 256 + threadIdx.x;
    if (i >= total) return;
    int k = i % K, nr = i / K, n = nr % N, l = nr / N;
    dst[((size_t)l * NP + n) * KP + k] = src[i];
}

// -------- host --------
extern "C" void kernel_launch(void* const* d_in, const int* in_sizes, int n_in,
                              void* d_out, int out_size) {
    const float* fuse  = (const float*)d_in[0];
    const float* nwv   = (const float*)d_in[1];
    const float* ipw   = (const float*)d_in[2];
    const float* cwv   = (const float*)d_in[3];
    const float* cbv   = (const float*)d_in[4];
    const float* xpw   = (const float*)d_in[5];
    const float* dtwv  = (const float*)d_in[6];
    const float* dtbv  = (const float*)d_in[7];
    const float* Alv   = (const float*)d_in[8];
    const float* Dpv   = (const float*)d_in[9];
    const float* opw   = (const float*)d_in[10];
    const float* fw    = (const float*)d_in[11];
    float* out = (float*)d_out;

    float *p_x, *p_xn, *p_xz, *p_xc, *p_xdbl, *p_dt, *p_y2, *p_win, *p_wout, *p_wxp;
    cudaGetSymbolAddress((void**)&p_x, g_x);
    cudaGetSymbolAddress((void**)&p_xn, g_xn);
    cudaGetSymbolAddress((void**)&p_xz, g_xz);
    cudaGetSymbolAddress((void**)&p_xc, g_xc);
    cudaGetSymbolAddress((void**)&p_xdbl, g_xdbl);
    cudaGetSymbolAddress((void**)&p_dt, g_dt);
    cudaGetSymbolAddress((void**)&p_y2, g_y2);
    cudaGetSymbolAddress((void**)&p_win, g_win);
    cudaGetSymbolAddress((void**)&p_wout, g_wout);
    cudaGetSymbolAddress((void**)&p_wxp, g_wxp);

    pack_kernel<<<(4 * 1032 * 258 + 255) / 256, 256>>>(ipw, p_win, 1032, 258, WIN_R, KM, 4 * 1032 * 258);
    pack_kernel<<<(4 * 258 * 516 + 255) / 256, 256>>>(opw, p_wout, 258, 516, WOUT_R, KI, 4 * 258 * 516);
    pack_kernel<<<(4 * 49 * 516 + 255) / 256, 256>>>(xpw, p_wxp, 49, 516, WXP_R, KI, 4 * 49 * 516);
    cudaMemcpyAsync(p_x, fuse, (size_t)NTOK * D_MODEL * sizeof(float), cudaMemcpyDeviceToDevice);

    for (int l = 0; l < N_LAYERS; ++l) {
        rmsnorm_kernel<<<NTOK, 256>>>(p_x, nwv + (size_t)l * D_MODEL, p_xn, KM);
        gemm_mma<<<dim3(17, 64), 256>>>(p_xn, p_win + (size_t)l * WIN_R * KM,
                                        p_xz, TWO_DI, KM, KM, TWO_DI, 0);
        conv_silu_kernel<<<dim3(5, L_SEQ, B_SZ), 128>>>(p_xz, cwv + (size_t)l * D_INNER * 4,
                                                        cbv + (size_t)l * D_INNER, p_xc);
        gemm_mma<<<dim3(1, 64), 256>>>(p_xc, p_wxp + (size_t)l * WXP_R * KI,
                                       p_xdbl, 49, KI, KI, XW, 0);
        dt_kernel<<<NTOK / DT_TB, 256>>>(p_xdbl, dtwv + (size_t)l * D_INNER * DT_RANK,
                                         dtbv + (size_t)l * D_INNER, p_dt);
        scan_kernel<<<dim3((D_INNER + SCH - 1) / SCH, B_SZ), 128>>>(
            p_dt, p_xc, p_xdbl, p_xz, Alv + (size_t)l * D_INNER * 16,
            Dpv + (size_t)l * D_INNER, p_y2);
        gemm_mma<<<dim3(5, 64), 256>>>(p_y2, p_wout + (size_t)l * WOUT_R * KI,
                                       p_x, D_MODEL, KI, KI, D_MODEL, 1);
    }
    final_kernel<<<NTOK, 256>>>(fuse, p_x, fw, out);
    (void)in_sizes; (void)n_in; (void)out_size;
}

// round 5
// speedup vs baseline: 1.0810x; 1.0810x over previous
#include <cuda_runtime.h>
#include <cuda_bf16.h>
#include <math.h>
#include <stdint.h>

#define B_SZ 4
#define L_SEQ 2048
#define D_MODEL 258
#define N_LAYERS 4
#define D_STATE 16
#define D_INNER 516
#define DT_RANK 17
#define TWO_DI 1032
#define XW 56            // padded xdbl stride (49 real cols)
#define NTOK 8192
#define EPS 1e-5f
#define KM 288           // 258 padded to 32-chunks
#define KI 544           // 516 padded
#define WIN_R 1088       // 17 * 64
#define WOUT_R 320       // 5 * 64
#define WXP_R 64

// -------- device scratch (zero-initialized; pads never written) --------
__device__ __align__(256) float g_x[NTOK * D_MODEL];
__device__ __align__(256) __nv_bfloat16 g_xn[NTOK * KM];
__device__ __align__(256) float g_xz[NTOK * TWO_DI];
__device__ __align__(256) __nv_bfloat16 g_xc[NTOK * KI];
__device__ __align__(256) float g_xdbl[NTOK * XW];
__device__ __align__(256) float g_dt[NTOK * D_INNER];
__device__ __align__(256) __nv_bfloat16 g_y2[NTOK * KI];
__device__ __align__(256) __nv_bfloat16 g_win[N_LAYERS * WIN_R * KM];
__device__ __align__(256) __nv_bfloat16 g_wout[N_LAYERS * WOUT_R * KI];
__device__ __align__(256) __nv_bfloat16 g_wxp[N_LAYERS * WXP_R * KI];

// -------- helpers --------
__device__ __forceinline__ uint32_t smem_u32(const void* p) {
    uint32_t a;
    asm("{ .reg .u64 t; cvta.to.shared.u64 t, %1; cvt.u32.u64 %0, t; }" : "=r"(a) : "l"(p));
    return a;
}
__device__ __forceinline__ void cp_async16(uint32_t dst, const void* src) {
    asm volatile("cp.async.ca.shared.global [%0], [%1], 16;" :: "r"(dst), "l"(src));
}
#define CP_COMMIT() asm volatile("cp.async.commit_group;" ::: "memory")
#define CP_WAIT(n) asm volatile("cp.async.wait_group %0;" :: "n"(n) : "memory")

__device__ __forceinline__ void mma_bf16(float* d, const uint32_t* a, const uint32_t* b) {
    asm volatile(
        "mma.sync.aligned.m16n8k16.row.col.f32.bf16.bf16.f32 "
        "{%0,%1,%2,%3},{%4,%5,%6,%7},{%8,%9},{%0,%1,%2,%3};"
        : "+f"(d[0]), "+f"(d[1]), "+f"(d[2]), "+f"(d[3])
        : "r"(a[0]), "r"(a[1]), "r"(a[2]), "r"(a[3]), "r"(b[0]), "r"(b[1]));
}

// -------- bf16 mma GEMM: C[8192,N] = A[8192,K]bf16 @ W[N,K]bf16^T (+C fp32) --------
// CTA 128x64, 8 warps 4(M)x2(N), warp 32x32; K chunk 32; 2-stage cp.async pipeline.
#define AW 20                    // smem row stride in 32-bit words (= 40 bf16)
#define ASTG (128 * AW)
#define BSTG (64 * AW)
__global__ __launch_bounds__(256) void gemm_bf16(
    const __nv_bfloat16* __restrict__ A, const __nv_bfloat16* __restrict__ W,
    float* __restrict__ C, int N_store, int K, int lda, int ldc, int doAdd) {
    __shared__ __align__(16) uint32_t sm[2 * ASTG + 2 * BSTG];
    uint32_t* sB = sm + 2 * ASTG;
    const int tid = threadIdx.x, wid = tid >> 5, lane = tid & 31;
    const int warpM = wid & 3, warpN = wid >> 2;
    const int quad = lane >> 2, qk = lane & 3;
    const int bm = blockIdx.y * 128, bn = blockIdx.x * 64;
    float acc[2][4][4];
    #pragma unroll
    for (int i = 0; i < 2; ++i)
        #pragma unroll
        for (int j = 0; j < 4; ++j)
            #pragma unroll
            for (int k = 0; k < 4; ++k) acc[i][j][k] = 0.f;

    const __nv_bfloat16* Ab = A + (size_t)bm * lda;
    const __nv_bfloat16* Wb = W + (size_t)bn * K;
    const int nch = K >> 5;
    const uint32_t smA_u = smem_u32(sm), smB_u = smem_u32(sB);
    const int br = tid >> 2, bs = tid & 3;

    auto load_chunk = [&](int c, int st) {
        const __nv_bfloat16* Ac = Ab + c * 32;
        #pragma unroll
        for (int i = 0; i < 2; ++i) {
            int fi = tid + i * 256;           // 0..511 : 16B segs of A chunk
            int r = fi >> 2, s = fi & 3;
            cp_async16(smA_u + (uint32_t)(st * ASTG + r * AW + s * 4) * 4,
                       Ac + (size_t)r * lda + s * 8);
        }
        cp_async16(smB_u + (uint32_t)(st * BSTG + br * AW + bs * 4) * 4,
                   Wb + (size_t)br * K + c * 32 + bs * 8);
    };

    load_chunk(0, 0);
    CP_COMMIT();
    for (int c = 0; c < nch; ++c) {
        int st = c & 1;
        if (c + 1 < nch) { load_chunk(c + 1, st ^ 1); CP_COMMIT(); CP_WAIT(1); }
        else { CP_WAIT(0); }
        __syncthreads();
        const uint32_t* aB = sm + st * ASTG;
        const uint32_t* bB = sB + st * BSTG;
        #pragma unroll
        for (int ks = 0; ks < 2; ++ks) {
            uint32_t a[2][4], b[4][2];
            #pragma unroll
            for (int mt = 0; mt < 2; ++mt) {
                int rb = warpM * 32 + mt * 16 + quad;
                a[mt][0] = aB[rb * AW + ks * 8 + qk];
                a[mt][1] = aB[(rb + 8) * AW + ks * 8 + qk];
                a[mt][2] = aB[rb * AW + ks * 8 + qk + 4];
                a[mt][3] = aB[(rb + 8) * AW + ks * 8 + qk + 4];
            }
            #pragma unroll
            for (int nt = 0; nt < 4; ++nt) {
                int nb = warpN * 32 + nt * 8 + quad;
                b[nt][0] = bB[nb * AW + ks * 8 + qk];
                b[nt][1] = bB[nb * AW + ks * 8 + qk + 4];
            }
            #pragma unroll
            for (int mt = 0; mt < 2; ++mt)
                #pragma unroll
                for (int nt = 0; nt < 4; ++nt)
                    mma_bf16(acc[mt][nt], a[mt], b[nt]);
        }
        __syncthreads();
    }

    #pragma unroll
    for (int mt = 0; mt < 2; ++mt) {
        int r0 = bm + warpM * 32 + mt * 16 + quad;
        #pragma unroll
        for (int nt = 0; nt < 4; ++nt) {
            int gc = bn + warpN * 32 + nt * 8 + qk * 2;
            #pragma unroll
            for (int half = 0; half < 2; ++half) {
                int row = r0 + half * 8;
                float v0 = acc[mt][nt][half * 2 + 0];
                float v1 = acc[mt][nt][half * 2 + 1];
                size_t gi = (size_t)row * ldc + gc;
                if (gc < N_store) {
                    if (doAdd) v0 += C[gi];
                    C[gi] = v0;
                }
                if (gc + 1 < N_store) {
                    if (doAdd) v1 += C[gi + 1];
                    C[gi + 1] = v1;
                }
            }
        }
    }
}

// -------- rmsnorm (bf16 out) / final --------
__device__ __forceinline__ float block_sum(float v) {
    __shared__ float sh[9];
    int lane = threadIdx.x & 31, w = threadIdx.x >> 5;
    #pragma unroll
    for (int o = 16; o; o >>= 1) v += __shfl_xor_sync(~0u, v, o);
    if (lane == 0) sh[w] = v;
    __syncthreads();
    if (w == 0) {
        v = (lane < 8) ? sh[lane] : 0.f;
        #pragma unroll
        for (int o = 4; o; o >>= 1) v += __shfl_xor_sync(~0u, v, o);
        if (lane == 0) sh[8] = v;
    }
    __syncthreads();
    return sh[8];
}
__global__ void rmsnorm_kernel(const float* __restrict__ x, const float* __restrict__ w,
                               __nv_bfloat16* __restrict__ o, int ldo) {
    int row = blockIdx.x;
    const float* xr = x + (size_t)row * D_MODEL;
    float ss = 0.f;
    for (int i = threadIdx.x; i < D_MODEL; i += 256) { float v = xr[i]; ss += v * v; }
    ss = block_sum(ss);
    float inv = rsqrtf(ss * (1.f / D_MODEL) + EPS);
    for (int i = threadIdx.x; i < D_MODEL; i += 256)
        o[(size_t)row * ldo + i] = __float2bfloat16(xr[i] * inv * w[i]);
}
__global__ void final_kernel(const float* __restrict__ f, const float* __restrict__ x,
                             const float* __restrict__ w, float* __restrict__ o) {
    int row = blockIdx.x;
    const float* xr = x + (size_t)row * D_MODEL;
    float ss = 0.f;
    for (int i = threadIdx.x; i < D_MODEL; i += 256) { float v = xr[i]; ss += v * v; }
    ss = block_sum(ss);
    float inv = rsqrtf(ss * (1.f / D_MODEL) + EPS);
    for (int i = threadIdx.x; i < D_MODEL; i += 256)
        o[(size_t)row * D_MODEL + i] = f[(size_t)row * D_MODEL + i] + xr[i] * inv * w[i];
}

// -------- conv(k=4, causal) + silu (bf16 out) --------
__global__ void conv_silu_kernel(const float* __restrict__ xz, const float* __restrict__ cw,
                                 const float* __restrict__ cb, __nv_bfloat16* __restrict__ xc) {
    int d = blockIdx.x * 128 + threadIdx.x;
    if (d >= D_INNER) return;
    int l = blockIdx.y, b = blockIdx.z;
    size_t rb = (size_t)b * L_SEQ + l;
    const float* base = xz + rb * TWO_DI + d;
    float acc = cb[d];
    if (l >= 3) acc += cw[d * 4 + 0] * base[-3 * TWO_DI];
    if (l >= 2) acc += cw[d * 4 + 1] * base[-2 * TWO_DI];
    if (l >= 1) acc += cw[d * 4 + 2] * base[-1 * TWO_DI];
    acc += cw[d * 4 + 3] * base[0];
    xc[rb * KI + d] = __float2bfloat16(acc / (1.f + __expf(-acc)));
}

// -------- dt = softplus(dt_lo @ dtw^T + dtb) --------
#define DT_TB 16
__global__ __launch_bounds__(256) void dt_kernel(
    const float* __restrict__ xdbl, const float* __restrict__ dtw,
    const float* __restrict__ dtb, float* __restrict__ dt) {
    __shared__ float sw[D_INNER * DT_RANK];
    __shared__ float slo[DT_TB][DT_RANK];
    int m0 = blockIdx.x * DT_TB;
    for (int i = threadIdx.x; i < D_INNER * DT_RANK; i += 256) sw[i] = dtw[i];
    for (int i = threadIdx.x; i < DT_TB * DT_RANK; i += 256)
        slo[i / DT_RANK][i % DT_RANK] = xdbl[(size_t)(m0 + i / DT_RANK) * XW + i % DT_RANK];
    __syncthreads();
    for (int idx = threadIdx.x; idx < DT_TB * D_INNER; idx += 256) {
        int t = idx / D_INNER, d = idx - t * D_INNER;
        float acc = dtb[d];
        #pragma unroll
        for (int r = 0; r < DT_RANK; ++r) acc += slo[t][r] * sw[d * DT_RANK + r];
        dt[(size_t)(m0 + t) * D_INNER + d] = (acc > 20.f) ? acc : log1pf(__expf(acc));
    }
}

// -------- selective scan + fused gate (bf16 u in, bf16 y2 out) --------
#define SCH 8
#define ST 128
__global__ __launch_bounds__(128) void scan_kernel(
    const float* __restrict__ dt, const __nv_bfloat16* __restrict__ u,
    const float* __restrict__ xdbl, const float* __restrict__ xz,
    const float* __restrict__ A_log, const float* __restrict__ Dp,
    __nv_bfloat16* __restrict__ y2) {
    __shared__ float s_dt[SCH][ST], s_u[SCH][ST], s_z[SCH][ST];
    __shared__ float s_B[ST][16], s_C[ST][16];
    int b = blockIdx.y, d0 = blockIdx.x * SCH;
    int tid = threadIdx.x, lane = tid & 31, warp = tid >> 5;
    int s = lane & 15, dloc = warp * 2 + (lane >> 4), d = d0 + dloc;
    int dc = (d < D_INNER) ? d : (D_INNER - 1);
    float Av = -__expf(A_log[(size_t)dc * 16 + s]);
    float Dv = Dp[dc];
    float h = 0.f;
    size_t bl = (size_t)b * L_SEQ;
    for (int l0 = 0; l0 < L_SEQ; l0 += ST) {
        for (int idx = tid; idx < SCH * ST; idx += 128) {
            int ch = idx & 7, t = idx >> 3;
            int dd = d0 + ch; if (dd >= D_INNER) dd = D_INNER - 1;
            size_t row = bl + l0 + t;
            s_dt[ch][t] = dt[row * D_INNER + dd];
            s_u[ch][t] = __bfloat162float(u[row * KI + dd]);
            s_z[ch][t] = xz[row * TWO_DI + D_INNER + dd];
        }
        for (int idx = tid; idx < ST * 16; idx += 128) {
            int ss = idx & 15, t = idx >> 4;
            const float* g = xdbl + (bl + l0 + t) * XW + DT_RANK;
            s_B[t][ss] = g[ss];
            s_C[t][ss] = g[16 + ss];
        }
        __syncthreads();
        #pragma unroll 4
        for (int t = 0; t < ST; ++t) {
            float dtv = s_dt[dloc][t], uv = s_u[dloc][t];
            float dA = __expf(dtv * Av);
            h = dA * h + (dtv * uv) * s_B[t][s];
            float p = h * s_C[t][s];
            p += __shfl_xor_sync(~0u, p, 8);
            p += __shfl_xor_sync(~0u, p, 4);
            p += __shfl_xor_sync(~0u, p, 2);
            p += __shfl_xor_sync(~0u, p, 1);
            if (s == 0 && d < D_INNER) {
                float z = s_z[dloc][t];
                y2[(bl + l0 + t) * KI + d] =
                    __float2bfloat16((p + uv * Dv) * (z / (1.f + __expf(-z))));
            }
        }
        __syncthreads();
    }
}

// -------- weight pack (fp32 -> padded bf16) --------
__global__ void pack_bf16(const float* __restrict__ src, __nv_bfloat16* __restrict__ dst,
                          int N, int K, int NP, int KP, int total) {
    int i = blockIdx.x * 256 + threadIdx.x;
    if (i >= total) return;
    int k = i % K, nr = i / K, n = nr % N, l = nr / N;
    dst[((size_t)l * NP + n) * KP + k] = __float2bfloat16(src[i]);
}

// -------- host --------
extern "C" void kernel_launch(void* const* d_in, const int* in_sizes, int n_in,
                              void* d_out, int out_size) {
    const float* fuse  = (const float*)d_in[0];
    const float* nwv   = (const float*)d_in[1];
    const float* ipw   = (const float*)d_in[2];
    const float* cwv   = (const float*)d_in[3];
    const float* cbv   = (const float*)d_in[4];
    const float* xpw   = (const float*)d_in[5];
    const float* dtwv  = (const float*)d_in[6];
    const float* dtbv  = (const float*)d_in[7];
    const float* Alv   = (const float*)d_in[8];
    const float* Dpv   = (const float*)d_in[9];
    const float* opw   = (const float*)d_in[10];
    const float* fw    = (const float*)d_in[11];
    float* out = (float*)d_out;

    float *p_x, *p_xz, *p_xdbl, *p_dt;
    __nv_bfloat16 *p_xn, *p_xc, *p_y2, *p_win, *p_wout, *p_wxp;
    cudaGetSymbolAddress((void**)&p_x, g_x);
    cudaGetSymbolAddress((void**)&p_xn, g_xn);
    cudaGetSymbolAddress((void**)&p_xz, g_xz);
    cudaGetSymbolAddress((void**)&p_xc, g_xc);
    cudaGetSymbolAddress((void**)&p_xdbl, g_xdbl);
    cudaGetSymbolAddress((void**)&p_dt, g_dt);
    cudaGetSymbolAddress((void**)&p_y2, g_y2);
    cudaGetSymbolAddress((void**)&p_win, g_win);
    cudaGetSymbolAddress((void**)&p_wout, g_wout);
    cudaGetSymbolAddress((void**)&p_wxp, g_wxp);

    pack_bf16<<<(4 * 1032 * 258 + 255) / 256, 256>>>(ipw, p_win, 1032, 258, WIN_R, KM, 4 * 1032 * 258);
    pack_bf16<<<(4 * 258 * 516 + 255) / 256, 256>>>(opw, p_wout, 258, 516, WOUT_R, KI, 4 * 258 * 516);
    pack_bf16<<<(4 * 49 * 516 + 255) / 256, 256>>>(xpw, p_wxp, 49, 516, WXP_R, KI, 4 * 49 * 516);
    cudaMemcpyAsync(p_x, fuse, (size_t)NTOK * D_MODEL * sizeof(float), cudaMemcpyDeviceToDevice);

    for (int l = 0; l < N_LAYERS; ++l) {
        rmsnorm_kernel<<<NTOK, 256>>>(p_x, nwv + (size_t)l * D_MODEL, p_xn, KM);
        gemm_bf16<<<dim3(17, 64), 256>>>(p_xn, p_win + (size_t)l * WIN_R * KM,
                                         p_xz, TWO_DI, KM, KM, TWO_DI, 0);
        conv_silu_kernel<<<dim3(5, L_SEQ, B_SZ), 128>>>(p_xz, cwv + (size_t)l * D_INNER * 4,
                                                        cbv + (size_t)l * D_INNER, p_xc);
        gemm_bf16<<<dim3(1, 64), 256>>>(p_xc, p_wxp + (size_t)l * WXP_R * KI,
                                        p_xdbl, 49, KI, KI, XW, 0);
        dt_kernel<<<NTOK / DT_TB, 256>>>(p_xdbl, dtwv + (size_t)l * D_INNER * DT_RANK,
                                         dtbv + (size_t)l * D_INNER, p_dt);
        scan_kernel<<<dim3((D_INNER + SCH - 1) / SCH, B_SZ), 128>>>(
            p_dt, p_xc, p_xdbl, p_xz, Alv + (size_t)l * D_INNER * 16,
            Dpv + (size_t)l * D_INNER, p_y2);
        gemm_bf16<<<dim3(5, 64), 256>>>(p_y2, p_wout + (size_t)l * WOUT_R * KI,
                                        p_x, D_MODEL, KI, KI, D_MODEL, 1);
    }
    final_kernel<<<NTOK, 256>>>(fuse, p_x, fw, out);
    (void)in_sizes; (void)n_in; (void)out_size;
}

// round 6
// speedup vs baseline: 2.1093x; 1.9512x over previous
#include <cuda_runtime.h>
#include <cuda_bf16.h>
#include <math.h>
#include <stdint.h>

#define B_SZ 4
#define L_SEQ 2048
#define D_MODEL 258
#define N_LAYERS 4
#define D_STATE 16
#define D_INNER 516
#define DT_RANK 17
#define TWO_DI 1032
#define XW 56            // padded xdbl stride (49 real cols)
#define NTOK 8192
#define EPS 1e-5f
#define KM 288           // 258 padded to 32-chunks
#define KI 544           // 516 padded
#define WIN_R 1088       // 17 * 64
#define WOUT_R 320       // 5 * 64
#define WXP_R 64
#define NCHK 16          // scan chunks
#define CT 128           // tokens per scan chunk

typedef __nv_bfloat16 bf16;

// -------- device scratch (zero-initialized; pads never written) --------
__device__ __align__(256) float g_x[NTOK * D_MODEL];
__device__ __align__(256) bf16  g_xn[NTOK * KM];
__device__ __align__(256) bf16  g_xz[NTOK * TWO_DI];
__device__ __align__(256) bf16  g_xc[NTOK * KI];
__device__ __align__(256) float g_xdbl[NTOK * XW];
__device__ __align__(256) bf16  g_dt[NTOK * D_INNER];
__device__ __align__(256) bf16  g_y2[NTOK * KI];
__device__ __align__(256) bf16  g_win[N_LAYERS * WIN_R * KM];
__device__ __align__(256) bf16  g_wout[N_LAYERS * WOUT_R * KI];
__device__ __align__(256) bf16  g_wxp[N_LAYERS * WXP_R * KI];
__device__ __align__(256) float g_L[B_SZ * NCHK * D_INNER * D_STATE];
__device__ __align__(256) float g_H0[B_SZ * NCHK * D_INNER * D_STATE];
__device__ __align__(256) float g_sdt[B_SZ * NCHK * D_INNER];

// -------- helpers --------
__device__ __forceinline__ uint32_t smem_u32(const void* p) {
    uint32_t a;
    asm("{ .reg .u64 t; cvta.to.shared.u64 t, %1; cvt.u32.u64 %0, t; }" : "=r"(a) : "l"(p));
    return a;
}
__device__ __forceinline__ void cp_async16(uint32_t dst, const void* src) {
    asm volatile("cp.async.ca.shared.global [%0], [%1], 16;" :: "r"(dst), "l"(src));
}
#define CP_COMMIT() asm volatile("cp.async.commit_group;" ::: "memory")
#define CP_WAIT(n) asm volatile("cp.async.wait_group %0;" :: "n"(n) : "memory")

__device__ __forceinline__ void mma_bf16(float* d, const uint32_t* a, const uint32_t* b) {
    asm volatile(
        "mma.sync.aligned.m16n8k16.row.col.f32.bf16.bf16.f32 "
        "{%0,%1,%2,%3},{%4,%5,%6,%7},{%8,%9},{%0,%1,%2,%3};"
        : "+f"(d[0]), "+f"(d[1]), "+f"(d[2]), "+f"(d[3])
        : "r"(a[0]), "r"(a[1]), "r"(a[2]), "r"(a[3]), "r"(b[0]), "r"(b[1]));
}

// -------- bf16 mma GEMM: C[8192,N] = A[8192,K]bf16 @ W[N,K]bf16^T --------
// CTA BM x 64; 8 warps; K chunk 32; 3-stage cp.async pipeline.
// OUTMODE: 0 = fp32 store, 1 = fp32 add-store, 2 = bf16 store.
#define AW 20            // smem row stride in words (40 bf16) — conflict-free frags
template <int BM, int OUTMODE>
__global__ __launch_bounds__(256) void gemm_bf16(
    const bf16* __restrict__ A, const bf16* __restrict__ W,
    void* __restrict__ Cv, int N_store, int K, int lda, int ldc) {
    constexpr int MW = BM / 32;       // M warps
    constexpr int NW = 8 / MW;        // N warps
    constexpr int WN = 64 / NW;       // warp N width
    constexpr int NT = WN / 8;        // n-tiles per warp
    constexpr int ASTG = BM * AW, BSTG = 64 * AW, STG = ASTG + BSTG;
    __shared__ __align__(16) uint32_t sm[3 * STG];
    const int tid = threadIdx.x, wid = tid >> 5, lane = tid & 31;
    const int warpM = wid % MW, warpN = wid / MW;
    const int quad = lane >> 2, qk = lane & 3;
    const int bm = blockIdx.y * BM, bn = blockIdx.x * 64;
    float acc[2][NT][4];
    #pragma unroll
    for (int i = 0; i < 2; ++i)
        #pragma unroll
        for (int j = 0; j < NT; ++j)
            #pragma unroll
            for (int k = 0; k < 4; ++k) acc[i][j][k] = 0.f;

    const bf16* Ab = A + (size_t)bm * lda;
    const bf16* Wb = W + (size_t)bn * K;
    const int nch = K >> 5;
    const uint32_t sm_u = smem_u32(sm);
    const int br = tid >> 2, bs = tid & 3;

    auto load_chunk = [&](int c, int st) {
        const bf16* Ac = Ab + c * 32;
        for (int fi = tid; fi < BM * 4; fi += 256) {
            int r = fi >> 2, sg = fi & 3;
            cp_async16(sm_u + (uint32_t)(st * STG + r * AW + sg * 4) * 4,
                       Ac + (size_t)r * lda + sg * 8);
        }
        cp_async16(sm_u + (uint32_t)(st * STG + ASTG + br * AW + bs * 4) * 4,
                   Wb + (size_t)br * K + c * 32 + bs * 8);
    };

    load_chunk(0, 0); CP_COMMIT();
    if (nch > 1) load_chunk(1, 1);
    CP_COMMIT();

    for (int c = 0; c < nch; ++c) {
        CP_WAIT(1);                       // chunk c complete
        __syncthreads();                  // all warps done with stage (c-1)%3
        if (c + 2 < nch) load_chunk(c + 2, (c + 2) % 3);
        CP_COMMIT();                      // one group per iteration (may be empty)
        const uint32_t* aB = sm + (c % 3) * STG;
        const uint32_t* bB = aB + ASTG;
        #pragma unroll
        for (int ks = 0; ks < 2; ++ks) {
            uint32_t a[2][4], b[NT][2];
            #pragma unroll
            for (int mt = 0; mt < 2; ++mt) {
                int rb = warpM * 32 + mt * 16 + quad;
                a[mt][0] = aB[rb * AW + ks * 8 + qk];
                a[mt][1] = aB[(rb + 8) * AW + ks * 8 + qk];
                a[mt][2] = aB[rb * AW + ks * 8 + qk + 4];
                a[mt][3] = aB[(rb + 8) * AW + ks * 8 + qk + 4];
            }
            #pragma unroll
            for (int nt = 0; nt < NT; ++nt) {
                int nb = warpN * WN + nt * 8 + quad;
                b[nt][0] = bB[nb * AW + ks * 8 + qk];
                b[nt][1] = bB[nb * AW + ks * 8 + qk + 4];
            }
            #pragma unroll
            for (int mt = 0; mt < 2; ++mt)
                #pragma unroll
                for (int nt = 0; nt < NT; ++nt)
                    mma_bf16(acc[mt][nt], a[mt], b[nt]);
        }
        __syncthreads();
    }

    #pragma unroll
    for (int mt = 0; mt < 2; ++mt) {
        int r0 = bm + warpM * 32 + mt * 16 + quad;
        #pragma unroll
        for (int nt = 0; nt < NT; ++nt) {
            int gc = bn + warpN * WN + nt * 8 + qk * 2;
            #pragma unroll
            for (int half = 0; half < 2; ++half) {
                int row = r0 + half * 8;
                float v0 = acc[mt][nt][half * 2 + 0];
                float v1 = acc[mt][nt][half * 2 + 1];
                size_t gi = (size_t)row * ldc + gc;
                if (OUTMODE == 2) {
                    bf16* C = (bf16*)Cv;
                    if (gc < N_store) C[gi] = __float2bfloat16(v0);
                    if (gc + 1 < N_store) C[gi + 1] = __float2bfloat16(v1);
                } else {
                    float* C = (float*)Cv;
                    if (gc < N_store) {
                        if (OUTMODE == 1) v0 += C[gi];
                        C[gi] = v0;
                    }
                    if (gc + 1 < N_store) {
                        if (OUTMODE == 1) v1 += C[gi + 1];
                        C[gi + 1] = v1;
                    }
                }
            }
        }
    }
}

// -------- rmsnorm: warp per token, bf16 out --------
__global__ void rmsnorm_kernel(const float* __restrict__ x, const float* __restrict__ w,
                               bf16* __restrict__ o, int ldo) {
    int tok = (blockIdx.x * blockDim.x + threadIdx.x) >> 5;
    int lane = threadIdx.x & 31;
    if (tok >= NTOK) return;
    const float* xr = x + (size_t)tok * D_MODEL;
    float ss = 0.f;
    for (int i = lane; i < D_MODEL; i += 32) { float v = xr[i]; ss += v * v; }
    #pragma unroll
    for (int off = 16; off; off >>= 1) ss += __shfl_xor_sync(~0u, ss, off);
    float inv = rsqrtf(ss * (1.f / D_MODEL) + EPS);
    for (int i = lane; i < D_MODEL; i += 32)
        o[(size_t)tok * ldo + i] = __float2bfloat16(xr[i] * inv * w[i]);
}

__global__ void final_kernel(const float* __restrict__ f, const float* __restrict__ x,
                             const float* __restrict__ w, float* __restrict__ o) {
    int tok = (blockIdx.x * blockDim.x + threadIdx.x) >> 5;
    int lane = threadIdx.x & 31;
    if (tok >= NTOK) return;
    const float* xr = x + (size_t)tok * D_MODEL;
    float ss = 0.f;
    for (int i = lane; i < D_MODEL; i += 32) { float v = xr[i]; ss += v * v; }
    #pragma unroll
    for (int off = 16; off; off >>= 1) ss += __shfl_xor_sync(~0u, ss, off);
    float inv = rsqrtf(ss * (1.f / D_MODEL) + EPS);
    for (int i = lane; i < D_MODEL; i += 32)
        o[(size_t)tok * D_MODEL + i] = f[(size_t)tok * D_MODEL + i] + xr[i] * inv * w[i];
}

// -------- conv(k=4, causal) + silu: register window over 64-token tiles --------
#define CLT 64
__global__ void conv_silu_kernel(const bf16* __restrict__ xz, const float* __restrict__ cw,
                                 const float* __restrict__ cb, bf16* __restrict__ xc) {
    int d = blockIdx.x * 128 + threadIdx.x;
    if (d >= D_INNER) return;
    int l0 = blockIdx.y * CLT, b = blockIdx.z;
    float w0 = cw[d * 4 + 0], w1 = cw[d * 4 + 1], w2 = cw[d * 4 + 2], w3 = cw[d * 4 + 3];
    float bb = cb[d];
    size_t row = (size_t)b * L_SEQ + l0;
    const bf16* src = xz + row * TWO_DI + d;
    bf16* dst = xc + row * KI + d;
    float x0, x1, x2;
    if (l0 == 0) { x0 = x1 = x2 = 0.f; }
    else {
        x0 = __bfloat162float(src[-3 * TWO_DI]);
        x1 = __bfloat162float(src[-2 * TWO_DI]);
        x2 = __bfloat162float(src[-1 * TWO_DI]);
    }
    #pragma unroll 4
    for (int i = 0; i < CLT; ++i) {
        float x3 = __bfloat162float(src[(size_t)i * TWO_DI]);
        float acc = bb + w0 * x0 + w1 * x1 + w2 * x2 + w3 * x3;
        dst[(size_t)i * KI] = __float2bfloat16(acc / (1.f + __expf(-acc)));
        x0 = x1; x1 = x2; x2 = x3;
    }
}

// -------- dt = softplus(dt_lo @ dtw^T + dtb), bf16 out --------
#define DT_TB 16
__global__ __launch_bounds__(256) void dt_kernel(
    const float* __restrict__ xdbl, const float* __restrict__ dtw,
    const float* __restrict__ dtb, bf16* __restrict__ dt) {
    __shared__ float sw[D_INNER * DT_RANK];
    __shared__ float slo[DT_TB][DT_RANK];
    int m0 = blockIdx.x * DT_TB;
    for (int i = threadIdx.x; i < D_INNER * DT_RANK; i += 256) sw[i] = dtw[i];
    for (int i = threadIdx.x; i < DT_TB * DT_RANK; i += 256)
        slo[i / DT_RANK][i % DT_RANK] = xdbl[(size_t)(m0 + i / DT_RANK) * XW + i % DT_RANK];
    __syncthreads();
    for (int idx = threadIdx.x; idx < DT_TB * D_INNER; idx += 256) {
        int t = idx / D_INNER, d = idx - t * D_INNER;
        float acc = dtb[d];
        #pragma unroll
        for (int r = 0; r < DT_RANK; ++r) acc += slo[t][r] * sw[d * DT_RANK + r];
        float sp = (acc > 20.f) ? acc : log1pf(__expf(acc));
        dt[(size_t)(m0 + t) * D_INNER + d] = __float2bfloat16(sp);
    }
}

// -------- chunked selective scan --------
// lane mapping: warp = 2 channels x 16 states; block 128 thr = 8 channels.
#define SCH 8
// S1: per-chunk local state (h from 0) + sum(dt)
__global__ __launch_bounds__(128) void scan1_kernel(
    const bf16* __restrict__ dt, const bf16* __restrict__ u,
    const float* __restrict__ xdbl, const float* __restrict__ A_log,
    float* __restrict__ Lc, float* __restrict__ sdtc) {
    __shared__ float s_dt[SCH][CT], s_u[SCH][CT], s_B[CT][16];
    int b = blockIdx.z, c = blockIdx.y, d0 = blockIdx.x * SCH;
    int tid = threadIdx.x, lane = tid & 31, warp = tid >> 5;
    int s = lane & 15, dloc = warp * 2 + (lane >> 4), d = d0 + dloc;
    int dc = (d < D_INNER) ? d : (D_INNER - 1);
    float Av = -__expf(A_log[(size_t)dc * 16 + s]);
    size_t rb = (size_t)b * L_SEQ + (size_t)c * CT;
    for (int idx = tid; idx < SCH * CT; idx += 128) {
        int ch = idx & 7, t = idx >> 3;
        int dd = d0 + ch; if (dd >= D_INNER) dd = D_INNER - 1;
        s_dt[ch][t] = __bfloat162float(dt[(rb + t) * D_INNER + dd]);
        s_u[ch][t]  = __bfloat162float(u[(rb + t) * KI + dd]);
    }
    for (int idx = tid; idx < CT * 16; idx += 128) {
        int ss = idx & 15, t = idx >> 4;
        s_B[t][ss] = xdbl[(rb + t) * XW + DT_RANK + ss];
    }
    __syncthreads();
    float h = 0.f, sd = 0.f;
    #pragma unroll 4
    for (int t = 0; t < CT; ++t) {
        float dtv = s_dt[dloc][t];
        h = __expf(dtv * Av) * h + (dtv * s_u[dloc][t]) * s_B[t][s];
        sd += dtv;
    }
    if (d < D_INNER) {
        size_t o = (((size_t)b * NCHK + c) * D_INNER + d);
        Lc[o * 16 + s] = h;
        if (s == 0) sdtc[o] = sd;
    }
}

// S2: stitch 16 chunk summaries -> initial state per chunk
__global__ void scan2_kernel(const float* __restrict__ Lc, const float* __restrict__ sdtc,
                             const float* __restrict__ A_log, float* __restrict__ H0) {
    int idx = blockIdx.x * 128 + threadIdx.x;
    if (idx >= B_SZ * D_INNER * D_STATE) return;
    int s = idx & 15, rest = idx >> 4;
    int d = rest % D_INNER, b = rest / D_INNER;
    float Av = -__expf(A_log[(size_t)d * 16 + s]);
    float h = 0.f;
    #pragma unroll
    for (int c = 0; c < NCHK; ++c) {
        size_t o = (((size_t)b * NCHK + c) * D_INNER + d);
        H0[o * 16 + s] = h;
        h = __expf(Av * sdtc[o]) * h + Lc[o * 16 + s];
    }
}

// S3: replay with correct initial state, compute y + fused gate
__global__ __launch_bounds__(128) void scan3_kernel(
    const bf16* __restrict__ dt, const bf16* __restrict__ u,
    const float* __restrict__ xdbl, const bf16* __restrict__ xz,
    const float* __restrict__ A_log, const float* __restrict__ Dp,
    const float* __restrict__ H0, bf16* __restrict__ y2) {
    __shared__ float s_dt[SCH][CT], s_u[SCH][CT], s_z[SCH][CT];
    __shared__ float s_B[CT][16], s_C[CT][16];
    int b = blockIdx.z, c = blockIdx.y, d0 = blockIdx.x * SCH;
    int tid = threadIdx.x, lane = tid & 31, warp = tid >> 5;
    int s = lane & 15, dloc = warp * 2 + (lane >> 4), d = d0 + dloc;
    int dc = (d < D_INNER) ? d : (D_INNER - 1);
    float Av = -__expf(A_log[(size_t)dc * 16 + s]);
    float Dv = Dp[dc];
    size_t rb = (size_t)b * L_SEQ + (size_t)c * CT;
    for (int idx = tid; idx < SCH * CT; idx += 128) {
        int ch = idx & 7, t = idx >> 3;
        int dd = d0 + ch; if (dd >= D_INNER) dd = D_INNER - 1;
        s_dt[ch][t] = __bfloat162float(dt[(rb + t) * D_INNER + dd]);
        s_u[ch][t]  = __bfloat162float(u[(rb + t) * KI + dd]);
        s_z[ch][t]  = __bfloat162float(xz[(rb + t) * TWO_DI + D_INNER + dd]);
    }
    for (int idx = tid; idx < CT * 16; idx += 128) {
        int ss = idx & 15, t = idx >> 4;
        const float* g = xdbl + (rb + t) * XW + DT_RANK;
        s_B[t][ss] = g[ss];
        s_C[t][ss] = g[16 + ss];
    }
    __syncthreads();
    float h = (d < D_INNER) ? H0[(((size_t)b * NCHK + c) * D_INNER + d) * 16 + s] : 0.f;
    #pragma unroll 4
    for (int t = 0; t < CT; ++t) {
        float dtv = s_dt[dloc][t], uv = s_u[dloc][t];
        h = __expf(dtv * Av) * h + (dtv * uv) * s_B[t][s];
        float p = h * s_C[t][s];
        p += __shfl_xor_sync(~0u, p, 8);
        p += __shfl_xor_sync(~0u, p, 4);
        p += __shfl_xor_sync(~0u, p, 2);
        p += __shfl_xor_sync(~0u, p, 1);
        if (s == 0 && d < D_INNER) {
            float z = s_z[dloc][t];
            y2[(rb + t) * KI + d] =
                __float2bfloat16((p + uv * Dv) * (z / (1.f + __expf(-z))));
        }
    }
}

// -------- weight packing --------
__global__ void pack1_kernel(const float* __restrict__ ipw, bf16* __restrict__ win) {
    int i = blockIdx.x * 256 + threadIdx.x;
    int total = N_LAYERS * 1032 * 258;
    if (i >= total) return;
    int k = i % 258, nr = i / 258, n = nr % 1032, l = nr / 1032;
    win[((size_t)l * WIN_R + n) * KM + k] = __float2bfloat16(ipw[i]);
}
__global__ void pack2_kernel(const float* __restrict__ opw, const float* __restrict__ xpw,
                             bf16* __restrict__ wout, bf16* __restrict__ wxp) {
    int i = blockIdx.x * 256 + threadIdx.x;
    const int OUT_T = N_LAYERS * 258 * 516, XP_T = N_LAYERS * 49 * 516;
    if (i < OUT_T) {
        int k = i % 516, nr = i / 516, n = nr % 258, l = nr / 258;
        wout[((size_t)l * WOUT_R + n) * KI + k] = __float2bfloat16(opw[i]);
    } else if (i < OUT_T + XP_T) {
        int j = i - OUT_T;
        int k = j % 516, nr = j / 516, n = nr % 49, l = nr / 49;
        wxp[((size_t)l * WXP_R + n) * KI + k] = __float2bfloat16(xpw[j]);
    }
}

// -------- host --------
extern "C" void kernel_launch(void* const* d_in, const int* in_sizes, int n_in,
                              void* d_out, int out_size) {
    const float* fuse  = (const float*)d_in[0];
    const float* nwv   = (const float*)d_in[1];
    const float* ipw   = (const float*)d_in[2];
    const float* cwv   = (const float*)d_in[3];
    const float* cbv   = (const float*)d_in[4];
    const float* xpw   = (const float*)d_in[5];
    const float* dtwv  = (const float*)d_in[6];
    const float* dtbv  = (const float*)d_in[7];
    const float* Alv   = (const float*)d_in[8];
    const float* Dpv   = (const float*)d_in[9];
    const float* opw   = (const float*)d_in[10];
    const float* fw    = (const float*)d_in[11];
    float* out = (float*)d_out;

    float *p_x, *p_xdbl, *p_L, *p_H0, *p_sdt;
    bf16 *p_xn, *p_xz, *p_xc, *p_dt, *p_y2, *p_win, *p_wout, *p_wxp;
    cudaGetSymbolAddress((void**)&p_x, g_x);
    cudaGetSymbolAddress((void**)&p_xn, g_xn);
    cudaGetSymbolAddress((void**)&p_xz, g_xz);
    cudaGetSymbolAddress((void**)&p_xc, g_xc);
    cudaGetSymbolAddress((void**)&p_xdbl, g_xdbl);
    cudaGetSymbolAddress((void**)&p_dt, g_dt);
    cudaGetSymbolAddress((void**)&p_y2, g_y2);
    cudaGetSymbolAddress((void**)&p_win, g_win);
    cudaGetSymbolAddress((void**)&p_wout, g_wout);
    cudaGetSymbolAddress((void**)&p_wxp, g_wxp);
    cudaGetSymbolAddress((void**)&p_L, g_L);
    cudaGetSymbolAddress((void**)&p_H0, g_H0);
    cudaGetSymbolAddress((void**)&p_sdt, g_sdt);

    pack1_kernel<<<(N_LAYERS * 1032 * 258 + 255) / 256, 256>>>(ipw, p_win);
    {
        int tot = N_LAYERS * 258 * 516 + N_LAYERS * 49 * 516;
        pack2_kernel<<<(tot + 255) / 256, 256>>>(opw, xpw, p_wout, p_wxp);
    }
    cudaMemcpyAsync(p_x, fuse, (size_t)NTOK * D_MODEL * sizeof(float),
                    cudaMemcpyDeviceToDevice);

    for (int l = 0; l < N_LAYERS; ++l) {
        rmsnorm_kernel<<<NTOK / 8, 256>>>(p_x, nwv + (size_t)l * D_MODEL, p_xn, KM);
        gemm_bf16<128, 2><<<dim3(17, 64), 256>>>(p_xn, p_win + (size_t)l * WIN_R * KM,
                                                 p_xz, TWO_DI, KM, KM, TWO_DI);
        conv_silu_kernel<<<dim3(5, L_SEQ / CLT, B_SZ), 128>>>(
            p_xz, cwv + (size_t)l * D_INNER * 4, cbv + (size_t)l * D_INNER, p_xc);
        gemm_bf16<32, 0><<<dim3(1, 256), 256>>>(p_xc, p_wxp + (size_t)l * WXP_R * KI,
                                                p_xdbl, 49, KI, KI, XW);
        dt_kernel<<<NTOK / DT_TB, 256>>>(p_xdbl, dtwv + (size_t)l * D_INNER * DT_RANK,
                                         dtbv + (size_t)l * D_INNER, p_dt);
        scan1_kernel<<<dim3(65, NCHK, B_SZ), 128>>>(
            p_dt, p_xc, p_xdbl, Alv + (size_t)l * D_INNER * 16, p_L, p_sdt);
        scan2_kernel<<<(B_SZ * D_INNER * D_STATE + 127) / 128, 128>>>(
            p_L, p_sdt, Alv + (size_t)l * D_INNER * 16, p_H0);
        scan3_kernel<<<dim3(65, NCHK, B_SZ), 128>>>(
            p_dt, p_xc, p_xdbl, p_xz, Alv + (size_t)l * D_INNER * 16,
            Dpv + (size_t)l * D_INNER, p_H0, p_y2);
        gemm_bf16<128, 1><<<dim3(5, 64), 256>>>(p_y2, p_wout + (size_t)l * WOUT_R * KI,
                                                p_x, D_MODEL, KI, KI, D_MODEL);
    }
    final_kernel<<<NTOK / 8, 256>>>(fuse, p_x, fw, out);
    (void)in_sizes; (void)n_in; (void)out_size;
}

// round 7
// speedup vs baseline: 2.5983x; 1.2319x over previous
#include <cuda_runtime.h>
#include <cuda_bf16.h>
#include <math.h>
#include <stdint.h>

#define B_SZ 4
#define L_SEQ 2048
#define D_MODEL 258
#define N_LAYERS 4
#define D_STATE 16
#define D_INNER 516
#define DT_RANK 17
#define TWO_DI 1032
#define XW 56            // padded xdbl stride (49 real cols)
#define NTOK 8192
#define EPS 1e-5f
#define KM 288           // 258 padded to 32-chunks
#define KI 544           // 516 padded
#define WIN_R 1088       // 17 * 64
#define WOUT_R 320       // 5 * 64
#define WXP_R 64
#define NCHK 16          // scan chunks
#define SCT 128          // tokens per scan chunk
#define STL 32           // scan stage tile (tokens)

typedef __nv_bfloat16 bf16;

// -------- device scratch (zero-init; +pad for vectorized edge reads) --------
__device__ __align__(256) float g_x[NTOK * D_MODEL];
__device__ __align__(256) bf16  g_xn[NTOK * KM];
__device__ __align__(256) bf16  g_xz[NTOK * TWO_DI + 256];
__device__ __align__(256) bf16  g_xc[NTOK * KI + 256];
__device__ __align__(256) float g_xdbl[NTOK * XW];
__device__ __align__(256) bf16  g_dt[NTOK * D_INNER + 256];
__device__ __align__(256) bf16  g_y2[NTOK * KI];
__device__ __align__(256) bf16  g_win[N_LAYERS * WIN_R * KM];
__device__ __align__(256) bf16  g_wout[N_LAYERS * WOUT_R * KI];
__device__ __align__(256) bf16  g_wxp[N_LAYERS * WXP_R * KI];
__device__ __align__(256) float g_L[B_SZ * NCHK * D_INNER * D_STATE];
__device__ __align__(256) float g_H0[B_SZ * NCHK * D_INNER * D_STATE];
__device__ __align__(256) float g_sdt[B_SZ * NCHK * D_INNER];

// -------- helpers --------
__device__ __forceinline__ uint32_t smem_u32(const void* p) {
    uint32_t a;
    asm("{ .reg .u64 t; cvta.to.shared.u64 t, %1; cvt.u32.u64 %0, t; }" : "=r"(a) : "l"(p));
    return a;
}
__device__ __forceinline__ void cp_async16(uint32_t dst, const void* src) {
    asm volatile("cp.async.ca.shared.global [%0], [%1], 16;" :: "r"(dst), "l"(src));
}
#define CP_COMMIT() asm volatile("cp.async.commit_group;" ::: "memory")
#define CP_WAIT(n) asm volatile("cp.async.wait_group %0;" :: "n"(n) : "memory")

__device__ __forceinline__ void mma_bf16(float* d, const uint32_t* a, const uint32_t* b) {
    asm volatile(
        "mma.sync.aligned.m16n8k16.row.col.f32.bf16.bf16.f32 "
        "{%0,%1,%2,%3},{%4,%5,%6,%7},{%8,%9},{%0,%1,%2,%3};"
        : "+f"(d[0]), "+f"(d[1]), "+f"(d[2]), "+f"(d[3])
        : "r"(a[0]), "r"(a[1]), "r"(a[2]), "r"(a[3]), "r"(b[0]), "r"(b[1]));
}
__device__ __forceinline__ void ldsm_x4(uint32_t* r, uint32_t addr) {
    asm volatile("ldmatrix.sync.aligned.m8n8.x4.shared.b16 {%0,%1,%2,%3}, [%4];"
        : "=r"(r[0]), "=r"(r[1]), "=r"(r[2]), "=r"(r[3]) : "r"(addr));
}
__device__ __forceinline__ void ldsm_x2(uint32_t* r, uint32_t addr) {
    asm volatile("ldmatrix.sync.aligned.m8n8.x2.shared.b16 {%0,%1}, [%2];"
        : "=r"(r[0]), "=r"(r[1]) : "r"(addr));
}

// -------- bf16 mma GEMM: C[8192,N] = A[8192,K]bf16 @ W[N,K]bf16^T --------
// CTA BM x 64; 8 warps; K chunk 32; 3-stage cp.async; ldmatrix fragments.
// OUTMODE: 0 = fp32 store, 1 = fp32 add-store, 2 = bf16 store.
#define AW 20            // smem row stride in words (40 bf16)
template <int BM, int OUTMODE>
__global__ __launch_bounds__(256) void gemm_bf16(
    const bf16* __restrict__ A, const bf16* __restrict__ W,
    void* __restrict__ Cv, int N_store, int K, int lda, int ldc) {
    constexpr int MW = BM / 32;
    constexpr int NW = 8 / MW;
    constexpr int WN = 64 / NW;
    constexpr int NT = WN / 8;
    constexpr int ASTG = BM * AW, BSTG = 64 * AW, STG = ASTG + BSTG;
    __shared__ __align__(16) uint32_t sm[3 * STG];
    const int tid = threadIdx.x, wid = tid >> 5, lane = tid & 31;
    const int warpM = wid % MW, warpN = wid / MW;
    const int quad = lane >> 2, qk = lane & 3;
    const int bm = blockIdx.y * BM, bn = blockIdx.x * 64;
    float acc[2][NT][4];
    #pragma unroll
    for (int i = 0; i < 2; ++i)
        #pragma unroll
        for (int j = 0; j < NT; ++j)
            #pragma unroll
            for (int k = 0; k < 4; ++k) acc[i][j][k] = 0.f;

    const bf16* Ab = A + (size_t)bm * lda;
    const bf16* Wb = W + (size_t)bn * K;
    const int nch = K >> 5;
    const uint32_t sm_u = smem_u32(sm);
    const int br = tid >> 2, bs = tid & 3;
    const int l8 = lane & 7, jm = lane >> 3;

    // ldmatrix lane base addresses (bytes)
    const uint32_t aLM = sm_u +
        (uint32_t)(((warpM * 32 + ((jm & 1) << 3) + l8) * AW + ((jm >> 1) << 2)) * 4);
    const uint32_t bLM4 = sm_u + ASTG * 4 +
        (uint32_t)(((warpN * WN + ((jm >> 1) << 3) + l8) * AW + ((jm & 1) << 2)) * 4);
    const uint32_t bLM2 = sm_u + ASTG * 4 +
        (uint32_t)(((warpN * WN + l8) * AW + (((lane >> 3) & 1) << 2)) * 4);

    auto load_chunk = [&](int c, int st) {
        const bf16* Ac = Ab + c * 32;
        for (int fi = tid; fi < BM * 4; fi += 256) {
            int r = fi >> 2, sg = fi & 3;
            cp_async16(sm_u + (uint32_t)(st * STG + r * AW + sg * 4) * 4,
                       Ac + (size_t)r * lda + sg * 8);
        }
        cp_async16(sm_u + (uint32_t)(st * STG + ASTG + br * AW + bs * 4) * 4,
                   Wb + (size_t)br * K + c * 32 + bs * 8);
    };

    load_chunk(0, 0); CP_COMMIT();
    if (nch > 1) load_chunk(1, 1);
    CP_COMMIT();

    for (int c = 0; c < nch; ++c) {
        CP_WAIT(1);
        __syncthreads();
        if (c + 2 < nch) load_chunk(c + 2, (c + 2) % 3);
        CP_COMMIT();
        const uint32_t stOff = (uint32_t)((c % 3) * STG * 4);
        #pragma unroll
        for (int ks = 0; ks < 2; ++ks) {
            uint32_t a[2][4], b[NT][2];
            #pragma unroll
            for (int mt = 0; mt < 2; ++mt)
                ldsm_x4(a[mt], aLM + stOff + (uint32_t)(mt * 16 * AW * 4 + ks * 32));
            if (NT == 4) {
                uint32_t t0[4], t1[4];
                ldsm_x4(t0, bLM4 + stOff + (uint32_t)(ks * 32));
                ldsm_x4(t1, bLM4 + stOff + (uint32_t)(16 * AW * 4 + ks * 32));
                b[0][0] = t0[0]; b[0][1] = t0[1];
                b[1][0] = t0[2]; b[1][1] = t0[3];
                b[2][0] = t1[0]; b[2][1] = t1[1];
                b[3][0] = t1[2]; b[3][1] = t1[3];
            } else {
                ldsm_x2(b[0], bLM2 + stOff + (uint32_t)(ks * 32));
            }
            #pragma unroll
            for (int mt = 0; mt < 2; ++mt)
                #pragma unroll
                for (int nt = 0; nt < NT; ++nt)
                    mma_bf16(acc[mt][nt], a[mt], b[nt]);
        }
        __syncthreads();
    }

    #pragma unroll
    for (int mt = 0; mt < 2; ++mt) {
        int r0 = bm + warpM * 32 + mt * 16 + quad;
        #pragma unroll
        for (int nt = 0; nt < NT; ++nt) {
            int gc = bn + warpN * WN + nt * 8 + qk * 2;
            #pragma unroll
            for (int half = 0; half < 2; ++half) {
                int row = r0 + half * 8;
                float v0 = acc[mt][nt][half * 2 + 0];
                float v1 = acc[mt][nt][half * 2 + 1];
                size_t gi = (size_t)row * ldc + gc;
                if (OUTMODE == 2) {
                    bf16* C = (bf16*)Cv;
                    if (gc < N_store) C[gi] = __float2bfloat16(v0);
                    if (gc + 1 < N_store) C[gi + 1] = __float2bfloat16(v1);
                } else {
                    float* C = (float*)Cv;
                    if (gc < N_store) {
                        if (OUTMODE == 1) v0 += C[gi];
                        C[gi] = v0;
                    }
                    if (gc + 1 < N_store) {
                        if (OUTMODE == 1) v1 += C[gi + 1];
                        C[gi + 1] = v1;
                    }
                }
            }
        }
    }
}

// -------- rmsnorm: warp per token, bf16 out --------
__global__ void rmsnorm_kernel(const float* __restrict__ x, const float* __restrict__ w,
                               bf16* __restrict__ o, int ldo) {
    int tok = (blockIdx.x * blockDim.x + threadIdx.x) >> 5;
    int lane = threadIdx.x & 31;
    if (tok >= NTOK) return;
    const float* xr = x + (size_t)tok * D_MODEL;
    float ss = 0.f;
    for (int i = lane; i < D_MODEL; i += 32) { float v = xr[i]; ss += v * v; }
    #pragma unroll
    for (int off = 16; off; off >>= 1) ss += __shfl_xor_sync(~0u, ss, off);
    float inv = rsqrtf(ss * (1.f / D_MODEL) + EPS);
    for (int i = lane; i < D_MODEL; i += 32)
        o[(size_t)tok * ldo + i] = __float2bfloat16(xr[i] * inv * w[i]);
}

__global__ void final_kernel(const float* __restrict__ f, const float* __restrict__ x,
                             const float* __restrict__ w, float* __restrict__ o) {
    int tok = (blockIdx.x * blockDim.x + threadIdx.x) >> 5;
    int lane = threadIdx.x & 31;
    if (tok >= NTOK) return;
    const float* xr = x + (size_t)tok * D_MODEL;
    float ss = 0.f;
    for (int i = lane; i < D_MODEL; i += 32) { float v = xr[i]; ss += v * v; }
    #pragma unroll
    for (int off = 16; off; off >>= 1) ss += __shfl_xor_sync(~0u, ss, off);
    float inv = rsqrtf(ss * (1.f / D_MODEL) + EPS);
    for (int i = lane; i < D_MODEL; i += 32)
        o[(size_t)tok * D_MODEL + i] = f[(size_t)tok * D_MODEL + i] + xr[i] * inv * w[i];
}

// -------- conv(k=4, causal) + silu: register window over 64-token tiles --------
#define CLT 64
__global__ void conv_silu_kernel(const bf16* __restrict__ xz, const float* __restrict__ cw,
                                 const float* __restrict__ cb, bf16* __restrict__ xc) {
    int d = blockIdx.x * 128 + threadIdx.x;
    if (d >= D_INNER) return;
    int l0 = blockIdx.y * CLT, b = blockIdx.z;
    float w0 = cw[d * 4 + 0], w1 = cw[d * 4 + 1], w2 = cw[d * 4 + 2], w3 = cw[d * 4 + 3];
    float bb = cb[d];
    size_t row = (size_t)b * L_SEQ + l0;
    const bf16* src = xz + row * TWO_DI + d;
    bf16* dst = xc + row * KI + d;
    float x0, x1, x2;
    if (l0 == 0) { x0 = x1 = x2 = 0.f; }
    else {
        x0 = __bfloat162float(src[-3 * TWO_DI]);
        x1 = __bfloat162float(src[-2 * TWO_DI]);
        x2 = __bfloat162float(src[-1 * TWO_DI]);
    }
    #pragma unroll 4
    for (int i = 0; i < CLT; ++i) {
        float x3 = __bfloat162float(src[(size_t)i * TWO_DI]);
        float acc = bb + w0 * x0 + w1 * x1 + w2 * x2 + w3 * x3;
        dst[(size_t)i * KI] = __float2bfloat16(acc / (1.f + __expf(-acc)));
        x0 = x1; x1 = x2; x2 = x3;
    }
}

// -------- dt = softplus(dt_lo @ dtw^T + dtb), bf16 out --------
#define DT_TB 16
__global__ __launch_bounds__(256) void dt_kernel(
    const float* __restrict__ xdbl, const float* __restrict__ dtw,
    const float* __restrict__ dtb, bf16* __restrict__ dt) {
    __shared__ float sw[D_INNER * DT_RANK];
    __shared__ float slo[DT_TB][DT_RANK];
    int m0 = blockIdx.x * DT_TB;
    for (int i = threadIdx.x; i < D_INNER * DT_RANK; i += 256) sw[i] = dtw[i];
    for (int i = threadIdx.x; i < DT_TB * DT_RANK; i += 256)
        slo[i / DT_RANK][i % DT_RANK] = xdbl[(size_t)(m0 + i / DT_RANK) * XW + i % DT_RANK];
    __syncthreads();
    for (int idx = threadIdx.x; idx < DT_TB * D_INNER; idx += 256) {
        int t = idx / D_INNER, d = idx - t * D_INNER;
        float acc = dtb[d];
        #pragma unroll
        for (int r = 0; r < DT_RANK; ++r) acc += slo[t][r] * sw[d * DT_RANK + r];
        float sp = (acc > 20.f) ? acc : log1pf(__expf(acc));
        dt[(size_t)(m0 + t) * D_INNER + d] = __float2bfloat16(sp);
    }
}

// -------- chunked selective scan: thread-per-channel, h[16] in regs --------
// S1: per-chunk local state (h from 0) + sum(dt)
__global__ __launch_bounds__(128) void scan1_kernel(
    const bf16* __restrict__ dt, const bf16* __restrict__ u,
    const float* __restrict__ xdbl, const float* __restrict__ A_log,
    float* __restrict__ Lc, float* __restrict__ sdtc) {
    __shared__ float sB[SCT][16];
    __shared__ bf16 s_dt[STL][128];
    __shared__ bf16 s_u[STL][128];
    int b = blockIdx.z, c = blockIdx.y, d0 = blockIdx.x * 128;
    int tid = threadIdx.x;
    int d = d0 + tid;
    bool act = d < D_INNER;
    int dc = act ? d : (D_INNER - 1);
    size_t rb = (size_t)b * L_SEQ + (size_t)c * SCT;
    float Av[16];
    #pragma unroll
    for (int s = 0; s < 16; s += 4) {
        float4 al = *(const float4*)(A_log + (size_t)dc * 16 + s);
        Av[s + 0] = -__expf(al.x); Av[s + 1] = -__expf(al.y);
        Av[s + 2] = -__expf(al.z); Av[s + 3] = -__expf(al.w);
    }
    for (int i = tid; i < SCT * 16; i += 128) {
        int t = i >> 4, s = i & 15;
        sB[t][s] = xdbl[(rb + t) * XW + DT_RANK + s];
    }
    float h[16];
    #pragma unroll
    for (int s = 0; s < 16; ++s) h[s] = 0.f;
    float sd = 0.f;
    for (int t0 = 0; t0 < SCT; t0 += STL) {
        __syncthreads();
        for (int q = tid; q < STL * 64; q += 128) {
            int tt = q >> 6, dp = (q & 63) * 2;
            *(uint32_t*)&s_dt[tt][dp] = *(const uint32_t*)(dt + (rb + t0 + tt) * D_INNER + d0 + dp);
            *(uint32_t*)&s_u[tt][dp]  = *(const uint32_t*)(u  + (rb + t0 + tt) * KI + d0 + dp);
        }
        __syncthreads();
        for (int tt = 0; tt < STL; ++tt) {
            float dtv = __bfloat162float(s_dt[tt][tid]);
            float uv  = __bfloat162float(s_u[tt][tid]);
            float e = dtv * uv;
            sd += dtv;
            const float4* pB = (const float4*)sB[t0 + tt];
            #pragma unroll
            for (int s4 = 0; s4 < 4; ++s4) {
                float4 Bv = pB[s4];
                h[s4*4+0] = __expf(dtv * Av[s4*4+0]) * h[s4*4+0] + e * Bv.x;
                h[s4*4+1] = __expf(dtv * Av[s4*4+1]) * h[s4*4+1] + e * Bv.y;
                h[s4*4+2] = __expf(dtv * Av[s4*4+2]) * h[s4*4+2] + e * Bv.z;
                h[s4*4+3] = __expf(dtv * Av[s4*4+3]) * h[s4*4+3] + e * Bv.w;
            }
        }
    }
    if (act) {
        size_t o = ((size_t)b * NCHK + c) * D_INNER + d;
        float4* pL = (float4*)(Lc + o * 16);
        #pragma unroll
        for (int s4 = 0; s4 < 4; ++s4)
            pL[s4] = make_float4(h[s4*4+0], h[s4*4+1], h[s4*4+2], h[s4*4+3]);
        sdtc[o] = sd;
    }
}

// S2: stitch chunk summaries -> initial state per chunk
__global__ void scan2_kernel(const float* __restrict__ Lc, const float* __restrict__ sdtc,
                             const float* __restrict__ A_log, float* __restrict__ H0) {
    int idx = blockIdx.x * 128 + threadIdx.x;
    if (idx >= B_SZ * D_INNER * D_STATE) return;
    int s = idx & 15, rest = idx >> 4;
    int d = rest % D_INNER, b = rest / D_INNER;
    float Av = -__expf(A_log[(size_t)d * 16 + s]);
    float h = 0.f;
    #pragma unroll
    for (int c = 0; c < NCHK; ++c) {
        size_t o = (((size_t)b * NCHK + c) * D_INNER + d);
        H0[o * 16 + s] = h;
        h = __expf(Av * sdtc[o]) * h + Lc[o * 16 + s];
    }
}

// S3: replay with initial state, y + fused gate; bf16 out
__global__ __launch_bounds__(128) void scan3_kernel(
    const bf16* __restrict__ dt, const bf16* __restrict__ u,
    const float* __restrict__ xdbl, const bf16* __restrict__ xz,
    const float* __restrict__ A_log, const float* __restrict__ Dp,
    const float* __restrict__ H0, bf16* __restrict__ y2) {
    __shared__ float sB[SCT][16];
    __shared__ float sC[SCT][16];
    __shared__ bf16 s_dt[STL][128];
    __shared__ bf16 s_u[STL][128];
    __shared__ bf16 s_z[STL][128];
    int b = blockIdx.z, c = blockIdx.y, d0 = blockIdx.x * 128;
    int tid = threadIdx.x;
    int d = d0 + tid;
    bool act = d < D_INNER;
    int dc = act ? d : (D_INNER - 1);
    size_t rb = (size_t)b * L_SEQ + (size_t)c * SCT;
    float Av[16];
    #pragma unroll
    for (int s = 0; s < 16; s += 4) {
        float4 al = *(const float4*)(A_log + (size_t)dc * 16 + s);
        Av[s + 0] = -__expf(al.x); Av[s + 1] = -__expf(al.y);
        Av[s + 2] = -__expf(al.z); Av[s + 3] = -__expf(al.w);
    }
    float Dv = Dp[dc];
    for (int i = tid; i < SCT * 16; i += 128) {
        int t = i >> 4, s = i & 15;
        const float* g = xdbl + (rb + t) * XW + DT_RANK;
        sB[t][s] = g[s];
        sC[t][s] = g[16 + s];
    }
    float h[16];
    {
        size_t o = ((size_t)b * NCHK + c) * D_INNER + dc;
        const float4* pH = (const float4*)(H0 + o * 16);
        #pragma unroll
        for (int s4 = 0; s4 < 4; ++s4) {
            float4 hv = pH[s4];
            h[s4*4+0] = hv.x; h[s4*4+1] = hv.y; h[s4*4+2] = hv.z; h[s4*4+3] = hv.w;
        }
    }
    for (int t0 = 0; t0 < SCT; t0 += STL) {
        __syncthreads();
        for (int q = tid; q < STL * 64; q += 128) {
            int tt = q >> 6, dp = (q & 63) * 2;
            *(uint32_t*)&s_dt[tt][dp] = *(const uint32_t*)(dt + (rb + t0 + tt) * D_INNER + d0 + dp);
            *(uint32_t*)&s_u[tt][dp]  = *(const uint32_t*)(u  + (rb + t0 + tt) * KI + d0 + dp);
            *(uint32_t*)&s_z[tt][dp]  = *(const uint32_t*)(xz + (rb + t0 + tt) * TWO_DI + D_INNER + d0 + dp);
        }
        __syncthreads();
        for (int tt = 0; tt < STL; ++tt) {
            float dtv = __bfloat162float(s_dt[tt][tid]);
            float uv  = __bfloat162float(s_u[tt][tid]);
            float e = dtv * uv;
            const float4* pB = (const float4*)sB[t0 + tt];
            const float4* pC = (const float4*)sC[t0 + tt];
            float y = 0.f;
            #pragma unroll
            for (int s4 = 0; s4 < 4; ++s4) {
                float4 Bv = pB[s4];
                float4 Cv = pC[s4];
                h[s4*4+0] = __expf(dtv * Av[s4*4+0]) * h[s4*4+0] + e * Bv.x;
                h[s4*4+1] = __expf(dtv * Av[s4*4+1]) * h[s4*4+1] + e * Bv.y;
                h[s4*4+2] = __expf(dtv * Av[s4*4+2]) * h[s4*4+2] + e * Bv.z;
                h[s4*4+3] = __expf(dtv * Av[s4*4+3]) * h[s4*4+3] + e * Bv.w;
                y += h[s4*4+0] * Cv.x + h[s4*4+1] * Cv.y
                   + h[s4*4+2] * Cv.z + h[s4*4+3] * Cv.w;
            }
            if (act) {
                float z = __bfloat162float(s_z[tt][tid]);
                y2[(rb + t0 + tt) * KI + d] =
                    __float2bfloat16((y + uv * Dv) * (z / (1.f + __expf(-z))));
            }
        }
    }
}

// -------- weight packing --------
__global__ void pack1_kernel(const float* __restrict__ ipw, bf16* __restrict__ win) {
    int i = blockIdx.x * 256 + threadIdx.x;
    int total = N_LAYERS * 1032 * 258;
    if (i >= total) return;
    int k = i % 258, nr = i / 258, n = nr % 1032, l = nr / 1032;
    win[((size_t)l * WIN_R + n) * KM + k] = __float2bfloat16(ipw[i]);
}
__global__ void pack2_kernel(const float* __restrict__ opw, const float* __restrict__ xpw,
                             bf16* __restrict__ wout, bf16* __restrict__ wxp) {
    int i = blockIdx.x * 256 + threadIdx.x;
    const int OUT_T = N_LAYERS * 258 * 516, XP_T = N_LAYERS * 49 * 516;
    if (i < OUT_T) {
        int k = i % 516, nr = i / 516, n = nr % 258, l = nr / 258;
        wout[((size_t)l * WOUT_R + n) * KI + k] = __float2bfloat16(opw[i]);
    } else if (i < OUT_T + XP_T) {
        int j = i - OUT_T;
        int k = j % 516, nr = j / 516, n = nr % 49, l = nr / 49;
        wxp[((size_t)l * WXP_R + n) * KI + k] = __float2bfloat16(xpw[j]);
    }
}

// -------- host --------
extern "C" void kernel_launch(void* const* d_in, const int* in_sizes, int n_in,
                              void* d_out, int out_size) {
    const float* fuse  = (const float*)d_in[0];
    const float* nwv   = (const float*)d_in[1];
    const float* ipw   = (const float*)d_in[2];
    const float* cwv   = (const float*)d_in[3];
    const float* cbv   = (const float*)d_in[4];
    const float* xpw   = (const float*)d_in[5];
    const float* dtwv  = (const float*)d_in[6];
    const float* dtbv  = (const float*)d_in[7];
    const float* Alv   = (const float*)d_in[8];
    const float* Dpv   = (const float*)d_in[9];
    const float* opw   = (const float*)d_in[10];
    const float* fw    = (const float*)d_in[11];
    float* out = (float*)d_out;

    float *p_x, *p_xdbl, *p_L, *p_H0, *p_sdt;
    bf16 *p_xn, *p_xz, *p_xc, *p_dt, *p_y2, *p_win, *p_wout, *p_wxp;
    cudaGetSymbolAddress((void**)&p_x, g_x);
    cudaGetSymbolAddress((void**)&p_xn, g_xn);
    cudaGetSymbolAddress((void**)&p_xz, g_xz);
    cudaGetSymbolAddress((void**)&p_xc, g_xc);
    cudaGetSymbolAddress((void**)&p_xdbl, g_xdbl);
    cudaGetSymbolAddress((void**)&p_dt, g_dt);
    cudaGetSymbolAddress((void**)&p_y2, g_y2);
    cudaGetSymbolAddress((void**)&p_win, g_win);
    cudaGetSymbolAddress((void**)&p_wout, g_wout);
    cudaGetSymbolAddress((void**)&p_wxp, g_wxp);
    cudaGetSymbolAddress((void**)&p_L, g_L);
    cudaGetSymbolAddress((void**)&p_H0, g_H0);
    cudaGetSymbolAddress((void**)&p_sdt, g_sdt);

    pack1_kernel<<<(N_LAYERS * 1032 * 258 + 255) / 256, 256>>>(ipw, p_win);
    {
        int tot = N_LAYERS * 258 * 516 + N_LAYERS * 49 * 516;
        pack2_kernel<<<(tot + 255) / 256, 256>>>(opw, xpw, p_wout, p_wxp);
    }
    cudaMemcpyAsync(p_x, fuse, (size_t)NTOK * D_MODEL * sizeof(float),
                    cudaMemcpyDeviceToDevice);

    for (int l = 0; l < N_LAYERS; ++l) {
        rmsnorm_kernel<<<NTOK / 8, 256>>>(p_x, nwv + (size_t)l * D_MODEL, p_xn, KM);
        gemm_bf16<128, 2><<<dim3(17, 64), 256>>>(p_xn, p_win + (size_t)l * WIN_R * KM,
                                                 p_xz, TWO_DI, KM, KM, TWO_DI);
        conv_silu_kernel<<<dim3(5, L_SEQ / CLT, B_SZ), 128>>>(
            p_xz, cwv + (size_t)l * D_INNER * 4, cbv + (size_t)l * D_INNER, p_xc);
        gemm_bf16<32, 0><<<dim3(1, 256), 256>>>(p_xc, p_wxp + (size_t)l * WXP_R * KI,
                                                p_xdbl, 49, KI, KI, XW);
        dt_kernel<<<NTOK / DT_TB, 256>>>(p_xdbl, dtwv + (size_t)l * D_INNER * DT_RANK,
                                         dtbv + (size_t)l * D_INNER, p_dt);
        scan1_kernel<<<dim3(5, NCHK, B_SZ), 128>>>(
            p_dt, p_xc, p_xdbl, Alv + (size_t)l * D_INNER * 16, p_L, p_sdt);
        scan2_kernel<<<(B_SZ * D_INNER * D_STATE + 127) / 128, 128>>>(
            p_L, p_sdt, Alv + (size_t)l * D_INNER * 16, p_H0);
        scan3_kernel<<<dim3(5, NCHK, B_SZ), 128>>>(
            p_dt, p_xc, p_xdbl, p_xz, Alv + (size_t)l * D_INNER * 16,
            Dpv + (size_t)l * D_INNER, p_H0, p_y2);
        gemm_bf16<128, 1><<<dim3(5, 64), 256>>>(p_y2, p_wout + (size_t)l * WOUT_R * KI,
                                                p_x, D_MODEL, KI, KI, D_MODEL);
    }
    final_kernel<<<NTOK / 8, 256>>>(fuse, p_x, fw, out);
    (void)in_sizes; (void)n_in; (void)out_size;
}

// round 8
// speedup vs baseline: 2.7404x; 1.0547x over previous
#include <cuda_runtime.h>
#include <cuda_bf16.h>
#include <math.h>
#include <stdint.h>

#define B_SZ 4
#define L_SEQ 2048
#define D_MODEL 258
#define N_LAYERS 4
#define D_STATE 16
#define D_INNER 516
#define DT_RANK 17
#define TWO_DI 1032
#define XW 56            // padded xdbl stride (49 real cols)
#define NTOK 8192
#define EPS 1e-5f
#define KM 288           // 258 padded to 32-chunks
#define KI 544           // 516 padded
#define WIN_R 1152       // 9 * 128
#define WOUT_R 384       // 3 * 128
#define WXP_R 64
#define NCHK 16          // scan chunks
#define SCT 128          // tokens per scan chunk
#define STL 32           // scan stage tile (tokens)

typedef __nv_bfloat16 bf16;

// -------- device scratch (zero-init; +pad for vectorized edge reads) --------
__device__ __align__(256) float g_x[NTOK * D_MODEL];
__device__ __align__(256) bf16  g_xn[NTOK * KM];
__device__ __align__(256) bf16  g_xz[NTOK * TWO_DI + 256];
__device__ __align__(256) bf16  g_xc[NTOK * KI + 256];
__device__ __align__(256) float g_xdbl[NTOK * XW];
__device__ __align__(256) bf16  g_y2[NTOK * KI];
__device__ __align__(256) bf16  g_win[N_LAYERS * WIN_R * KM];
__device__ __align__(256) bf16  g_wout[N_LAYERS * WOUT_R * KI];
__device__ __align__(256) bf16  g_wxp[N_LAYERS * WXP_R * KI];
__device__ __align__(256) float g_L[B_SZ * NCHK * D_INNER * D_STATE];
__device__ __align__(256) float g_H0[B_SZ * NCHK * D_INNER * D_STATE];
__device__ __align__(256) float g_sdt[B_SZ * NCHK * D_INNER];

// -------- helpers --------
__device__ __forceinline__ uint32_t smem_u32(const void* p) {
    uint32_t a;
    asm("{ .reg .u64 t; cvta.to.shared.u64 t, %1; cvt.u32.u64 %0, t; }" : "=r"(a) : "l"(p));
    return a;
}
__device__ __forceinline__ void cp_async16(uint32_t dst, const void* src) {
    asm volatile("cp.async.ca.shared.global [%0], [%1], 16;" :: "r"(dst), "l"(src));
}
#define CP_COMMIT() asm volatile("cp.async.commit_group;" ::: "memory")
#define CP_WAIT(n) asm volatile("cp.async.wait_group %0;" :: "n"(n) : "memory")

__device__ __forceinline__ void mma_bf16(float* d, const uint32_t* a, const uint32_t* b) {
    asm volatile(
        "mma.sync.aligned.m16n8k16.row.col.f32.bf16.bf16.f32 "
        "{%0,%1,%2,%3},{%4,%5,%6,%7},{%8,%9},{%0,%1,%2,%3};"
        : "+f"(d[0]), "+f"(d[1]), "+f"(d[2]), "+f"(d[3])
        : "r"(a[0]), "r"(a[1]), "r"(a[2]), "r"(a[3]), "r"(b[0]), "r"(b[1]));
}
__device__ __forceinline__ void ldsm_x4(uint32_t* r, uint32_t addr) {
    asm volatile("ldmatrix.sync.aligned.m8n8.x4.shared.b16 {%0,%1,%2,%3}, [%4];"
        : "=r"(r[0]), "=r"(r[1]), "=r"(r[2]), "=r"(r[3]) : "r"(addr));
}
__device__ __forceinline__ void ldsm_x2(uint32_t* r, uint32_t addr) {
    asm volatile("ldmatrix.sync.aligned.m8n8.x2.shared.b16 {%0,%1}, [%2];"
        : "=r"(r[0]), "=r"(r[1]) : "r"(addr));
}

// -------- bf16 mma GEMM: C[8192,N] = A[8192,K]bf16 @ W[N,K]bf16^T --------
// CTA BM x BN; 8 warps; K chunk 32; cp.async multi-stage; ldmatrix fragments.
// OUTMODE: 0 = fp32 store, 1 = fp32 add-store, 2 = bf16 store.
#define AW 20            // smem row stride in words (40 bf16) — LDSM conflict-free
template <int BM, int BN, int OUTMODE>
__global__ __launch_bounds__(256) void gemm_bf16(
    const bf16* __restrict__ A, const bf16* __restrict__ W,
    void* __restrict__ Cv, int N_store, int K, int lda, int ldc) {
    constexpr int MW = BM / 32;
    constexpr int NW = 8 / MW;
    constexpr int WN = BN / NW;
    constexpr int NT = WN / 8;
    constexpr int ASTG = BM * AW, BSTG = BN * AW, STG = ASTG + BSTG;
    constexpr int NSTAGE = (3 * STG * 4 <= 46000) ? 3 : 2;
    __shared__ __align__(16) uint32_t sm[NSTAGE * STG];
    const int tid = threadIdx.x, wid = tid >> 5, lane = tid & 31;
    const int warpM = wid % MW, warpN = wid / MW;
    const int quad = lane >> 2, qk = lane & 3;
    const int bm = blockIdx.y * BM, bn = blockIdx.x * BN;
    float acc[2][NT][4];
    #pragma unroll
    for (int i = 0; i < 2; ++i)
        #pragma unroll
        for (int j = 0; j < NT; ++j)
            #pragma unroll
            for (int k = 0; k < 4; ++k) acc[i][j][k] = 0.f;

    const bf16* Ab = A + (size_t)bm * lda;
    const bf16* Wb = W + (size_t)bn * K;
    const int nch = K >> 5;
    const uint32_t sm_u = smem_u32(sm);
    const int l8 = lane & 7, jm = lane >> 3;

    const uint32_t aLM = sm_u +
        (uint32_t)(((warpM * 32 + ((jm & 1) << 3) + l8) * AW + ((jm >> 1) << 2)) * 4);
    const uint32_t bLM4 = sm_u + ASTG * 4 +
        (uint32_t)(((warpN * WN + ((jm >> 1) << 3) + l8) * AW + ((jm & 1) << 2)) * 4);
    const uint32_t bLM2 = sm_u + ASTG * 4 +
        (uint32_t)(((warpN * WN + l8) * AW + (((lane >> 3) & 1) << 2)) * 4);

    auto load_chunk = [&](int c, int st) {
        const bf16* Ac = Ab + c * 32;
        #pragma unroll
        for (int fi = tid; fi < BM * 4; fi += 256) {
            int r = fi >> 2, sg = fi & 3;
            cp_async16(sm_u + (uint32_t)(st * STG + r * AW + sg * 4) * 4,
                       Ac + (size_t)r * lda + sg * 8);
        }
        const bf16* Wc = Wb + c * 32;
        #pragma unroll
        for (int fi = tid; fi < BN * 4; fi += 256) {
            int r = fi >> 2, sg = fi & 3;
            cp_async16(sm_u + (uint32_t)(st * STG + ASTG + r * AW + sg * 4) * 4,
                       Wc + (size_t)r * K + sg * 8);
        }
    };

    load_chunk(0, 0); CP_COMMIT();
    if (NSTAGE == 3) { if (nch > 1) load_chunk(1, 1); CP_COMMIT(); }

    for (int c = 0; c < nch; ++c) {
        if (NSTAGE == 3) { CP_WAIT(1); } else { CP_WAIT(0); }
        __syncthreads();
        int nx = c + NSTAGE - 1;
        if (nx < nch) load_chunk(nx, nx % NSTAGE);
        CP_COMMIT();
        const uint32_t stOff = (uint32_t)((c % NSTAGE) * STG * 4);
        #pragma unroll
        for (int ks = 0; ks < 2; ++ks) {
            uint32_t a[2][4], b[NT][2];
            #pragma unroll
            for (int mt = 0; mt < 2; ++mt)
                ldsm_x4(a[mt], aLM + stOff + (uint32_t)(mt * 16 * AW * 4 + ks * 32));
            if (NT == 1) {
                ldsm_x2(b[0], bLM2 + stOff + (uint32_t)(ks * 32));
            } else {
                #pragma unroll
                for (int p = 0; p < NT / 2; ++p) {
                    uint32_t t4[4];
                    ldsm_x4(t4, bLM4 + stOff + (uint32_t)(p * 16 * AW * 4 + ks * 32));
                    b[2*p][0] = t4[0]; b[2*p][1] = t4[1];
                    b[2*p+1][0] = t4[2]; b[2*p+1][1] = t4[3];
                }
            }
            #pragma unroll
            for (int mt = 0; mt < 2; ++mt)
                #pragma unroll
                for (int nt = 0; nt < NT; ++nt)
                    mma_bf16(acc[mt][nt], a[mt], b[nt]);
        }
        __syncthreads();
    }

    #pragma unroll
    for (int mt = 0; mt < 2; ++mt) {
        int r0 = bm + warpM * 32 + mt * 16 + quad;
        #pragma unroll
        for (int nt = 0; nt < NT; ++nt) {
            int gc = bn + warpN * WN + nt * 8 + qk * 2;
            #pragma unroll
            for (int half = 0; half < 2; ++half) {
                int row = r0 + half * 8;
                float v0 = acc[mt][nt][half * 2 + 0];
                float v1 = acc[mt][nt][half * 2 + 1];
                size_t gi = (size_t)row * ldc + gc;
                if (OUTMODE == 2) {
                    bf16* C = (bf16*)Cv;
                    if (gc < N_store) C[gi] = __float2bfloat16(v0);
                    if (gc + 1 < N_store) C[gi + 1] = __float2bfloat16(v1);
                } else {
                    float* C = (float*)Cv;
                    if (gc < N_store) {
                        if (OUTMODE == 1) v0 += C[gi];
                        C[gi] = v0;
                    }
                    if (gc + 1 < N_store) {
                        if (OUTMODE == 1) v1 += C[gi + 1];
                        C[gi + 1] = v1;
                    }
                }
            }
        }
    }
}

// -------- rmsnorm: warp per token, bf16 out --------
__global__ void rmsnorm_kernel(const float* __restrict__ x, const float* __restrict__ w,
                               bf16* __restrict__ o, int ldo) {
    int tok = (blockIdx.x * blockDim.x + threadIdx.x) >> 5;
    int lane = threadIdx.x & 31;
    if (tok >= NTOK) return;
    const float* xr = x + (size_t)tok * D_MODEL;
    float ss = 0.f;
    for (int i = lane; i < D_MODEL; i += 32) { float v = xr[i]; ss += v * v; }
    #pragma unroll
    for (int off = 16; off; off >>= 1) ss += __shfl_xor_sync(~0u, ss, off);
    float inv = rsqrtf(ss * (1.f / D_MODEL) + EPS);
    for (int i = lane; i < D_MODEL; i += 32)
        o[(size_t)tok * ldo + i] = __float2bfloat16(xr[i] * inv * w[i]);
}

__global__ void final_kernel(const float* __restrict__ f, const float* __restrict__ x,
                             const float* __restrict__ w, float* __restrict__ o) {
    int tok = (blockIdx.x * blockDim.x + threadIdx.x) >> 5;
    int lane = threadIdx.x & 31;
    if (tok >= NTOK) return;
    const float* xr = x + (size_t)tok * D_MODEL;
    float ss = 0.f;
    for (int i = lane; i < D_MODEL; i += 32) { float v = xr[i]; ss += v * v; }
    #pragma unroll
    for (int off = 16; off; off >>= 1) ss += __shfl_xor_sync(~0u, ss, off);
    float inv = rsqrtf(ss * (1.f / D_MODEL) + EPS);
    for (int i = lane; i < D_MODEL; i += 32)
        o[(size_t)tok * D_MODEL + i] = f[(size_t)tok * D_MODEL + i] + xr[i] * inv * w[i];
}

// -------- conv(k=4, causal) + silu: register window over 64-token tiles --------
#define CLT 64
__global__ void conv_silu_kernel(const bf16* __restrict__ xz, const float* __restrict__ cw,
                                 const float* __restrict__ cb, bf16* __restrict__ xc) {
    int d = blockIdx.x * 128 + threadIdx.x;
    if (d >= D_INNER) return;
    int l0 = blockIdx.y * CLT, b = blockIdx.z;
    float w0 = cw[d * 4 + 0], w1 = cw[d * 4 + 1], w2 = cw[d * 4 + 2], w3 = cw[d * 4 + 3];
    float bb = cb[d];
    size_t row = (size_t)b * L_SEQ + l0;
    const bf16* src = xz + row * TWO_DI + d;
    bf16* dst = xc + row * KI + d;
    float x0, x1, x2;
    if (l0 == 0) { x0 = x1 = x2 = 0.f; }
    else {
        x0 = __bfloat162float(src[-3 * TWO_DI]);
        x1 = __bfloat162float(src[-2 * TWO_DI]);
        x2 = __bfloat162float(src[-1 * TWO_DI]);
    }
    #pragma unroll 4
    for (int i = 0; i < CLT; ++i) {
        float x3 = __bfloat162float(src[(size_t)i * TWO_DI]);
        float acc = bb + w0 * x0 + w1 * x1 + w2 * x2 + w3 * x3;
        dst[(size_t)i * KI] = __float2bfloat16(acc / (1.f + __expf(-acc)));
        x0 = x1; x1 = x2; x2 = x3;
    }
}

// -------- chunked selective scan; dt computed inline (softplus fused) --------
__device__ __forceinline__ float softplus_f(float a) {
    return (a > 15.f) ? a : log1pf(__expf(a));
}

// S1: per-chunk local state (h from 0) + sum(dt)
__global__ __launch_bounds__(128) void scan1_kernel(
    const bf16* __restrict__ u, const float* __restrict__ xdbl,
    const float* __restrict__ A_log, const float* __restrict__ dtw,
    const float* __restrict__ dtb, float* __restrict__ Lc, float* __restrict__ sdtc) {
    __shared__ float sDL[SCT][18];
    __shared__ float sB[SCT][16];
    __shared__ bf16 s_u[STL][128];
    int b = blockIdx.z, c = blockIdx.y, d0 = blockIdx.x * 128;
    int tid = threadIdx.x;
    int d = d0 + tid;
    bool act = d < D_INNER;
    int dc = act ? d : (D_INNER - 1);
    size_t rb = (size_t)b * L_SEQ + (size_t)c * SCT;
    float Av[16];
    #pragma unroll
    for (int s = 0; s < 16; s += 4) {
        float4 al = *(const float4*)(A_log + (size_t)dc * 16 + s);
        Av[s + 0] = -__expf(al.x); Av[s + 1] = -__expf(al.y);
        Av[s + 2] = -__expf(al.z); Av[s + 3] = -__expf(al.w);
    }
    float wv[DT_RANK];
    #pragma unroll
    for (int r = 0; r < DT_RANK; ++r) wv[r] = dtw[(size_t)dc * DT_RANK + r];
    float bias = dtb[dc];
    for (int i = tid; i < SCT * 16; i += 128) {
        int t = i >> 4, s = i & 15;
        sB[t][s] = xdbl[(rb + t) * XW + DT_RANK + s];
    }
    for (int i = tid; i < SCT * DT_RANK; i += 128) {
        int t = i / DT_RANK, r = i - t * DT_RANK;
        sDL[t][r] = xdbl[(rb + t) * XW + r];
    }
    float h[16];
    #pragma unroll
    for (int s = 0; s < 16; ++s) h[s] = 0.f;
    float sd = 0.f;
    for (int t0 = 0; t0 < SCT; t0 += STL) {
        __syncthreads();
        for (int q = tid; q < STL * 64; q += 128) {
            int tt = q >> 6, dp = (q & 63) * 2;
            *(uint32_t*)&s_u[tt][dp] = *(const uint32_t*)(u + (rb + t0 + tt) * KI + d0 + dp);
        }
        __syncthreads();
        for (int tt = 0; tt < STL; ++tt) {
            float dta = bias;
            const float* dl = sDL[t0 + tt];
            #pragma unroll
            for (int r = 0; r < DT_RANK; ++r) dta = fmaf(dl[r], wv[r], dta);
            float dtv = softplus_f(dta);
            float uv = __bfloat162float(s_u[tt][tid]);
            float e = dtv * uv;
            sd += dtv;
            const float4* pB = (const float4*)sB[t0 + tt];
            #pragma unroll
            for (int s4 = 0; s4 < 4; ++s4) {
                float4 Bv = pB[s4];
                h[s4*4+0] = __expf(dtv * Av[s4*4+0]) * h[s4*4+0] + e * Bv.x;
                h[s4*4+1] = __expf(dtv * Av[s4*4+1]) * h[s4*4+1] + e * Bv.y;
                h[s4*4+2] = __expf(dtv * Av[s4*4+2]) * h[s4*4+2] + e * Bv.z;
                h[s4*4+3] = __expf(dtv * Av[s4*4+3]) * h[s4*4+3] + e * Bv.w;
            }
        }
    }
    if (act) {
        size_t o = ((size_t)b * NCHK + c) * D_INNER + d;
        float4* pL = (float4*)(Lc + o * 16);
        #pragma unroll
        for (int s4 = 0; s4 < 4; ++s4)
            pL[s4] = make_float4(h[s4*4+0], h[s4*4+1], h[s4*4+2], h[s4*4+3]);
        sdtc[o] = sd;
    }
}

// S2: stitch chunk summaries -> initial state per chunk
__global__ void scan2_kernel(const float* __restrict__ Lc, const float* __restrict__ sdtc,
                             const float* __restrict__ A_log, float* __restrict__ H0) {
    int idx = blockIdx.x * 128 + threadIdx.x;
    if (idx >= B_SZ * D_INNER * D_STATE) return;
    int s = idx & 15, rest = idx >> 4;
    int d = rest % D_INNER, b = rest / D_INNER;
    float Av = -__expf(A_log[(size_t)d * 16 + s]);
    float h = 0.f;
    #pragma unroll
    for (int c = 0; c < NCHK; ++c) {
        size_t o = (((size_t)b * NCHK + c) * D_INNER + d);
        H0[o * 16 + s] = h;
        h = __expf(Av * sdtc[o]) * h + Lc[o * 16 + s];
    }
}

// S3: replay with initial state, y + fused gate; bf16 out
__global__ __launch_bounds__(128) void scan3_kernel(
    const bf16* __restrict__ u, const float* __restrict__ xdbl,
    const bf16* __restrict__ xz, const float* __restrict__ A_log,
    const float* __restrict__ dtw, const float* __restrict__ dtb,
    const float* __restrict__ Dp, const float* __restrict__ H0,
    bf16* __restrict__ y2) {
    __shared__ float sDL[SCT][18];
    __shared__ float sB[SCT][16];
    __shared__ float sC[SCT][16];
    __shared__ bf16 s_u[STL][128];
    __shared__ bf16 s_z[STL][128];
    int b = blockIdx.z, c = blockIdx.y, d0 = blockIdx.x * 128;
    int tid = threadIdx.x;
    int d = d0 + tid;
    bool act = d < D_INNER;
    int dc = act ? d : (D_INNER - 1);
    size_t rb = (size_t)b * L_SEQ + (size_t)c * SCT;
    float Av[16];
    #pragma unroll
    for (int s = 0; s < 16; s += 4) {
        float4 al = *(const float4*)(A_log + (size_t)dc * 16 + s);
        Av[s + 0] = -__expf(al.x); Av[s + 1] = -__expf(al.y);
        Av[s + 2] = -__expf(al.z); Av[s + 3] = -__expf(al.w);
    }
    float wv[DT_RANK];
    #pragma unroll
    for (int r = 0; r < DT_RANK; ++r) wv[r] = dtw[(size_t)dc * DT_RANK + r];
    float bias = dtb[dc];
    float Dv = Dp[dc];
    for (int i = tid; i < SCT * 16; i += 128) {
        int t = i >> 4, s = i & 15;
        const float* g = xdbl + (rb + t) * XW + DT_RANK;
        sB[t][s] = g[s];
        sC[t][s] = g[16 + s];
    }
    for (int i = tid; i < SCT * DT_RANK; i += 128) {
        int t = i / DT_RANK, r = i - t * DT_RANK;
        sDL[t][r] = xdbl[(rb + t) * XW + r];
    }
    float h[16];
    {
        size_t o = ((size_t)b * NCHK + c) * D_INNER + dc;
        const float4* pH = (const float4*)(H0 + o * 16);
        #pragma unroll
        for (int s4 = 0; s4 < 4; ++s4) {
            float4 hv = pH[s4];
            h[s4*4+0] = hv.x; h[s4*4+1] = hv.y; h[s4*4+2] = hv.z; h[s4*4+3] = hv.w;
        }
    }
    for (int t0 = 0; t0 < SCT; t0 += STL) {
        __syncthreads();
        for (int q = tid; q < STL * 64; q += 128) {
            int tt = q >> 6, dp = (q & 63) * 2;
            *(uint32_t*)&s_u[tt][dp] = *(const uint32_t*)(u  + (rb + t0 + tt) * KI + d0 + dp);
            *(uint32_t*)&s_z[tt][dp] = *(const uint32_t*)(xz + (rb + t0 + tt) * TWO_DI + D_INNER + d0 + dp);
        }
        __syncthreads();
        for (int tt = 0; tt < STL; ++tt) {
            float dta = bias;
            const float* dl = sDL[t0 + tt];
            #pragma unroll
            for (int r = 0; r < DT_RANK; ++r) dta = fmaf(dl[r], wv[r], dta);
            float dtv = softplus_f(dta);
            float uv = __bfloat162float(s_u[tt][tid]);
            float e = dtv * uv;
            const float4* pB = (const float4*)sB[t0 + tt];
            const float4* pC = (const float4*)sC[t0 + tt];
            float y = 0.f;
            #pragma unroll
            for (int s4 = 0; s4 < 4; ++s4) {
                float4 Bv = pB[s4];
                float4 Cv = pC[s4];
                h[s4*4+0] = __expf(dtv * Av[s4*4+0]) * h[s4*4+0] + e * Bv.x;
                h[s4*4+1] = __expf(dtv * Av[s4*4+1]) * h[s4*4+1] + e * Bv.y;
                h[s4*4+2] = __expf(dtv * Av[s4*4+2]) * h[s4*4+2] + e * Bv.z;
                h[s4*4+3] = __expf(dtv * Av[s4*4+3]) * h[s4*4+3] + e * Bv.w;
                y += h[s4*4+0] * Cv.x + h[s4*4+1] * Cv.y
                   + h[s4*4+2] * Cv.z + h[s4*4+3] * Cv.w;
            }
            if (act) {
                float z = __bfloat162float(s_z[tt][tid]);
                y2[(rb + t0 + tt) * KI + d] =
                    __float2bfloat16((y + uv * Dv) * (z / (1.f + __expf(-z))));
            }
        }
    }
}

// -------- weight packing --------
__global__ void pack1_kernel(const float* __restrict__ ipw, bf16* __restrict__ win) {
    int i = blockIdx.x * 256 + threadIdx.x;
    int total = N_LAYERS * 1032 * 258;
    if (i >= total) return;
    int k = i % 258, nr = i / 258, n = nr % 1032, l = nr / 1032;
    win[((size_t)l * WIN_R + n) * KM + k] = __float2bfloat16(ipw[i]);
}
__global__ void pack2_kernel(const float* __restrict__ opw, const float* __restrict__ xpw,
                             bf16* __restrict__ wout, bf16* __restrict__ wxp) {
    int i = blockIdx.x * 256 + threadIdx.x;
    const int OUT_T = N_LAYERS * 258 * 516, XP_T = N_LAYERS * 49 * 516;
    if (i < OUT_T) {
        int k = i % 516, nr = i / 516, n = nr % 258, l = nr / 258;
        wout[((size_t)l * WOUT_R + n) * KI + k] = __float2bfloat16(opw[i]);
    } else if (i < OUT_T + XP_T) {
        int j = i - OUT_T;
        int k = j % 516, nr = j / 516, n = nr % 49, l = nr / 49;
        wxp[((size_t)l * WXP_R + n) * KI + k] = __float2bfloat16(xpw[j]);
    }
}

// -------- host --------
extern "C" void kernel_launch(void* const* d_in, const int* in_sizes, int n_in,
                              void* d_out, int out_size) {
    const float* fuse  = (const float*)d_in[0];
    const float* nwv   = (const float*)d_in[1];
    const float* ipw   = (const float*)d_in[2];
    const float* cwv   = (const float*)d_in[3];
    const float* cbv   = (const float*)d_in[4];
    const float* xpw   = (const float*)d_in[5];
    const float* dtwv  = (const float*)d_in[6];
    const float* dtbv  = (const float*)d_in[7];
    const float* Alv   = (const float*)d_in[8];
    const float* Dpv   = (const float*)d_in[9];
    const float* opw   = (const float*)d_in[10];
    const float* fw    = (const float*)d_in[11];
    float* out = (float*)d_out;

    float *p_x, *p_xdbl, *p_L, *p_H0, *p_sdt;
    bf16 *p_xn, *p_xz, *p_xc, *p_y2, *p_win, *p_wout, *p_wxp;
    cudaGetSymbolAddress((void**)&p_x, g_x);
    cudaGetSymbolAddress((void**)&p_xn, g_xn);
    cudaGetSymbolAddress((void**)&p_xz, g_xz);
    cudaGetSymbolAddress((void**)&p_xc, g_xc);
    cudaGetSymbolAddress((void**)&p_xdbl, g_xdbl);
    cudaGetSymbolAddress((void**)&p_y2, g_y2);
    cudaGetSymbolAddress((void**)&p_win, g_win);
    cudaGetSymbolAddress((void**)&p_wout, g_wout);
    cudaGetSymbolAddress((void**)&p_wxp, g_wxp);
    cudaGetSymbolAddress((void**)&p_L, g_L);
    cudaGetSymbolAddress((void**)&p_H0, g_H0);
    cudaGetSymbolAddress((void**)&p_sdt, g_sdt);

    pack1_kernel<<<(N_LAYERS * 1032 * 258 + 255) / 256, 256>>>(ipw, p_win);
    {
        int tot = N_LAYERS * 258 * 516 + N_LAYERS * 49 * 516;
        pack2_kernel<<<(tot + 255) / 256, 256>>>(opw, xpw, p_wout, p_wxp);
    }
    cudaMemcpyAsync(p_x, fuse, (size_t)NTOK * D_MODEL * sizeof(float),
                    cudaMemcpyDeviceToDevice);

    for (int l = 0; l < N_LAYERS; ++l) {
        const float* Al = Alv + (size_t)l * D_INNER * 16;
        const float* dtw = dtwv + (size_t)l * D_INNER * DT_RANK;
        const float* dtb = dtbv + (size_t)l * D_INNER;
        rmsnorm_kernel<<<NTOK / 8, 256>>>(p_x, nwv + (size_t)l * D_MODEL, p_xn, KM);
        gemm_bf16<128, 128, 2><<<dim3(9, 64), 256>>>(
            p_xn, p_win + (size_t)l * WIN_R * KM, p_xz, TWO_DI, KM, KM, TWO_DI);
        conv_silu_kernel<<<dim3(5, L_SEQ / CLT, B_SZ), 128>>>(
            p_xz, cwv + (size_t)l * D_INNER * 4, cbv + (size_t)l * D_INNER, p_xc);
        gemm_bf16<32, 64, 0><<<dim3(1, 256), 256>>>(
            p_xc, p_wxp + (size_t)l * WXP_R * KI, p_xdbl, 49, KI, KI, XW);
        scan1_kernel<<<dim3(5, NCHK, B_SZ), 128>>>(
            p_xc, p_xdbl, Al, dtw, dtb, p_L, p_sdt);
        scan2_kernel<<<(B_SZ * D_INNER * D_STATE + 127) / 128, 128>>>(
            p_L, p_sdt, Al, p_H0);
        scan3_kernel<<<dim3(5, NCHK, B_SZ), 128>>>(
            p_xc, p_xdbl, p_xz, Al, dtw, dtb, Dpv + (size_t)l * D_INNER, p_H0, p_y2);
        gemm_bf16<64, 128, 1><<<dim3(3, 128), 256>>>(
            p_y2, p_wout + (size_t)l * WOUT_R * KI, p_x, D_MODEL, KI, KI, D_MODEL);
    }
    final_kernel<<<NTOK / 8, 256>>>(fuse, p_x, fw, out);
    (void)in_sizes; (void)n_in; (void)out_size;
}

// round 9
// speedup vs baseline: 2.9046x; 1.0599x over previous
#include <cuda_runtime.h>
#include <cuda_bf16.h>
#include <math.h>
#include <stdint.h>

#define B_SZ 4
#define L_SEQ 2048
#define D_MODEL 258
#define N_LAYERS 4
#define D_STATE 16
#define D_INNER 516
#define DT_RANK 17
#define TWO_DI 1032
#define XW 56            // padded xdbl stride (49 real cols)
#define NTOK 8192
#define EPS 1e-5f
#define KM 288           // 258 padded to 32-chunks
#define KI 544           // 516 padded
#define WIN_R 1152       // 9 * 128
#define WOUT_R 384       // 3 * 128
#define WXP_R 64
#define NCHK 16          // scan chunks
#define SCT 128          // tokens per scan chunk
#define STL 32           // scan stage tile (tokens)

typedef __nv_bfloat16 bf16;

// -------- device scratch (zero-init; +pad for vectorized edge reads) --------
__device__ __align__(256) float g_x[NTOK * D_MODEL];
__device__ __align__(256) bf16  g_xn[NTOK * KM];
__device__ __align__(256) bf16  g_xz[NTOK * TWO_DI + 256];
__device__ __align__(256) bf16  g_xc[NTOK * KI + 256];
__device__ __align__(256) float g_xdbl[NTOK * XW];
__device__ __align__(256) bf16  g_y2[NTOK * KI];
__device__ __align__(256) bf16  g_win[N_LAYERS * WIN_R * KM];
__device__ __align__(256) bf16  g_wout[N_LAYERS * WOUT_R * KI];
__device__ __align__(256) bf16  g_wxp[N_LAYERS * WXP_R * KI];
__device__ __align__(256) float g_L[B_SZ * NCHK * D_INNER * D_STATE];
__device__ __align__(256) float g_H0[B_SZ * NCHK * D_INNER * D_STATE];
__device__ __align__(256) float g_sdt[B_SZ * NCHK * D_INNER];

// -------- helpers --------
__device__ __forceinline__ uint32_t smem_u32(const void* p) {
    uint32_t a;
    asm("{ .reg .u64 t; cvta.to.shared.u64 t, %1; cvt.u32.u64 %0, t; }" : "=r"(a) : "l"(p));
    return a;
}
__device__ __forceinline__ void cp_async16(uint32_t dst, const void* src) {
    asm volatile("cp.async.cg.shared.global [%0], [%1], 16;" :: "r"(dst), "l"(src));
}
#define CP_COMMIT() asm volatile("cp.async.commit_group;" ::: "memory")

__device__ __forceinline__ void mma_bf16(float* d, const uint32_t* a, const uint32_t* b) {
    asm volatile(
        "mma.sync.aligned.m16n8k16.row.col.f32.bf16.bf16.f32 "
        "{%0,%1,%2,%3},{%4,%5,%6,%7},{%8,%9},{%0,%1,%2,%3};"
        : "+f"(d[0]), "+f"(d[1]), "+f"(d[2]), "+f"(d[3])
        : "r"(a[0]), "r"(a[1]), "r"(a[2]), "r"(a[3]), "r"(b[0]), "r"(b[1]));
}
__device__ __forceinline__ void ldsm_x4(uint32_t* r, uint32_t addr) {
    asm volatile("ldmatrix.sync.aligned.m8n8.x4.shared.b16 {%0,%1,%2,%3}, [%4];"
        : "=r"(r[0]), "=r"(r[1]), "=r"(r[2]), "=r"(r[3]) : "r"(addr));
}
__device__ __forceinline__ void ldsm_x2(uint32_t* r, uint32_t addr) {
    asm volatile("ldmatrix.sync.aligned.m8n8.x2.shared.b16 {%0,%1}, [%2];"
        : "=r"(r[0]), "=r"(r[1]) : "r"(addr));
}

// -------- bf16 mma GEMM: C[8192,N] = A[8192,K]bf16 @ W[N,K]bf16^T --------
// CTA BM x BN; 8 warps; K chunk 32; NSTAGE-deep cp.async; 1 barrier/chunk.
// OUTMODE: 0 = fp32 store, 1 = fp32 add-store, 2 = bf16 store.
#define AW 20            // smem row stride in words (40 bf16) — LDSM conflict-free
template <int BM, int BN, int OUTMODE, int NSTAGE>
__global__ __launch_bounds__(256) void gemm_bf16(
    const bf16* __restrict__ A, const bf16* __restrict__ W,
    void* __restrict__ Cv, int N_store, int K, int lda, int ldc) {
    constexpr int MW = BM / 32;
    constexpr int NW = 8 / MW;
    constexpr int WN = BN / NW;
    constexpr int NT = WN / 8;
    constexpr int ASTG = BM * AW, BSTG = BN * AW, STG = ASTG + BSTG;
    extern __shared__ uint32_t sm[];
    const int tid = threadIdx.x, wid = tid >> 5, lane = tid & 31;
    const int warpM = wid % MW, warpN = wid / MW;
    const int quad = lane >> 2, qk = lane & 3;
    const int bm = blockIdx.y * BM, bn = blockIdx.x * BN;
    float acc[2][NT][4];
    #pragma unroll
    for (int i = 0; i < 2; ++i)
        #pragma unroll
        for (int j = 0; j < NT; ++j)
            #pragma unroll
            for (int k = 0; k < 4; ++k) acc[i][j][k] = 0.f;

    const bf16* Ab = A + (size_t)bm * lda;
    const bf16* Wb = W + (size_t)bn * K;
    const int nch = K >> 5;
    const uint32_t sm_u = smem_u32(sm);
    const int l8 = lane & 7, jm = lane >> 3;

    const uint32_t aLM = sm_u +
        (uint32_t)(((warpM * 32 + ((jm & 1) << 3) + l8) * AW + ((jm >> 1) << 2)) * 4);
    const uint32_t bLM4 = sm_u + ASTG * 4 +
        (uint32_t)(((warpN * WN + ((jm >> 1) << 3) + l8) * AW + ((jm & 1) << 2)) * 4);
    const uint32_t bLM2 = sm_u + ASTG * 4 +
        (uint32_t)(((warpN * WN + l8) * AW + (((lane >> 3) & 1) << 2)) * 4);

    auto load_chunk = [&](int c, int st) {
        const bf16* Ac = Ab + c * 32;
        #pragma unroll
        for (int fi = tid; fi < BM * 4; fi += 256) {
            int r = fi >> 2, sg = fi & 3;
            cp_async16(sm_u + (uint32_t)(st * STG + r * AW + sg * 4) * 4,
                       Ac + (size_t)r * lda + sg * 8);
        }
        const bf16* Wc = Wb + c * 32;
        #pragma unroll
        for (int fi = tid; fi < BN * 4; fi += 256) {
            int r = fi >> 2, sg = fi & 3;
            cp_async16(sm_u + (uint32_t)(st * STG + ASTG + r * AW + sg * 4) * 4,
                       Wc + (size_t)r * K + sg * 8);
        }
    };

    #pragma unroll
    for (int p = 0; p < NSTAGE - 1; ++p) {
        if (p < nch) load_chunk(p, p);
        CP_COMMIT();
    }

    for (int c = 0; c < nch; ++c) {
        asm volatile("cp.async.wait_group %0;" :: "n"(NSTAGE - 2) : "memory");
        __syncthreads();
        int nx = c + NSTAGE - 1;
        if (nx < nch) load_chunk(nx, nx % NSTAGE);
        CP_COMMIT();
        const uint32_t stOff = (uint32_t)((c % NSTAGE) * STG * 4);
        #pragma unroll
        for (int ks = 0; ks < 2; ++ks) {
            uint32_t a[2][4], b[NT][2];
            #pragma unroll
            for (int mt = 0; mt < 2; ++mt)
                ldsm_x4(a[mt], aLM + stOff + (uint32_t)(mt * 16 * AW * 4 + ks * 32));
            if (NT == 1) {
                ldsm_x2(b[0], bLM2 + stOff + (uint32_t)(ks * 32));
            } else {
                #pragma unroll
                for (int p = 0; p < NT / 2; ++p) {
                    uint32_t t4[4];
                    ldsm_x4(t4, bLM4 + stOff + (uint32_t)(p * 16 * AW * 4 + ks * 32));
                    b[2*p][0] = t4[0]; b[2*p][1] = t4[1];
                    b[2*p+1][0] = t4[2]; b[2*p+1][1] = t4[3];
                }
            }
            #pragma unroll
            for (int mt = 0; mt < 2; ++mt)
                #pragma unroll
                for (int nt = 0; nt < NT; ++nt)
                    mma_bf16(acc[mt][nt], a[mt], b[nt]);
        }
    }
    __syncthreads();

    #pragma unroll
    for (int mt = 0; mt < 2; ++mt) {
        int r0 = bm + warpM * 32 + mt * 16 + quad;
        #pragma unroll
        for (int nt = 0; nt < NT; ++nt) {
            int gc = bn + warpN * WN + nt * 8 + qk * 2;
            #pragma unroll
            for (int half = 0; half < 2; ++half) {
                int row = r0 + half * 8;
                float v0 = acc[mt][nt][half * 2 + 0];
                float v1 = acc[mt][nt][half * 2 + 1];
                size_t gi = (size_t)row * ldc + gc;
                if (OUTMODE == 2) {
                    bf16* C = (bf16*)Cv;
                    if (gc < N_store) C[gi] = __float2bfloat16(v0);
                    if (gc + 1 < N_store) C[gi + 1] = __float2bfloat16(v1);
                } else {
                    float* C = (float*)Cv;
                    if (gc < N_store) {
                        if (OUTMODE == 1) v0 += C[gi];
                        C[gi] = v0;
                    }
                    if (gc + 1 < N_store) {
                        if (OUTMODE == 1) v1 += C[gi + 1];
                        C[gi + 1] = v1;
                    }
                }
            }
        }
    }
}

// -------- rmsnorm: warp per token, bf16 out --------
__global__ void rmsnorm_kernel(const float* __restrict__ x, const float* __restrict__ w,
                               bf16* __restrict__ o, int ldo) {
    int tok = (blockIdx.x * blockDim.x + threadIdx.x) >> 5;
    int lane = threadIdx.x & 31;
    if (tok >= NTOK) return;
    const float* xr = x + (size_t)tok * D_MODEL;
    float ss = 0.f;
    for (int i = lane; i < D_MODEL; i += 32) { float v = xr[i]; ss += v * v; }
    #pragma unroll
    for (int off = 16; off; off >>= 1) ss += __shfl_xor_sync(~0u, ss, off);
    float inv = rsqrtf(ss * (1.f / D_MODEL) + EPS);
    for (int i = lane; i < D_MODEL; i += 32)
        o[(size_t)tok * ldo + i] = __float2bfloat16(xr[i] * inv * w[i]);
}

__global__ void final_kernel(const float* __restrict__ f, const float* __restrict__ x,
                             const float* __restrict__ w, float* __restrict__ o) {
    int tok = (blockIdx.x * blockDim.x + threadIdx.x) >> 5;
    int lane = threadIdx.x & 31;
    if (tok >= NTOK) return;
    const float* xr = x + (size_t)tok * D_MODEL;
    float ss = 0.f;
    for (int i = lane; i < D_MODEL; i += 32) { float v = xr[i]; ss += v * v; }
    #pragma unroll
    for (int off = 16; off; off >>= 1) ss += __shfl_xor_sync(~0u, ss, off);
    float inv = rsqrtf(ss * (1.f / D_MODEL) + EPS);
    for (int i = lane; i < D_MODEL; i += 32)
        o[(size_t)tok * D_MODEL + i] = f[(size_t)tok * D_MODEL + i] + xr[i] * inv * w[i];
}

// -------- conv(k=4, causal) + silu: register window over 64-token tiles --------
#define CLT 64
__global__ void conv_silu_kernel(const bf16* __restrict__ xz, const float* __restrict__ cw,
                                 const float* __restrict__ cb, bf16* __restrict__ xc) {
    int d = blockIdx.x * 128 + threadIdx.x;
    if (d >= D_INNER) return;
    int l0 = blockIdx.y * CLT, b = blockIdx.z;
    float w0 = cw[d * 4 + 0], w1 = cw[d * 4 + 1], w2 = cw[d * 4 + 2], w3 = cw[d * 4 + 3];
    float bb = cb[d];
    size_t row = (size_t)b * L_SEQ + l0;
    const bf16* src = xz + row * TWO_DI + d;
    bf16* dst = xc + row * KI + d;
    float x0, x1, x2;
    if (l0 == 0) { x0 = x1 = x2 = 0.f; }
    else {
        x0 = __bfloat162float(src[-3 * TWO_DI]);
        x1 = __bfloat162float(src[-2 * TWO_DI]);
        x2 = __bfloat162float(src[-1 * TWO_DI]);
    }
    #pragma unroll 4
    for (int i = 0; i < CLT; ++i) {
        float x3 = __bfloat162float(src[(size_t)i * TWO_DI]);
        float acc = bb + w0 * x0 + w1 * x1 + w2 * x2 + w3 * x3;
        dst[(size_t)i * KI] = __float2bfloat16(acc / (1.f + __expf(-acc)));
        x0 = x1; x1 = x2; x2 = x3;
    }
}

// -------- chunked selective scan; dt inline; fast q-power path --------
__device__ __forceinline__ float softplus_f(float a) {
    return (a > 15.f) ? a : log1pf(__expf(a));
}
__device__ __forceinline__ bool a_is_arange(const float* Av) {
    bool ok = Av[0] < 0.f;
    #pragma unroll
    for (int s = 1; s < 16; ++s)
        ok = ok && (fabsf(Av[s] - (float)(s + 1) * Av[0]) <= 1e-4f * fabsf(Av[s]));
    return ok;
}

// S1: per-chunk local state (h from 0) + sum(dt)
__global__ __launch_bounds__(128) void scan1_kernel(
    const bf16* __restrict__ u, const float* __restrict__ xdbl,
    const float* __restrict__ A_log, const float* __restrict__ dtw,
    const float* __restrict__ dtb, float* __restrict__ Lc, float* __restrict__ sdtc) {
    __shared__ float sDL[SCT][18];
    __shared__ float sB[SCT][16];
    __shared__ bf16 s_u[STL][128];
    int b = blockIdx.z, c = blockIdx.y, d0 = blockIdx.x * 128;
    int tid = threadIdx.x;
    int d = d0 + tid;
    bool act = d < D_INNER;
    int dc = act ? d : (D_INNER - 1);
    size_t rb = (size_t)b * L_SEQ + (size_t)c * SCT;
    float Av[16];
    #pragma unroll
    for (int s = 0; s < 16; s += 4) {
        float4 al = *(const float4*)(A_log + (size_t)dc * 16 + s);
        Av[s + 0] = -__expf(al.x); Av[s + 1] = -__expf(al.y);
        Av[s + 2] = -__expf(al.z); Av[s + 3] = -__expf(al.w);
    }
    const bool fast = a_is_arange(Av);
    const float Av0 = Av[0];
    float wv[DT_RANK];
    #pragma unroll
    for (int r = 0; r < DT_RANK; ++r) wv[r] = dtw[(size_t)dc * DT_RANK + r];
    float bias = dtb[dc];
    for (int i = tid; i < SCT * 16; i += 128) {
        int t = i >> 4, s = i & 15;
        sB[t][s] = xdbl[(rb + t) * XW + DT_RANK + s];
    }
    for (int i = tid; i < SCT * DT_RANK; i += 128) {
        int t = i / DT_RANK, r = i - t * DT_RANK;
        sDL[t][r] = xdbl[(rb + t) * XW + r];
    }
    float h[16];
    #pragma unroll
    for (int s = 0; s < 16; ++s) h[s] = 0.f;
    float sd = 0.f;
    for (int t0 = 0; t0 < SCT; t0 += STL) {
        __syncthreads();
        for (int q = tid; q < STL * 64; q += 128) {
            int tt = q >> 6, dp = (q & 63) * 2;
            *(uint32_t*)&s_u[tt][dp] = *(const uint32_t*)(u + (rb + t0 + tt) * KI + d0 + dp);
        }
        __syncthreads();
        for (int tt = 0; tt < STL; ++tt) {
            float dta = bias;
            const float* dl = sDL[t0 + tt];
            #pragma unroll
            for (int r = 0; r < DT_RANK; ++r) dta = fmaf(dl[r], wv[r], dta);
            float dtv = softplus_f(dta);
            float uv = __bfloat162float(s_u[tt][tid]);
            float e = dtv * uv;
            sd += dtv;
            const float4* pB = (const float4*)sB[t0 + tt];
            if (fast) {
                float q = __expf(dtv * Av0);
                float p = 1.f;
                #pragma unroll
                for (int s4 = 0; s4 < 4; ++s4) {
                    float4 Bv = pB[s4];
                    p *= q; h[s4*4+0] = fmaf(p, h[s4*4+0], e * Bv.x);
                    p *= q; h[s4*4+1] = fmaf(p, h[s4*4+1], e * Bv.y);
                    p *= q; h[s4*4+2] = fmaf(p, h[s4*4+2], e * Bv.z);
                    p *= q; h[s4*4+3] = fmaf(p, h[s4*4+3], e * Bv.w);
                }
            } else {
                #pragma unroll
                for (int s4 = 0; s4 < 4; ++s4) {
                    float4 Bv = pB[s4];
                    h[s4*4+0] = fmaf(__expf(dtv * Av[s4*4+0]), h[s4*4+0], e * Bv.x);
                    h[s4*4+1] = fmaf(__expf(dtv * Av[s4*4+1]), h[s4*4+1], e * Bv.y);
                    h[s4*4+2] = fmaf(__expf(dtv * Av[s4*4+2]), h[s4*4+2], e * Bv.z);
                    h[s4*4+3] = fmaf(__expf(dtv * Av[s4*4+3]), h[s4*4+3], e * Bv.w);
                }
            }
        }
    }
    if (act) {
        size_t o = ((size_t)b * NCHK + c) * D_INNER + d;
        float4* pL = (float4*)(Lc + o * 16);
        #pragma unroll
        for (int s4 = 0; s4 < 4; ++s4)
            pL[s4] = make_float4(h[s4*4+0], h[s4*4+1], h[s4*4+2], h[s4*4+3]);
        sdtc[o] = sd;
    }
}

// S2: stitch chunk summaries -> initial state per chunk
__global__ void scan2_kernel(const float* __restrict__ Lc, const float* __restrict__ sdtc,
                             const float* __restrict__ A_log, float* __restrict__ H0) {
    int idx = blockIdx.x * 128 + threadIdx.x;
    if (idx >= B_SZ * D_INNER * D_STATE) return;
    int s = idx & 15, rest = idx >> 4;
    int d = rest % D_INNER, b = rest / D_INNER;
    float Av = -__expf(A_log[(size_t)d * 16 + s]);
    float h = 0.f;
    #pragma unroll
    for (int c = 0; c < NCHK; ++c) {
        size_t o = (((size_t)b * NCHK + c) * D_INNER + d);
        H0[o * 16 + s] = h;
        h = __expf(Av * sdtc[o]) * h + Lc[o * 16 + s];
    }
}

// S3: replay with initial state, y + fused gate; bf16 out
__global__ __launch_bounds__(128) void scan3_kernel(
    const bf16* __restrict__ u, const float* __restrict__ xdbl,
    const bf16* __restrict__ xz, const float* __restrict__ A_log,
    const float* __restrict__ dtw, const float* __restrict__ dtb,
    const float* __restrict__ Dp, const float* __restrict__ H0,
    bf16* __restrict__ y2) {
    __shared__ float sDL[SCT][18];
    __shared__ float sB[SCT][16];
    __shared__ float sC[SCT][16];
    __shared__ bf16 s_u[STL][128];
    __shared__ bf16 s_z[STL][128];
    int b = blockIdx.z, c = blockIdx.y, d0 = blockIdx.x * 128;
    int tid = threadIdx.x;
    int d = d0 + tid;
    bool act = d < D_INNER;
    int dc = act ? d : (D_INNER - 1);
    size_t rb = (size_t)b * L_SEQ + (size_t)c * SCT;
    float Av[16];
    #pragma unroll
    for (int s = 0; s < 16; s += 4) {
        float4 al = *(const float4*)(A_log + (size_t)dc * 16 + s);
        Av[s + 0] = -__expf(al.x); Av[s + 1] = -__expf(al.y);
        Av[s + 2] = -__expf(al.z); Av[s + 3] = -__expf(al.w);
    }
    const bool fast = a_is_arange(Av);
    const float Av0 = Av[0];
    float wv[DT_RANK];
    #pragma unroll
    for (int r = 0; r < DT_RANK; ++r) wv[r] = dtw[(size_t)dc * DT_RANK + r];
    float bias = dtb[dc];
    float Dv = Dp[dc];
    for (int i = tid; i < SCT * 16; i += 128) {
        int t = i >> 4, s = i & 15;
        const float* g = xdbl + (rb + t) * XW + DT_RANK;
        sB[t][s] = g[s];
        sC[t][s] = g[16 + s];
    }
    for (int i = tid; i < SCT * DT_RANK; i += 128) {
        int t = i / DT_RANK, r = i - t * DT_RANK;
        sDL[t][r] = xdbl[(rb + t) * XW + r];
    }
    float h[16];
    {
        size_t o = ((size_t)b * NCHK + c) * D_INNER + dc;
        const float4* pH = (const float4*)(H0 + o * 16);
        #pragma unroll
        for (int s4 = 0; s4 < 4; ++s4) {
            float4 hv = pH[s4];
            h[s4*4+0] = hv.x; h[s4*4+1] = hv.y; h[s4*4+2] = hv.z; h[s4*4+3] = hv.w;
        }
    }
    for (int t0 = 0; t0 < SCT; t0 += STL) {
        __syncthreads();
        for (int q = tid; q < STL * 64; q += 128) {
            int tt = q >> 6, dp = (q & 63) * 2;
            *(uint32_t*)&s_u[tt][dp] = *(const uint32_t*)(u  + (rb + t0 + tt) * KI + d0 + dp);
            *(uint32_t*)&s_z[tt][dp] = *(const uint32_t*)(xz + (rb + t0 + tt) * TWO_DI + D_INNER + d0 + dp);
        }
        __syncthreads();
        for (int tt = 0; tt < STL; ++tt) {
            float dta = bias;
            const float* dl = sDL[t0 + tt];
            #pragma unroll
            for (int r = 0; r < DT_RANK; ++r) dta = fmaf(dl[r], wv[r], dta);
            float dtv = softplus_f(dta);
            float uv = __bfloat162float(s_u[tt][tid]);
            float e = dtv * uv;
            const float4* pB = (const float4*)sB[t0 + tt];
            const float4* pC = (const float4*)sC[t0 + tt];
            float y = 0.f;
            if (fast) {
                float q = __expf(dtv * Av0);
                float p = 1.f;
                #pragma unroll
                for (int s4 = 0; s4 < 4; ++s4) {
                    float4 Bv = pB[s4];
                    float4 Cv = pC[s4];
                    p *= q; h[s4*4+0] = fmaf(p, h[s4*4+0], e * Bv.x);
                    p *= q; h[s4*4+1] = fmaf(p, h[s4*4+1], e * Bv.y);
                    p *= q; h[s4*4+2] = fmaf(p, h[s4*4+2], e * Bv.z);
                    p *= q; h[s4*4+3] = fmaf(p, h[s4*4+3], e * Bv.w);
                    y += h[s4*4+0] * Cv.x + h[s4*4+1] * Cv.y
                       + h[s4*4+2] * Cv.z + h[s4*4+3] * Cv.w;
                }
            } else {
                #pragma unroll
                for (int s4 = 0; s4 < 4; ++s4) {
                    float4 Bv = pB[s4];
                    float4 Cv = pC[s4];
                    h[s4*4+0] = fmaf(__expf(dtv * Av[s4*4+0]), h[s4*4+0], e * Bv.x);
                    h[s4*4+1] = fmaf(__expf(dtv * Av[s4*4+1]), h[s4*4+1], e * Bv.y);
                    h[s4*4+2] = fmaf(__expf(dtv * Av[s4*4+2]), h[s4*4+2], e * Bv.z);
                    h[s4*4+3] = fmaf(__expf(dtv * Av[s4*4+3]), h[s4*4+3], e * Bv.w);
                    y += h[s4*4+0] * Cv.x + h[s4*4+1] * Cv.y
                       + h[s4*4+2] * Cv.z + h[s4*4+3] * Cv.w;
                }
            }
            if (act) {
                float z = __bfloat162float(s_z[tt][tid]);
                y2[(rb + t0 + tt) * KI + d] =
                    __float2bfloat16((y + uv * Dv) * (z / (1.f + __expf(-z))));
            }
        }
    }
}

// -------- weight packing --------
__global__ void pack1_kernel(const float* __restrict__ ipw, bf16* __restrict__ win) {
    int i = blockIdx.x * 256 + threadIdx.x;
    int total = N_LAYERS * 1032 * 258;
    if (i >= total) return;
    int k = i % 258, nr = i / 258, n = nr % 1032, l = nr / 1032;
    win[((size_t)l * WIN_R + n) * KM + k] = __float2bfloat16(ipw[i]);
}
__global__ void pack2_kernel(const float* __restrict__ opw, const float* __restrict__ xpw,
                             bf16* __restrict__ wout, bf16* __restrict__ wxp) {
    int i = blockIdx.x * 256 + threadIdx.x;
    const int OUT_T = N_LAYERS * 258 * 516, XP_T = N_LAYERS * 49 * 516;
    if (i < OUT_T) {
        int k = i % 516, nr = i / 516, n = nr % 258, l = nr / 258;
        wout[((size_t)l * WOUT_R + n) * KI + k] = __float2bfloat16(opw[i]);
    } else if (i < OUT_T + XP_T) {
        int j = i - OUT_T;
        int k = j % 516, nr = j / 516, n = nr % 49, l = nr / 49;
        wxp[((size_t)l * WXP_R + n) * KI + k] = __float2bfloat16(xpw[j]);
    }
}

// -------- host --------
extern "C" void kernel_launch(void* const* d_in, const int* in_sizes, int n_in,
                              void* d_out, int out_size) {
    const float* fuse  = (const float*)d_in[0];
    const float* nwv   = (const float*)d_in[1];
    const float* ipw   = (const float*)d_in[2];
    const float* cwv   = (const float*)d_in[3];
    const float* cbv   = (const float*)d_in[4];
    const float* xpw   = (const float*)d_in[5];
    const float* dtwv  = (const float*)d_in[6];
    const float* dtbv  = (const float*)d_in[7];
    const float* Alv   = (const float*)d_in[8];
    const float* Dpv   = (const float*)d_in[9];
    const float* opw   = (const float*)d_in[10];
    const float* fw    = (const float*)d_in[11];
    float* out = (float*)d_out;

    float *p_x, *p_xdbl, *p_L, *p_H0, *p_sdt;
    bf16 *p_xn, *p_xz, *p_xc, *p_y2, *p_win, *p_wout, *p_wxp;
    cudaGetSymbolAddress((void**)&p_x, g_x);
    cudaGetSymbolAddress((void**)&p_xn, g_xn);
    cudaGetSymbolAddress((void**)&p_xz, g_xz);
    cudaGetSymbolAddress((void**)&p_xc, g_xc);
    cudaGetSymbolAddress((void**)&p_xdbl, g_xdbl);
    cudaGetSymbolAddress((void**)&p_y2, g_y2);
    cudaGetSymbolAddress((void**)&p_win, g_win);
    cudaGetSymbolAddress((void**)&p_wout, g_wout);
    cudaGetSymbolAddress((void**)&p_wxp, g_wxp);
    cudaGetSymbolAddress((void**)&p_L, g_L);
    cudaGetSymbolAddress((void**)&p_H0, g_H0);
    cudaGetSymbolAddress((void**)&p_sdt, g_sdt);

    // smem sizes: NSTAGE * (BM+BN) * AW * 4 bytes
    const int SM_IN  = 3 * (128 + 128) * AW * 4;  // 61440 (needs opt-in)
    const int SM_OUT = 3 * (64 + 128) * AW * 4;   // 46080
    const int SM_XP  = 3 * (32 + 64) * AW * 4;    // 23040
    cudaFuncSetAttribute((const void*)gemm_bf16<128, 128, 2, 3>,
                         cudaFuncAttributeMaxDynamicSharedMemorySize, SM_IN);

    pack1_kernel<<<(N_LAYERS * 1032 * 258 + 255) / 256, 256>>>(ipw, p_win);
    {
        int tot = N_LAYERS * 258 * 516 + N_LAYERS * 49 * 516;
        pack2_kernel<<<(tot + 255) / 256, 256>>>(opw, xpw, p_wout, p_wxp);
    }
    cudaMemcpyAsync(p_x, fuse, (size_t)NTOK * D_MODEL * sizeof(float),
                    cudaMemcpyDeviceToDevice);

    for (int l = 0; l < N_LAYERS; ++l) {
        const float* Al = Alv + (size_t)l * D_INNER * 16;
        const float* dtw = dtwv + (size_t)l * D_INNER * DT_RANK;
        const float* dtb = dtbv + (size_t)l * D_INNER;
        rmsnorm_kernel<<<NTOK / 8, 256>>>(p_x, nwv + (size_t)l * D_MODEL, p_xn, KM);
        gemm_bf16<128, 128, 2, 3><<<dim3(9, 64), 256, SM_IN>>>(
            p_xn, p_win + (size_t)l * WIN_R * KM, p_xz, TWO_DI, KM, KM, TWO_DI);
        conv_silu_kernel<<<dim3(5, L_SEQ / CLT, B_SZ), 128>>>(
            p_xz, cwv + (size_t)l * D_INNER * 4, cbv + (size_t)l * D_INNER, p_xc);
        gemm_bf16<32, 64, 0, 3><<<dim3(1, 256), 256, SM_XP>>>(
            p_xc, p_wxp + (size_t)l * WXP_R * KI, p_xdbl, 49, KI, KI, XW);
        scan1_kernel<<<dim3(5, NCHK, B_SZ), 128>>>(
            p_xc, p_xdbl, Al, dtw, dtb, p_L, p_sdt);
        scan2_kernel<<<(B_SZ * D_INNER * D_STATE + 127) / 128, 128>>>(
            p_L, p_sdt, Al, p_H0);
        scan3_kernel<<<dim3(5, NCHK, B_SZ), 128>>>(
            p_xc, p_xdbl, p_xz, Al, dtw, dtb, Dpv + (size_t)l * D_INNER, p_H0, p_y2);
        gemm_bf16<64, 128, 1, 3><<<dim3(3, 128), 256, SM_OUT>>>(
            p_y2, p_wout + (size_t)l * WOUT_R * KI, p_x, D_MODEL, KI, KI, D_MODEL);
    }
    final_kernel<<<NTOK / 8, 256>>>(fuse, p_x, fw, out);
    (void)in_sizes; (void)n_in; (void)out_size;
}

// round 10
// speedup vs baseline: 3.5196x; 1.2117x over previous
#include <cuda_runtime.h>
#include <cuda_bf16.h>
#include <math.h>
#include <stdint.h>

#define B_SZ 4
#define L_SEQ 2048
#define D_MODEL 258
#define N_LAYERS 4
#define D_STATE 16
#define D_INNER 516
#define DT_RANK 17
#define TWO_DI 1032
#define XW 56            // padded xdbl stride (49 real cols)
#define NTOK 8192
#define EPS 1e-5f
#define KM 288           // 258 padded to 32-chunks
#define KI 544           // 516 padded
#define WIN_R 1152       // 9 * 128
#define WOUT_R 384       // 3 * 128
#define WXP_R 64
#define NCHK 32          // scan chunks
#define SCT 64           // tokens per scan chunk
#define STL 32           // scan stage tile (tokens)

typedef __nv_bfloat16 bf16;

// -------- device scratch (zero-init; +pad for vectorized edge reads) --------
__device__ __align__(256) float g_x[NTOK * D_MODEL];
__device__ __align__(256) bf16  g_xn[NTOK * KM];
__device__ __align__(256) bf16  g_xz[NTOK * TWO_DI + 256];
__device__ __align__(256) bf16  g_xc[NTOK * KI + 256];
__device__ __align__(256) float g_xdbl[NTOK * XW];
__device__ __align__(256) bf16  g_y2[NTOK * KI];
__device__ __align__(256) bf16  g_win[N_LAYERS * WIN_R * KM];
__device__ __align__(256) bf16  g_wout[N_LAYERS * WOUT_R * KI];
__device__ __align__(256) bf16  g_wxp[N_LAYERS * WXP_R * KI];
__device__ __align__(256) float g_L[B_SZ * NCHK * D_INNER * D_STATE];
__device__ __align__(256) float g_H0[B_SZ * NCHK * D_INNER * D_STATE];
__device__ __align__(256) float g_sdt[B_SZ * NCHK * D_INNER];

// -------- helpers --------
__device__ __forceinline__ uint32_t smem_u32(const void* p) {
    uint32_t a;
    asm("{ .reg .u64 t; cvta.to.shared.u64 t, %1; cvt.u32.u64 %0, t; }" : "=r"(a) : "l"(p));
    return a;
}
__device__ __forceinline__ void cp_async16(uint32_t dst, const void* src) {
    asm volatile("cp.async.cg.shared.global [%0], [%1], 16;" :: "r"(dst), "l"(src));
}
#define CP_COMMIT() asm volatile("cp.async.commit_group;" ::: "memory")

__device__ __forceinline__ void mma_bf16(float* d, const uint32_t* a, const uint32_t* b) {
    asm volatile(
        "mma.sync.aligned.m16n8k16.row.col.f32.bf16.bf16.f32 "
        "{%0,%1,%2,%3},{%4,%5,%6,%7},{%8,%9},{%0,%1,%2,%3};"
        : "+f"(d[0]), "+f"(d[1]), "+f"(d[2]), "+f"(d[3])
        : "r"(a[0]), "r"(a[1]), "r"(a[2]), "r"(a[3]), "r"(b[0]), "r"(b[1]));
}
__device__ __forceinline__ void ldsm_x4(uint32_t* r, uint32_t addr) {
    asm volatile("ldmatrix.sync.aligned.m8n8.x4.shared.b16 {%0,%1,%2,%3}, [%4];"
        : "=r"(r[0]), "=r"(r[1]), "=r"(r[2]), "=r"(r[3]) : "r"(addr));
}
__device__ __forceinline__ void ldsm_x2(uint32_t* r, uint32_t addr) {
    asm volatile("ldmatrix.sync.aligned.m8n8.x2.shared.b16 {%0,%1}, [%2];"
        : "=r"(r[0]), "=r"(r[1]) : "r"(addr));
}

// -------- bf16 mma GEMM: C[8192,N] = A[8192,K]bf16 @ W[N,K]bf16^T --------
// CTA BM x BN; 8 warps; K chunk 32; NSTAGE-deep cp.async; 1 barrier/chunk.
// OUTMODE: 0 = fp32 store, 1 = fp32 add-store, 2 = bf16 store.
#define AW 20            // smem row stride in words (40 bf16) — LDSM conflict-free
template <int BM, int BN, int OUTMODE, int NSTAGE>
__global__ __launch_bounds__(256) void gemm_bf16(
    const bf16* __restrict__ A, const bf16* __restrict__ W,
    void* __restrict__ Cv, int N_store, int K, int lda, int ldc) {
    constexpr int MW = BM / 32;
    constexpr int NW = 8 / MW;
    constexpr int WN = BN / NW;
    constexpr int NT = WN / 8;
    constexpr int ASTG = BM * AW, BSTG = BN * AW, STG = ASTG + BSTG;
    extern __shared__ uint32_t sm[];
    const int tid = threadIdx.x, wid = tid >> 5, lane = tid & 31;
    const int warpM = wid % MW, warpN = wid / MW;
    const int quad = lane >> 2, qk = lane & 3;
    const int bm = blockIdx.y * BM, bn = blockIdx.x * BN;
    float acc[2][NT][4];
    #pragma unroll
    for (int i = 0; i < 2; ++i)
        #pragma unroll
        for (int j = 0; j < NT; ++j)
            #pragma unroll
            for (int k = 0; k < 4; ++k) acc[i][j][k] = 0.f;

    const bf16* Ab = A + (size_t)bm * lda;
    const bf16* Wb = W + (size_t)bn * K;
    const int nch = K >> 5;
    const uint32_t sm_u = smem_u32(sm);
    const int l8 = lane & 7, jm = lane >> 3;

    const uint32_t aLM = sm_u +
        (uint32_t)(((warpM * 32 + ((jm & 1) << 3) + l8) * AW + ((jm >> 1) << 2)) * 4);
    const uint32_t bLM4 = sm_u + ASTG * 4 +
        (uint32_t)(((warpN * WN + ((jm >> 1) << 3) + l8) * AW + ((jm & 1) << 2)) * 4);
    const uint32_t bLM2 = sm_u + ASTG * 4 +
        (uint32_t)(((warpN * WN + l8) * AW + (((lane >> 3) & 1) << 2)) * 4);

    auto load_chunk = [&](int c, int st) {
        const bf16* Ac = Ab + c * 32;
        #pragma unroll
        for (int fi = tid; fi < BM * 4; fi += 256) {
            int r = fi >> 2, sg = fi & 3;
            cp_async16(sm_u + (uint32_t)(st * STG + r * AW + sg * 4) * 4,
                       Ac + (size_t)r * lda + sg * 8);
        }
        const bf16* Wc = Wb + c * 32;
        #pragma unroll
        for (int fi = tid; fi < BN * 4; fi += 256) {
            int r = fi >> 2, sg = fi & 3;
            cp_async16(sm_u + (uint32_t)(st * STG + ASTG + r * AW + sg * 4) * 4,
                       Wc + (size_t)r * K + sg * 8);
        }
    };

    #pragma unroll
    for (int p = 0; p < NSTAGE - 1; ++p) {
        if (p < nch) load_chunk(p, p);
        CP_COMMIT();
    }

    for (int c = 0; c < nch; ++c) {
        asm volatile("cp.async.wait_group %0;" :: "n"(NSTAGE - 2) : "memory");
        __syncthreads();
        int nx = c + NSTAGE - 1;
        if (nx < nch) load_chunk(nx, nx % NSTAGE);
        CP_COMMIT();
        const uint32_t stOff = (uint32_t)((c % NSTAGE) * STG * 4);
        #pragma unroll
        for (int ks = 0; ks < 2; ++ks) {
            uint32_t a[2][4], b[NT][2];
            #pragma unroll
            for (int mt = 0; mt < 2; ++mt)
                ldsm_x4(a[mt], aLM + stOff + (uint32_t)(mt * 16 * AW * 4 + ks * 32));
            if (NT == 1) {
                ldsm_x2(b[0], bLM2 + stOff + (uint32_t)(ks * 32));
            } else {
                #pragma unroll
                for (int p = 0; p < NT / 2; ++p) {
                    uint32_t t4[4];
                    ldsm_x4(t4, bLM4 + stOff + (uint32_t)(p * 16 * AW * 4 + ks * 32));
                    b[2*p][0] = t4[0]; b[2*p][1] = t4[1];
                    b[2*p+1][0] = t4[2]; b[2*p+1][1] = t4[3];
                }
            }
            #pragma unroll
            for (int mt = 0; mt < 2; ++mt)
                #pragma unroll
                for (int nt = 0; nt < NT; ++nt)
                    mma_bf16(acc[mt][nt], a[mt], b[nt]);
        }
    }
    __syncthreads();

    #pragma unroll
    for (int mt = 0; mt < 2; ++mt) {
        int r0 = bm + warpM * 32 + mt * 16 + quad;
        #pragma unroll
        for (int nt = 0; nt < NT; ++nt) {
            int gc = bn + warpN * WN + nt * 8 + qk * 2;
            #pragma unroll
            for (int half = 0; half < 2; ++half) {
                int row = r0 + half * 8;
                float v0 = acc[mt][nt][half * 2 + 0];
                float v1 = acc[mt][nt][half * 2 + 1];
                size_t gi = (size_t)row * ldc + gc;
                if (OUTMODE == 2) {
                    bf16* C = (bf16*)Cv;
                    if (gc < N_store) C[gi] = __float2bfloat16(v0);
                    if (gc + 1 < N_store) C[gi + 1] = __float2bfloat16(v1);
                } else {
                    float* C = (float*)Cv;
                    if (gc < N_store) {
                        if (OUTMODE == 1) v0 += C[gi];
                        C[gi] = v0;
                    }
                    if (gc + 1 < N_store) {
                        if (OUTMODE == 1) v1 += C[gi + 1];
                        C[gi + 1] = v1;
                    }
                }
            }
        }
    }
}

// -------- rmsnorm: warp per token, bf16 out --------
__global__ void rmsnorm_kernel(const float* __restrict__ x, const float* __restrict__ w,
                               bf16* __restrict__ o, int ldo) {
    int tok = (blockIdx.x * blockDim.x + threadIdx.x) >> 5;
    int lane = threadIdx.x & 31;
    if (tok >= NTOK) return;
    const float* xr = x + (size_t)tok * D_MODEL;
    float ss = 0.f;
    for (int i = lane; i < D_MODEL; i += 32) { float v = xr[i]; ss += v * v; }
    #pragma unroll
    for (int off = 16; off; off >>= 1) ss += __shfl_xor_sync(~0u, ss, off);
    float inv = rsqrtf(ss * (1.f / D_MODEL) + EPS);
    for (int i = lane; i < D_MODEL; i += 32)
        o[(size_t)tok * ldo + i] = __float2bfloat16(xr[i] * inv * w[i]);
}

__global__ void final_kernel(const float* __restrict__ f, const float* __restrict__ x,
                             const float* __restrict__ w, float* __restrict__ o) {
    int tok = (blockIdx.x * blockDim.x + threadIdx.x) >> 5;
    int lane = threadIdx.x & 31;
    if (tok >= NTOK) return;
    const float* xr = x + (size_t)tok * D_MODEL;
    float ss = 0.f;
    for (int i = lane; i < D_MODEL; i += 32) { float v = xr[i]; ss += v * v; }
    #pragma unroll
    for (int off = 16; off; off >>= 1) ss += __shfl_xor_sync(~0u, ss, off);
    float inv = rsqrtf(ss * (1.f / D_MODEL) + EPS);
    for (int i = lane; i < D_MODEL; i += 32)
        o[(size_t)tok * D_MODEL + i] = f[(size_t)tok * D_MODEL + i] + xr[i] * inv * w[i];
}

// -------- conv(k=4, causal) + silu: register window over 64-token tiles --------
#define CLT 64
__global__ void conv_silu_kernel(const bf16* __restrict__ xz, const float* __restrict__ cw,
                                 const float* __restrict__ cb, bf16* __restrict__ xc) {
    int d = blockIdx.x * 128 + threadIdx.x;
    if (d >= D_INNER) return;
    int l0 = blockIdx.y * CLT, b = blockIdx.z;
    float w0 = cw[d * 4 + 0], w1 = cw[d * 4 + 1], w2 = cw[d * 4 + 2], w3 = cw[d * 4 + 3];
    float bb = cb[d];
    size_t row = (size_t)b * L_SEQ + l0;
    const bf16* src = xz + row * TWO_DI + d;
    bf16* dst = xc + row * KI + d;
    float x0, x1, x2;
    if (l0 == 0) { x0 = x1 = x2 = 0.f; }
    else {
        x0 = __bfloat162float(src[-3 * TWO_DI]);
        x1 = __bfloat162float(src[-2 * TWO_DI]);
        x2 = __bfloat162float(src[-1 * TWO_DI]);
    }
    #pragma unroll 4
    for (int i = 0; i < CLT; ++i) {
        float x3 = __bfloat162float(src[(size_t)i * TWO_DI]);
        float acc = bb + w0 * x0 + w1 * x1 + w2 * x2 + w3 * x3;
        dst[(size_t)i * KI] = __float2bfloat16(acc / (1.f + __expf(-acc)));
        x0 = x1; x1 = x2; x2 = x3;
    }
}

// -------- chunked selective scan; dt inline; fast q-power path --------
__device__ __forceinline__ float softplus_f(float a) {
    return (a > 15.f) ? a : log1pf(__expf(a));
}
__device__ __forceinline__ bool a_is_arange(const float* Av) {
    bool ok = Av[0] < 0.f;
    #pragma unroll
    for (int s = 1; s < 16; ++s)
        ok = ok && (fabsf(Av[s] - (float)(s + 1) * Av[0]) <= 1e-4f * fabsf(Av[s]));
    return ok;
}

// S1: per-chunk local state (h from 0) + sum(dt)
__global__ __launch_bounds__(128) void scan1_kernel(
    const bf16* __restrict__ u, const float* __restrict__ xdbl,
    const float* __restrict__ A_log, const float* __restrict__ dtw,
    const float* __restrict__ dtb, float* __restrict__ Lc, float* __restrict__ sdtc) {
    __shared__ float sDL[SCT][18];
    __shared__ float sB[SCT][16];
    __shared__ bf16 s_u[STL][128];
    int b = blockIdx.z, c = blockIdx.y, d0 = blockIdx.x * 128;
    int tid = threadIdx.x;
    int d = d0 + tid;
    bool act = d < D_INNER;
    int dc = act ? d : (D_INNER - 1);
    size_t rb = (size_t)b * L_SEQ + (size_t)c * SCT;
    float Av[16];
    #pragma unroll
    for (int s = 0; s < 16; s += 4) {
        float4 al = *(const float4*)(A_log + (size_t)dc * 16 + s);
        Av[s + 0] = -__expf(al.x); Av[s + 1] = -__expf(al.y);
        Av[s + 2] = -__expf(al.z); Av[s + 3] = -__expf(al.w);
    }
    const bool fast = a_is_arange(Av);
    const float Av0 = Av[0];
    float wv[DT_RANK];
    #pragma unroll
    for (int r = 0; r < DT_RANK; ++r) wv[r] = dtw[(size_t)dc * DT_RANK + r];
    float bias = dtb[dc];
    for (int i = tid; i < SCT * 16; i += 128) {
        int t = i >> 4, s = i & 15;
        sB[t][s] = xdbl[(rb + t) * XW + DT_RANK + s];
    }
    for (int i = tid; i < SCT * DT_RANK; i += 128) {
        int t = i / DT_RANK, r = i - t * DT_RANK;
        sDL[t][r] = xdbl[(rb + t) * XW + r];
    }
    float h[16];
    #pragma unroll
    for (int s = 0; s < 16; ++s) h[s] = 0.f;
    float sd = 0.f;
    for (int t0 = 0; t0 < SCT; t0 += STL) {
        __syncthreads();
        for (int q = tid; q < STL * 64; q += 128) {
            int tt = q >> 6, dp = (q & 63) * 2;
            *(uint32_t*)&s_u[tt][dp] = *(const uint32_t*)(u + (rb + t0 + tt) * KI + d0 + dp);
        }
        __syncthreads();
        for (int tt = 0; tt < STL; ++tt) {
            float dta = bias;
            const float* dl = sDL[t0 + tt];
            #pragma unroll
            for (int r = 0; r < DT_RANK; ++r) dta = fmaf(dl[r], wv[r], dta);
            float dtv = softplus_f(dta);
            float uv = __bfloat162float(s_u[tt][tid]);
            float e = dtv * uv;
            sd += dtv;
            const float4* pB = (const float4*)sB[t0 + tt];
            if (fast) {
                float q = __expf(dtv * Av0);
                float p = 1.f;
                #pragma unroll
                for (int s4 = 0; s4 < 4; ++s4) {
                    float4 Bv = pB[s4];
                    p *= q; h[s4*4+0] = fmaf(p, h[s4*4+0], e * Bv.x);
                    p *= q; h[s4*4+1] = fmaf(p, h[s4*4+1], e * Bv.y);
                    p *= q; h[s4*4+2] = fmaf(p, h[s4*4+2], e * Bv.z);
                    p *= q; h[s4*4+3] = fmaf(p, h[s4*4+3], e * Bv.w);
                }
            } else {
                #pragma unroll
                for (int s4 = 0; s4 < 4; ++s4) {
                    float4 Bv = pB[s4];
                    h[s4*4+0] = fmaf(__expf(dtv * Av[s4*4+0]), h[s4*4+0], e * Bv.x);
                    h[s4*4+1] = fmaf(__expf(dtv * Av[s4*4+1]), h[s4*4+1], e * Bv.y);
                    h[s4*4+2] = fmaf(__expf(dtv * Av[s4*4+2]), h[s4*4+2], e * Bv.z);
                    h[s4*4+3] = fmaf(__expf(dtv * Av[s4*4+3]), h[s4*4+3], e * Bv.w);
                }
            }
        }
    }
    if (act) {
        size_t o = ((size_t)b * NCHK + c) * D_INNER + d;
        float4* pL = (float4*)(Lc + o * 16);
        #pragma unroll
        for (int s4 = 0; s4 < 4; ++s4)
            pL[s4] = make_float4(h[s4*4+0], h[s4*4+1], h[s4*4+2], h[s4*4+3]);
        sdtc[o] = sd;
    }
}

// S2: stitch chunk summaries -> initial state per chunk
__global__ void scan2_kernel(const float* __restrict__ Lc, const float* __restrict__ sdtc,
                             const float* __restrict__ A_log, float* __restrict__ H0) {
    int idx = blockIdx.x * 128 + threadIdx.x;
    if (idx >= B_SZ * D_INNER * D_STATE) return;
    int s = idx & 15, rest = idx >> 4;
    int d = rest % D_INNER, b = rest / D_INNER;
    float Av = -__expf(A_log[(size_t)d * 16 + s]);
    float h = 0.f;
    #pragma unroll 8
    for (int c = 0; c < NCHK; ++c) {
        size_t o = (((size_t)b * NCHK + c) * D_INNER + d);
        H0[o * 16 + s] = h;
        h = __expf(Av * sdtc[o]) * h + Lc[o * 16 + s];
    }
}

// S3: replay with initial state, y + fused gate; bf16 out
__global__ __launch_bounds__(128) void scan3_kernel(
    const bf16* __restrict__ u, const float* __restrict__ xdbl,
    const bf16* __restrict__ xz, const float* __restrict__ A_log,
    const float* __restrict__ dtw, const float* __restrict__ dtb,
    const float* __restrict__ Dp, const float* __restrict__ H0,
    bf16* __restrict__ y2) {
    __shared__ float sDL[SCT][18];
    __shared__ float sB[SCT][16];
    __shared__ float sC[SCT][16];
    __shared__ bf16 s_u[STL][128];
    __shared__ bf16 s_z[STL][128];
    int b = blockIdx.z, c = blockIdx.y, d0 = blockIdx.x * 128;
    int tid = threadIdx.x;
    int d = d0 + tid;
    bool act = d < D_INNER;
    int dc = act ? d : (D_INNER - 1);
    size_t rb = (size_t)b * L_SEQ + (size_t)c * SCT;
    float Av[16];
    #pragma unroll
    for (int s = 0; s < 16; s += 4) {
        float4 al = *(const float4*)(A_log + (size_t)dc * 16 + s);
        Av[s + 0] = -__expf(al.x); Av[s + 1] = -__expf(al.y);
        Av[s + 2] = -__expf(al.z); Av[s + 3] = -__expf(al.w);
    }
    const bool fast = a_is_arange(Av);
    const float Av0 = Av[0];
    float wv[DT_RANK];
    #pragma unroll
    for (int r = 0; r < DT_RANK; ++r) wv[r] = dtw[(size_t)dc * DT_RANK + r];
    float bias = dtb[dc];
    float Dv = Dp[dc];
    for (int i = tid; i < SCT * 16; i += 128) {
        int t = i >> 4, s = i & 15;
        const float* g = xdbl + (rb + t) * XW + DT_RANK;
        sB[t][s] = g[s];
        sC[t][s] = g[16 + s];
    }
    for (int i = tid; i < SCT * DT_RANK; i += 128) {
        int t = i / DT_RANK, r = i - t * DT_RANK;
        sDL[t][r] = xdbl[(rb + t) * XW + r];
    }
    float h[16];
    {
        size_t o = ((size_t)b * NCHK + c) * D_INNER + dc;
        const float4* pH = (const float4*)(H0 + o * 16);
        #pragma unroll
        for (int s4 = 0; s4 < 4; ++s4) {
            float4 hv = pH[s4];
            h[s4*4+0] = hv.x; h[s4*4+1] = hv.y; h[s4*4+2] = hv.z; h[s4*4+3] = hv.w;
        }
    }
    for (int t0 = 0; t0 < SCT; t0 += STL) {
        __syncthreads();
        for (int q = tid; q < STL * 64; q += 128) {
            int tt = q >> 6, dp = (q & 63) * 2;
            *(uint32_t*)&s_u[tt][dp] = *(const uint32_t*)(u  + (rb + t0 + tt) * KI + d0 + dp);
            *(uint32_t*)&s_z[tt][dp] = *(const uint32_t*)(xz + (rb + t0 + tt) * TWO_DI + D_INNER + d0 + dp);
        }
        __syncthreads();
        for (int tt = 0; tt < STL; ++tt) {
            float dta = bias;
            const float* dl = sDL[t0 + tt];
            #pragma unroll
            for (int r = 0; r < DT_RANK; ++r) dta = fmaf(dl[r], wv[r], dta);
            float dtv = softplus_f(dta);
            float uv = __bfloat162float(s_u[tt][tid]);
            float e = dtv * uv;
            const float4* pB = (const float4*)sB[t0 + tt];
            const float4* pC = (const float4*)sC[t0 + tt];
            float y = 0.f;
            if (fast) {
                float q = __expf(dtv * Av0);
                float p = 1.f;
                #pragma unroll
                for (int s4 = 0; s4 < 4; ++s4) {
                    float4 Bv = pB[s4];
                    float4 Cv = pC[s4];
                    p *= q; h[s4*4+0] = fmaf(p, h[s4*4+0], e * Bv.x);
                    p *= q; h[s4*4+1] = fmaf(p, h[s4*4+1], e * Bv.y);
                    p *= q; h[s4*4+2] = fmaf(p, h[s4*4+2], e * Bv.z);
                    p *= q; h[s4*4+3] = fmaf(p, h[s4*4+3], e * Bv.w);
                    y += h[s4*4+0] * Cv.x + h[s4*4+1] * Cv.y
                       + h[s4*4+2] * Cv.z + h[s4*4+3] * Cv.w;
                }
            } else {
                #pragma unroll
                for (int s4 = 0; s4 < 4; ++s4) {
                    float4 Bv = pB[s4];
                    float4 Cv = pC[s4];
                    h[s4*4+0] = fmaf(__expf(dtv * Av[s4*4+0]), h[s4*4+0], e * Bv.x);
                    h[s4*4+1] = fmaf(__expf(dtv * Av[s4*4+1]), h[s4*4+1], e * Bv.y);
                    h[s4*4+2] = fmaf(__expf(dtv * Av[s4*4+2]), h[s4*4+2], e * Bv.z);
                    h[s4*4+3] = fmaf(__expf(dtv * Av[s4*4+3]), h[s4*4+3], e * Bv.w);
                    y += h[s4*4+0] * Cv.x + h[s4*4+1] * Cv.y
                       + h[s4*4+2] * Cv.z + h[s4*4+3] * Cv.w;
                }
            }
            if (act) {
                float z = __bfloat162float(s_z[tt][tid]);
                y2[(rb + t0 + tt) * KI + d] =
                    __float2bfloat16((y + uv * Dv) * (z / (1.f + __expf(-z))));
            }
        }
    }
}

// -------- weight packing --------
__global__ void pack1_kernel(const float* __restrict__ ipw, bf16* __restrict__ win) {
    int i = blockIdx.x * 256 + threadIdx.x;
    int total = N_LAYERS * 1032 * 258;
    if (i >= total) return;
    int k = i % 258, nr = i / 258, n = nr % 1032, l = nr / 1032;
    win[((size_t)l * WIN_R + n) * KM + k] = __float2bfloat16(ipw[i]);
}
__global__ void pack2_kernel(const float* __restrict__ opw, const float* __restrict__ xpw,
                             bf16* __restrict__ wout, bf16* __restrict__ wxp) {
    int i = blockIdx.x * 256 + threadIdx.x;
    const int OUT_T = N_LAYERS * 258 * 516, XP_T = N_LAYERS * 49 * 516;
    if (i < OUT_T) {
        int k = i % 516, nr = i / 516, n = nr % 258, l = nr / 258;
        wout[((size_t)l * WOUT_R + n) * KI + k] = __float2bfloat16(opw[i]);
    } else if (i < OUT_T + XP_T) {
        int j = i - OUT_T;
        int k = j % 516, nr = j / 516, n = nr % 49, l = nr / 49;
        wxp[((size_t)l * WXP_R + n) * KI + k] = __float2bfloat16(xpw[j]);
    }
}

// -------- host --------
extern "C" void kernel_launch(void* const* d_in, const int* in_sizes, int n_in,
                              void* d_out, int out_size) {
    const float* fuse  = (const float*)d_in[0];
    const float* nwv   = (const float*)d_in[1];
    const float* ipw   = (const float*)d_in[2];
    const float* cwv   = (const float*)d_in[3];
    const float* cbv   = (const float*)d_in[4];
    const float* xpw   = (const float*)d_in[5];
    const float* dtwv  = (const float*)d_in[6];
    const float* dtbv  = (const float*)d_in[7];
    const float* Alv   = (const float*)d_in[8];
    const float* Dpv   = (const float*)d_in[9];
    const float* opw   = (const float*)d_in[10];
    const float* fw    = (const float*)d_in[11];
    float* out = (float*)d_out;

    float *p_x, *p_xdbl, *p_L, *p_H0, *p_sdt;
    bf16 *p_xn, *p_xz, *p_xc, *p_y2, *p_win, *p_wout, *p_wxp;
    cudaGetSymbolAddress((void**)&p_x, g_x);
    cudaGetSymbolAddress((void**)&p_xn, g_xn);
    cudaGetSymbolAddress((void**)&p_xz, g_xz);
    cudaGetSymbolAddress((void**)&p_xc, g_xc);
    cudaGetSymbolAddress((void**)&p_xdbl, g_xdbl);
    cudaGetSymbolAddress((void**)&p_y2, g_y2);
    cudaGetSymbolAddress((void**)&p_win, g_win);
    cudaGetSymbolAddress((void**)&p_wout, g_wout);
    cudaGetSymbolAddress((void**)&p_wxp, g_wxp);
    cudaGetSymbolAddress((void**)&p_L, g_L);
    cudaGetSymbolAddress((void**)&p_H0, g_H0);
    cudaGetSymbolAddress((void**)&p_sdt, g_sdt);

    // smem sizes: NSTAGE * (BM+BN) * AW * 4 bytes
    const int SM_BIG = 4 * (64 + 128) * AW * 4;   // 61440 (needs opt-in)
    const int SM_XP  = 3 * (32 + 64) * AW * 4;    // 23040
    cudaFuncSetAttribute((const void*)gemm_bf16<64, 128, 2, 4>,
                         cudaFuncAttributeMaxDynamicSharedMemorySize, SM_BIG);
    cudaFuncSetAttribute((const void*)gemm_bf16<64, 128, 1, 4>,
                         cudaFuncAttributeMaxDynamicSharedMemorySize, SM_BIG);

    pack1_kernel<<<(N_LAYERS * 1032 * 258 + 255) / 256, 256>>>(ipw, p_win);
    {
        int tot = N_LAYERS * 258 * 516 + N_LAYERS * 49 * 516;
        pack2_kernel<<<(tot + 255) / 256, 256>>>(opw, xpw, p_wout, p_wxp);
    }
    cudaMemcpyAsync(p_x, fuse, (size_t)NTOK * D_MODEL * sizeof(float),
                    cudaMemcpyDeviceToDevice);

    for (int l = 0; l < N_LAYERS; ++l) {
        const float* Al = Alv + (size_t)l * D_INNER * 16;
        const float* dtw = dtwv + (size_t)l * D_INNER * DT_RANK;
        const float* dtb = dtbv + (size_t)l * D_INNER;
        rmsnorm_kernel<<<NTOK / 8, 256>>>(p_x, nwv + (size_t)l * D_MODEL, p_xn, KM);
        gemm_bf16<64, 128, 2, 4><<<dim3(9, 128), 256, SM_BIG>>>(
            p_xn, p_win + (size_t)l * WIN_R * KM, p_xz, TWO_DI, KM, KM, TWO_DI);
        conv_silu_kernel<<<dim3(5, L_SEQ / CLT, B_SZ), 128>>>(
            p_xz, cwv + (size_t)l * D_INNER * 4, cbv + (size_t)l * D_INNER, p_xc);
        gemm_bf16<32, 64, 0, 3><<<dim3(1, 256), 256, SM_XP>>>(
            p_xc, p_wxp + (size_t)l * WXP_R * KI, p_xdbl, 49, KI, KI, XW);
        scan1_kernel<<<dim3(5, NCHK, B_SZ), 128>>>(
            p_xc, p_xdbl, Al, dtw, dtb, p_L, p_sdt);
        scan2_kernel<<<(B_SZ * D_INNER * D_STATE + 127) / 128, 128>>>(
            p_L, p_sdt, Al, p_H0);
        scan3_kernel<<<dim3(5, NCHK, B_SZ), 128>>>(
            p_xc, p_xdbl, p_xz, Al, dtw, dtb, Dpv + (size_t)l * D_INNER, p_H0, p_y2);
        gemm_bf16<64, 128, 1, 4><<<dim3(3, 128), 256, SM_BIG>>>(
            p_y2, p_wout + (size_t)l * WOUT_R * KI, p_x, D_MODEL, KI, KI, D_MODEL);
    }
    final_kernel<<<NTOK / 8, 256>>>(fuse, p_x, fw, out);
    (void)in_sizes; (void)n_in; (void)out_size;
}

// round 11
// speedup vs baseline: 3.6808x; 1.0458x over previous
#include <cuda_runtime.h>
#include <cuda_bf16.h>
#include <math.h>
#include <stdint.h>

#define B_SZ 4
#define L_SEQ 2048
#define D_MODEL 258
#define N_LAYERS 4
#define D_STATE 16
#define D_INNER 516
#define DT_RANK 17
#define TWO_DI 1032
#define XW 56            // padded xdbl stride (49 real cols)
#define NTOK 8192
#define EPS 1e-5f
#define KM 288           // 258 padded to 32-chunks
#define KI 544           // 516 padded
#define WIN_R 1152       // 9 * 128
#define WOUT_R 384       // 3 * 128
#define WXP_R 64
#define NCHK 64          // scan chunks
#define SCT 32           // tokens per scan chunk

typedef __nv_bfloat16 bf16;

// -------- device scratch (zero-init; +pad for vectorized edge reads) --------
__device__ __align__(256) float g_x[NTOK * D_MODEL];
__device__ __align__(256) bf16  g_xn[NTOK * KM];
__device__ __align__(256) bf16  g_xz[NTOK * TWO_DI + 256];
__device__ __align__(256) bf16  g_xc[NTOK * KI + 256];
__device__ __align__(256) float g_xdbl[NTOK * XW];
__device__ __align__(256) bf16  g_y2[NTOK * KI + 256];
__device__ __align__(256) float g_cum[NTOK * KI + 256];
__device__ __align__(256) bf16  g_win[N_LAYERS * WIN_R * KM];
__device__ __align__(256) bf16  g_wout[N_LAYERS * WOUT_R * KI];
__device__ __align__(256) bf16  g_wxp[N_LAYERS * WXP_R * KI];
__device__ __align__(256) float g_L[B_SZ * NCHK * D_INNER * D_STATE];
__device__ __align__(256) float g_H0[B_SZ * NCHK * D_INNER * D_STATE];
__device__ __align__(256) float g_sdt[B_SZ * NCHK * D_INNER];

// -------- helpers --------
__device__ __forceinline__ uint32_t smem_u32(const void* p) {
    uint32_t a;
    asm("{ .reg .u64 t; cvta.to.shared.u64 t, %1; cvt.u32.u64 %0, t; }" : "=r"(a) : "l"(p));
    return a;
}
__device__ __forceinline__ void cp_async16(uint32_t dst, const void* src) {
    asm volatile("cp.async.cg.shared.global [%0], [%1], 16;" :: "r"(dst), "l"(src));
}
#define CP_COMMIT() asm volatile("cp.async.commit_group;" ::: "memory")

__device__ __forceinline__ void mma_bf16(float* d, const uint32_t* a, const uint32_t* b) {
    asm volatile(
        "mma.sync.aligned.m16n8k16.row.col.f32.bf16.bf16.f32 "
        "{%0,%1,%2,%3},{%4,%5,%6,%7},{%8,%9},{%0,%1,%2,%3};"
        : "+f"(d[0]), "+f"(d[1]), "+f"(d[2]), "+f"(d[3])
        : "r"(a[0]), "r"(a[1]), "r"(a[2]), "r"(a[3]), "r"(b[0]), "r"(b[1]));
}
__device__ __forceinline__ void ldsm_x4(uint32_t* r, uint32_t addr) {
    asm volatile("ldmatrix.sync.aligned.m8n8.x4.shared.b16 {%0,%1,%2,%3}, [%4];"
        : "=r"(r[0]), "=r"(r[1]), "=r"(r[2]), "=r"(r[3]) : "r"(addr));
}
__device__ __forceinline__ void ldsm_x2(uint32_t* r, uint32_t addr) {
    asm volatile("ldmatrix.sync.aligned.m8n8.x2.shared.b16 {%0,%1}, [%2];"
        : "=r"(r[0]), "=r"(r[1]) : "r"(addr));
}

// -------- bf16 mma GEMM: C[8192,N] = A[8192,K]bf16 @ W[N,K]bf16^T --------
#define AW 20            // smem row stride in words (40 bf16) — LDSM conflict-free
template <int BM, int BN, int OUTMODE, int NSTAGE>
__global__ __launch_bounds__(256) void gemm_bf16(
    const bf16* __restrict__ A, const bf16* __restrict__ W,
    void* __restrict__ Cv, int N_store, int K, int lda, int ldc) {
    constexpr int MW = BM / 32;
    constexpr int NW = 8 / MW;
    constexpr int WN = BN / NW;
    constexpr int NT = WN / 8;
    constexpr int ASTG = BM * AW, BSTG = BN * AW, STG = ASTG + BSTG;
    extern __shared__ uint32_t sm[];
    const int tid = threadIdx.x, wid = tid >> 5, lane = tid & 31;
    const int warpM = wid % MW, warpN = wid / MW;
    const int quad = lane >> 2, qk = lane & 3;
    const int bm = blockIdx.y * BM, bn = blockIdx.x * BN;
    float acc[2][NT][4];
    #pragma unroll
    for (int i = 0; i < 2; ++i)
        #pragma unroll
        for (int j = 0; j < NT; ++j)
            #pragma unroll
            for (int k = 0; k < 4; ++k) acc[i][j][k] = 0.f;

    const bf16* Ab = A + (size_t)bm * lda;
    const bf16* Wb = W + (size_t)bn * K;
    const int nch = K >> 5;
    const uint32_t sm_u = smem_u32(sm);
    const int l8 = lane & 7, jm = lane >> 3;

    const uint32_t aLM = sm_u +
        (uint32_t)(((warpM * 32 + ((jm & 1) << 3) + l8) * AW + ((jm >> 1) << 2)) * 4);
    const uint32_t bLM4 = sm_u + ASTG * 4 +
        (uint32_t)(((warpN * WN + ((jm >> 1) << 3) + l8) * AW + ((jm & 1) << 2)) * 4);
    const uint32_t bLM2 = sm_u + ASTG * 4 +
        (uint32_t)(((warpN * WN + l8) * AW + (((lane >> 3) & 1) << 2)) * 4);

    auto load_chunk = [&](int c, int st) {
        const bf16* Ac = Ab + c * 32;
        #pragma unroll
        for (int fi = tid; fi < BM * 4; fi += 256) {
            int r = fi >> 2, sg = fi & 3;
            cp_async16(sm_u + (uint32_t)(st * STG + r * AW + sg * 4) * 4,
                       Ac + (size_t)r * lda + sg * 8);
        }
        const bf16* Wc = Wb + c * 32;
        #pragma unroll
        for (int fi = tid; fi < BN * 4; fi += 256) {
            int r = fi >> 2, sg = fi & 3;
            cp_async16(sm_u + (uint32_t)(st * STG + ASTG + r * AW + sg * 4) * 4,
                       Wc + (size_t)r * K + sg * 8);
        }
    };

    #pragma unroll
    for (int p = 0; p < NSTAGE - 1; ++p) {
        if (p < nch) load_chunk(p, p);
        CP_COMMIT();
    }

    for (int c = 0; c < nch; ++c) {
        asm volatile("cp.async.wait_group %0;" :: "n"(NSTAGE - 2) : "memory");
        __syncthreads();
        int nx = c + NSTAGE - 1;
        if (nx < nch) load_chunk(nx, nx % NSTAGE);
        CP_COMMIT();
        const uint32_t stOff = (uint32_t)((c % NSTAGE) * STG * 4);
        #pragma unroll
        for (int ks = 0; ks < 2; ++ks) {
            uint32_t a[2][4], b[NT][2];
            #pragma unroll
            for (int mt = 0; mt < 2; ++mt)
                ldsm_x4(a[mt], aLM + stOff + (uint32_t)(mt * 16 * AW * 4 + ks * 32));
            if (NT == 1) {
                ldsm_x2(b[0], bLM2 + stOff + (uint32_t)(ks * 32));
            } else {
                #pragma unroll
                for (int p = 0; p < NT / 2; ++p) {
                    uint32_t t4[4];
                    ldsm_x4(t4, bLM4 + stOff + (uint32_t)(p * 16 * AW * 4 + ks * 32));
                    b[2*p][0] = t4[0]; b[2*p][1] = t4[1];
                    b[2*p+1][0] = t4[2]; b[2*p+1][1] = t4[3];
                }
            }
            #pragma unroll
            for (int mt = 0; mt < 2; ++mt)
                #pragma unroll
                for (int nt = 0; nt < NT; ++nt)
                    mma_bf16(acc[mt][nt], a[mt], b[nt]);
        }
    }
    __syncthreads();

    #pragma unroll
    for (int mt = 0; mt < 2; ++mt) {
        int r0 = bm + warpM * 32 + mt * 16 + quad;
        #pragma unroll
        for (int nt = 0; nt < NT; ++nt) {
            int gc = bn + warpN * WN + nt * 8 + qk * 2;
            #pragma unroll
            for (int half = 0; half < 2; ++half) {
                int row = r0 + half * 8;
                float v0 = acc[mt][nt][half * 2 + 0];
                float v1 = acc[mt][nt][half * 2 + 1];
                size_t gi = (size_t)row * ldc + gc;
                if (OUTMODE == 2) {
                    bf16* C = (bf16*)Cv;
                    if (gc < N_store) C[gi] = __float2bfloat16(v0);
                    if (gc + 1 < N_store) C[gi + 1] = __float2bfloat16(v1);
                } else {
                    float* C = (float*)Cv;
                    if (gc < N_store) {
                        if (OUTMODE == 1) v0 += C[gi];
                        C[gi] = v0;
                    }
                    if (gc + 1 < N_store) {
                        if (OUTMODE == 1) v1 += C[gi + 1];
                        C[gi + 1] = v1;
                    }
                }
            }
        }
    }
}

// -------- rmsnorm: warp per token, bf16 out --------
__global__ void rmsnorm_kernel(const float* __restrict__ x, const float* __restrict__ w,
                               bf16* __restrict__ o, int ldo) {
    int tok = (blockIdx.x * blockDim.x + threadIdx.x) >> 5;
    int lane = threadIdx.x & 31;
    if (tok >= NTOK) return;
    const float* xr = x + (size_t)tok * D_MODEL;
    float ss = 0.f;
    for (int i = lane; i < D_MODEL; i += 32) { float v = xr[i]; ss += v * v; }
    #pragma unroll
    for (int off = 16; off; off >>= 1) ss += __shfl_xor_sync(~0u, ss, off);
    float inv = rsqrtf(ss * (1.f / D_MODEL) + EPS);
    for (int i = lane; i < D_MODEL; i += 32)
        o[(size_t)tok * ldo + i] = __float2bfloat16(xr[i] * inv * w[i]);
}

__global__ void final_kernel(const float* __restrict__ f, const float* __restrict__ x,
                             const float* __restrict__ w, float* __restrict__ o) {
    int tok = (blockIdx.x * blockDim.x + threadIdx.x) >> 5;
    int lane = threadIdx.x & 31;
    if (tok >= NTOK) return;
    const float* xr = x + (size_t)tok * D_MODEL;
    float ss = 0.f;
    for (int i = lane; i < D_MODEL; i += 32) { float v = xr[i]; ss += v * v; }
    #pragma unroll
    for (int off = 16; off; off >>= 1) ss += __shfl_xor_sync(~0u, ss, off);
    float inv = rsqrtf(ss * (1.f / D_MODEL) + EPS);
    for (int i = lane; i < D_MODEL; i += 32)
        o[(size_t)tok * D_MODEL + i] = f[(size_t)tok * D_MODEL + i] + xr[i] * inv * w[i];
}

// -------- conv(k=4, causal) + silu: register window over 64-token tiles --------
#define CLT 64
__global__ void conv_silu_kernel(const bf16* __restrict__ xz, const float* __restrict__ cw,
                                 const float* __restrict__ cb, bf16* __restrict__ xc) {
    int d = blockIdx.x * 128 + threadIdx.x;
    if (d >= D_INNER) return;
    int l0 = blockIdx.y * CLT, b = blockIdx.z;
    float w0 = cw[d * 4 + 0], w1 = cw[d * 4 + 1], w2 = cw[d * 4 + 2], w3 = cw[d * 4 + 3];
    float bb = cb[d];
    size_t row = (size_t)b * L_SEQ + l0;
    const bf16* src = xz + row * TWO_DI + d;
    bf16* dst = xc + row * KI + d;
    float x0, x1, x2;
    if (l0 == 0) { x0 = x1 = x2 = 0.f; }
    else {
        x0 = __bfloat162float(src[-3 * TWO_DI]);
        x1 = __bfloat162float(src[-2 * TWO_DI]);
        x2 = __bfloat162float(src[-1 * TWO_DI]);
    }
    #pragma unroll 4
    for (int i = 0; i < CLT; ++i) {
        float x3 = __bfloat162float(src[(size_t)i * TWO_DI]);
        float acc = bb + w0 * x0 + w1 * x1 + w2 * x2 + w3 * x3;
        dst[(size_t)i * KI] = __float2bfloat16(acc / (1.f + __expf(-acc)));
        x0 = x1; x1 = x2; x2 = x3;
    }
}

// -------- chunked selective scan (single serial pass + parallel fixup) ----
__device__ __forceinline__ float softplus_f(float a) {
    return (a > 15.f) ? a : log1pf(__expf(a));
}
__device__ __forceinline__ bool a_is_arange(const float* Av) {
    bool ok = Av[0] < 0.f;
    #pragma unroll
    for (int s = 1; s < 16; ++s)
        ok = ok && (fabsf(Av[s] - (float)(s + 1) * Av[0]) <= 1e-4f * fabsf(Av[s]));
    return ok;
}

// scanA: serial pass with h0=0. Emits ylocal, cumdt, chunk summary Lc + sum(dt).
__global__ __launch_bounds__(128) void scanA_kernel(
    const bf16* __restrict__ u, const float* __restrict__ xdbl,
    const float* __restrict__ A_log, const float* __restrict__ dtw,
    const float* __restrict__ dtb, float* __restrict__ Lc, float* __restrict__ sdtc,
    bf16* __restrict__ yloc, float* __restrict__ cum) {
    __shared__ float sDL[SCT][18];
    __shared__ float sB[SCT][16];
    __shared__ float sC[SCT][16];
    __shared__ bf16 s_u[SCT][128];
    int b = blockIdx.z, c = blockIdx.y, d0 = blockIdx.x * 128;
    int tid = threadIdx.x;
    int d = d0 + tid;
    bool act = d < D_INNER;
    int dc = act ? d : (D_INNER - 1);
    size_t rb = (size_t)b * L_SEQ + (size_t)c * SCT;
    float Av[16];
    #pragma unroll
    for (int s = 0; s < 16; s += 4) {
        float4 al = *(const float4*)(A_log + (size_t)dc * 16 + s);
        Av[s + 0] = -__expf(al.x); Av[s + 1] = -__expf(al.y);
        Av[s + 2] = -__expf(al.z); Av[s + 3] = -__expf(al.w);
    }
    const bool fast = a_is_arange(Av);
    const float Av0 = Av[0];
    float wv[DT_RANK];
    #pragma unroll
    for (int r = 0; r < DT_RANK; ++r) wv[r] = dtw[(size_t)dc * DT_RANK + r];
    float bias = dtb[dc];
    for (int i = tid; i < SCT * 16; i += 128) {
        int t = i >> 4, s = i & 15;
        const float* g = xdbl + (rb + t) * XW + DT_RANK;
        sB[t][s] = g[s];
        sC[t][s] = g[16 + s];
    }
    for (int i = tid; i < SCT * DT_RANK; i += 128) {
        int t = i / DT_RANK, r = i - t * DT_RANK;
        sDL[t][r] = xdbl[(rb + t) * XW + r];
    }
    for (int q = tid; q < SCT * 64; q += 128) {
        int tt = q >> 6, dp = (q & 63) * 2;
        *(uint32_t*)&s_u[tt][dp] = *(const uint32_t*)(u + (rb + tt) * KI + d0 + dp);
    }
    __syncthreads();
    float h[16];
    #pragma unroll
    for (int s = 0; s < 16; ++s) h[s] = 0.f;
    float sd = 0.f;
    for (int t = 0; t < SCT; ++t) {
        float dta = bias;
        const float* dl = sDL[t];
        #pragma unroll
        for (int r = 0; r < DT_RANK; ++r) dta = fmaf(dl[r], wv[r], dta);
        float dtv = softplus_f(dta);
        float uv = __bfloat162float(s_u[t][tid]);
        float e = dtv * uv;
        sd += dtv;
        const float4* pB = (const float4*)sB[t];
        const float4* pC = (const float4*)sC[t];
        float y = 0.f;
        if (fast) {
            float q = __expf(dtv * Av0);
            float p = 1.f;
            #pragma unroll
            for (int s4 = 0; s4 < 4; ++s4) {
                float4 Bv = pB[s4];
                float4 Cv = pC[s4];
                p *= q; h[s4*4+0] = fmaf(p, h[s4*4+0], e * Bv.x);
                p *= q; h[s4*4+1] = fmaf(p, h[s4*4+1], e * Bv.y);
                p *= q; h[s4*4+2] = fmaf(p, h[s4*4+2], e * Bv.z);
                p *= q; h[s4*4+3] = fmaf(p, h[s4*4+3], e * Bv.w);
                y += h[s4*4+0] * Cv.x + h[s4*4+1] * Cv.y
                   + h[s4*4+2] * Cv.z + h[s4*4+3] * Cv.w;
            }
        } else {
            #pragma unroll
            for (int s4 = 0; s4 < 4; ++s4) {
                float4 Bv = pB[s4];
                float4 Cv = pC[s4];
                h[s4*4+0] = fmaf(__expf(dtv * Av[s4*4+0]), h[s4*4+0], e * Bv.x);
                h[s4*4+1] = fmaf(__expf(dtv * Av[s4*4+1]), h[s4*4+1], e * Bv.y);
                h[s4*4+2] = fmaf(__expf(dtv * Av[s4*4+2]), h[s4*4+2], e * Bv.z);
                h[s4*4+3] = fmaf(__expf(dtv * Av[s4*4+3]), h[s4*4+3], e * Bv.w);
                y += h[s4*4+0] * Cv.x + h[s4*4+1] * Cv.y
                   + h[s4*4+2] * Cv.z + h[s4*4+3] * Cv.w;
            }
        }
        if (act) {
            yloc[(rb + t) * KI + d] = __float2bfloat16(y);
            cum[(rb + t) * KI + d] = sd;
        }
    }
    if (act) {
        size_t o = ((size_t)b * NCHK + c) * D_INNER + d;
        float4* pL = (float4*)(Lc + o * 16);
        #pragma unroll
        for (int s4 = 0; s4 < 4; ++s4)
            pL[s4] = make_float4(h[s4*4+0], h[s4*4+1], h[s4*4+2], h[s4*4+3]);
        sdtc[o] = sd;
    }
}

// scan2: stitch chunk summaries -> initial state per chunk
__global__ void scan2_kernel(const float* __restrict__ Lc, const float* __restrict__ sdtc,
                             const float* __restrict__ A_log, float* __restrict__ H0) {
    int idx = blockIdx.x * 128 + threadIdx.x;
    if (idx >= B_SZ * D_INNER * D_STATE) return;
    int s = idx & 15, rest = idx >> 4;
    int d = rest % D_INNER, b = rest / D_INNER;
    float Av = -__expf(A_log[(size_t)d * 16 + s]);
    float h = 0.f;
    #pragma unroll 8
    for (int c = 0; c < NCHK; ++c) {
        size_t o = (((size_t)b * NCHK + c) * D_INNER + d);
        H0[o * 16 + s] = h;
        h = __expf(Av * sdtc[o]) * h + Lc[o * 16 + s];
    }
}

// scanC: parallel fixup: y = ylocal + C·(P(cumdt)·H0); then +u*D and gate.
__global__ __launch_bounds__(128) void scanC_kernel(
    const bf16* __restrict__ u, const float* __restrict__ xdbl,
    const bf16* __restrict__ xz, const float* __restrict__ A_log,
    const float* __restrict__ Dp, const float* __restrict__ H0,
    const float* __restrict__ cum, bf16* __restrict__ y2) {
    __shared__ float sC[SCT][16];
    int b = blockIdx.z, c = blockIdx.y, d0 = blockIdx.x * 128;
    int tid = threadIdx.x;
    int d = d0 + tid;
    bool act = d < D_INNER;
    int dc = act ? d : (D_INNER - 1);
    size_t rb = (size_t)b * L_SEQ + (size_t)c * SCT;
    float Av[16];
    #pragma unroll
    for (int s = 0; s < 16; s += 4) {
        float4 al = *(const float4*)(A_log + (size_t)dc * 16 + s);
        Av[s + 0] = -__expf(al.x); Av[s + 1] = -__expf(al.y);
        Av[s + 2] = -__expf(al.z); Av[s + 3] = -__expf(al.w);
    }
    const bool fast = a_is_arange(Av);
    const float Av0 = Av[0];
    float Dv = Dp[dc];
    float h0[16];
    {
        size_t o = ((size_t)b * NCHK + c) * D_INNER + dc;
        const float4* pH = (const float4*)(H0 + o * 16);
        #pragma unroll
        for (int s4 = 0; s4 < 4; ++s4) {
            float4 hv = pH[s4];
            h0[s4*4+0] = hv.x; h0[s4*4+1] = hv.y; h0[s4*4+2] = hv.z; h0[s4*4+3] = hv.w;
        }
    }
    for (int i = tid; i < SCT * 16; i += 128) {
        int t = i >> 4, s = i & 15;
        sC[t][s] = xdbl[(rb + t) * XW + DT_RANK + 16 + s];
    }
    __syncthreads();
    for (int t = 0; t < SCT; ++t) {
        size_t gi = (rb + t) * KI + (size_t)dc;
        float cu = cum[gi];
        float yl = __bfloat162float(y2[gi]);
        float uv = __bfloat162float(u[gi]);
        float z = __bfloat162float(xz[(rb + t) * TWO_DI + D_INNER + dc]);
        const float* Cv = sC[t];
        float corr = 0.f;
        if (fast) {
            float q = __expf(cu * Av0);
            float p = 1.f;
            #pragma unroll
            for (int s = 0; s < 16; ++s) {
                p *= q;
                corr = fmaf(p * h0[s], Cv[s], corr);
            }
        } else {
            #pragma unroll
            for (int s = 0; s < 16; ++s)
                corr = fmaf(__expf(cu * Av[s]) * h0[s], Cv[s], corr);
        }
        if (act) {
            float y = yl + corr;
            y2[gi] = __float2bfloat16((y + uv * Dv) * (z / (1.f + __expf(-z))));
        }
    }
}

// -------- weight packing --------
__global__ void pack1_kernel(const float* __restrict__ ipw, bf16* __restrict__ win) {
    int i = blockIdx.x * 256 + threadIdx.x;
    int total = N_LAYERS * 1032 * 258;
    if (i >= total) return;
    int k = i % 258, nr = i / 258, n = nr % 1032, l = nr / 1032;
    win[((size_t)l * WIN_R + n) * KM + k] = __float2bfloat16(ipw[i]);
}
__global__ void pack2_kernel(const float* __restrict__ opw, const float* __restrict__ xpw,
                             bf16* __restrict__ wout, bf16* __restrict__ wxp) {
    int i = blockIdx.x * 256 + threadIdx.x;
    const int OUT_T = N_LAYERS * 258 * 516, XP_T = N_LAYERS * 49 * 516;
    if (i < OUT_T) {
        int k = i % 516, nr = i / 516, n = nr % 258, l = nr / 258;
        wout[((size_t)l * WOUT_R + n) * KI + k] = __float2bfloat16(opw[i]);
    } else if (i < OUT_T + XP_T) {
        int j = i - OUT_T;
        int k = j % 516, nr = j / 516, n = nr % 49, l = nr / 49;
        wxp[((size_t)l * WXP_R + n) * KI + k] = __float2bfloat16(xpw[j]);
    }
}

// -------- host --------
extern "C" void kernel_launch(void* const* d_in, const int* in_sizes, int n_in,
                              void* d_out, int out_size) {
    const float* fuse  = (const float*)d_in[0];
    const float* nwv   = (const float*)d_in[1];
    const float* ipw   = (const float*)d_in[2];
    const float* cwv   = (const float*)d_in[3];
    const float* cbv   = (const float*)d_in[4];
    const float* xpw   = (const float*)d_in[5];
    const float* dtwv  = (const float*)d_in[6];
    const float* dtbv  = (const float*)d_in[7];
    const float* Alv   = (const float*)d_in[8];
    const float* Dpv   = (const float*)d_in[9];
    const float* opw   = (const float*)d_in[10];
    const float* fw    = (const float*)d_in[11];
    float* out = (float*)d_out;

    float *p_x, *p_xdbl, *p_L, *p_H0, *p_sdt, *p_cum;
    bf16 *p_xn, *p_xz, *p_xc, *p_y2, *p_win, *p_wout, *p_wxp;
    cudaGetSymbolAddress((void**)&p_x, g_x);
    cudaGetSymbolAddress((void**)&p_xn, g_xn);
    cudaGetSymbolAddress((void**)&p_xz, g_xz);
    cudaGetSymbolAddress((void**)&p_xc, g_xc);
    cudaGetSymbolAddress((void**)&p_xdbl, g_xdbl);
    cudaGetSymbolAddress((void**)&p_y2, g_y2);
    cudaGetSymbolAddress((void**)&p_cum, g_cum);
    cudaGetSymbolAddress((void**)&p_win, g_win);
    cudaGetSymbolAddress((void**)&p_wout, g_wout);
    cudaGetSymbolAddress((void**)&p_wxp, g_wxp);
    cudaGetSymbolAddress((void**)&p_L, g_L);
    cudaGetSymbolAddress((void**)&p_H0, g_H0);
    cudaGetSymbolAddress((void**)&p_sdt, g_sdt);

    // smem sizes: NSTAGE * (BM+BN) * AW * 4 bytes
    const int SM_BIG = 4 * (64 + 128) * AW * 4;   // 61440 (needs opt-in)
    const int SM_XP  = 3 * (32 + 64) * AW * 4;    // 23040
    cudaFuncSetAttribute((const void*)gemm_bf16<64, 128, 2, 4>,
                         cudaFuncAttributeMaxDynamicSharedMemorySize, SM_BIG);
    cudaFuncSetAttribute((const void*)gemm_bf16<64, 128, 1, 4>,
                         cudaFuncAttributeMaxDynamicSharedMemorySize, SM_BIG);

    pack1_kernel<<<(N_LAYERS * 1032 * 258 + 255) / 256, 256>>>(ipw, p_win);
    {
        int tot = N_LAYERS * 258 * 516 + N_LAYERS * 49 * 516;
        pack2_kernel<<<(tot + 255) / 256, 256>>>(opw, xpw, p_wout, p_wxp);
    }
    cudaMemcpyAsync(p_x, fuse, (size_t)NTOK * D_MODEL * sizeof(float),
                    cudaMemcpyDeviceToDevice);

    for (int l = 0; l < N_LAYERS; ++l) {
        const float* Al = Alv + (size_t)l * D_INNER * 16;
        const float* dtw = dtwv + (size_t)l * D_INNER * DT_RANK;
        const float* dtb = dtbv + (size_t)l * D_INNER;
        rmsnorm_kernel<<<NTOK / 8, 256>>>(p_x, nwv + (size_t)l * D_MODEL, p_xn, KM);
        gemm_bf16<64, 128, 2, 4><<<dim3(9, 128), 256, SM_BIG>>>(
            p_xn, p_win + (size_t)l * WIN_R * KM, p_xz, TWO_DI, KM, KM, TWO_DI);
        conv_silu_kernel<<<dim3(5, L_SEQ / CLT, B_SZ), 128>>>(
            p_xz, cwv + (size_t)l * D_INNER * 4, cbv + (size_t)l * D_INNER, p_xc);
        gemm_bf16<32, 64, 0, 3><<<dim3(1, 256), 256, SM_XP>>>(
            p_xc, p_wxp + (size_t)l * WXP_R * KI, p_xdbl, 49, KI, KI, XW);
        scanA_kernel<<<dim3(5, NCHK, B_SZ), 128>>>(
            p_xc, p_xdbl, Al, dtw, dtb, p_L, p_sdt, p_y2, p_cum);
        scan2_kernel<<<(B_SZ * D_INNER * D_STATE + 127) / 128, 128>>>(
            p_L, p_sdt, Al, p_H0);
        scanC_kernel<<<dim3(5, NCHK, B_SZ), 128>>>(
            p_xc, p_xdbl, p_xz, Al, Dpv + (size_t)l * D_INNER, p_H0, p_cum, p_y2);
        gemm_bf16<64, 128, 1, 4><<<dim3(3, 128), 256, SM_BIG>>>(
            p_y2, p_wout + (size_t)l * WOUT_R * KI, p_x, D_MODEL, KI, KI, D_MODEL);
    }
    final_kernel<<<NTOK / 8, 256>>>(fuse, p_x, fw, out);
    (void)in_sizes; (void)n_in; (void)out_size;
}

// round 12
// speedup vs baseline: 3.7468x; 1.0179x over previous
#include <cuda_runtime.h>
#include <cuda_bf16.h>
#include <math.h>
#include <stdint.h>

#define B_SZ 4
#define L_SEQ 2048
#define D_MODEL 258
#define N_LAYERS 4
#define D_STATE 16
#define D_INNER 516
#define DT_RANK 17
#define TWO_DI 1032
#define XW 56            // padded xdbl stride (49 real cols)
#define NTOK 8192
#define EPS 1e-5f
#define KM 288           // 258 padded to 32-chunks
#define KI 544           // 516 padded
#define WIN_R 1152       // 9 * 128
#define WOUT_R 384       // 3 * 128
#define WXP_R 64
#define NCHK 64          // scan chunks
#define SCT 32           // tokens per scan chunk

typedef __nv_bfloat16 bf16;

// -------- device scratch (zero-init; +pad for vectorized edge reads) --------
__device__ __align__(256) float g_x[NTOK * D_MODEL];
__device__ __align__(256) bf16  g_xn[NTOK * KM];
__device__ __align__(256) bf16  g_xz[NTOK * TWO_DI + 256];
__device__ __align__(256) bf16  g_xc[NTOK * KI + 256];
__device__ __align__(256) float g_xdbl[NTOK * XW];
__device__ __align__(256) bf16  g_y2[NTOK * KI + 256];
__device__ __align__(256) float g_cum[NTOK * KI + 256];
__device__ __align__(256) bf16  g_win[N_LAYERS * WIN_R * KM];
__device__ __align__(256) bf16  g_wout[N_LAYERS * WOUT_R * KI];
__device__ __align__(256) bf16  g_wxp[N_LAYERS * WXP_R * KI];
__device__ __align__(256) float g_L[B_SZ * NCHK * D_INNER * D_STATE];
__device__ __align__(256) float g_H0[B_SZ * NCHK * D_INNER * D_STATE];
__device__ __align__(256) float g_sdt[B_SZ * NCHK * D_INNER];

// -------- helpers --------
__device__ __forceinline__ uint32_t smem_u32(const void* p) {
    uint32_t a;
    asm("{ .reg .u64 t; cvta.to.shared.u64 t, %1; cvt.u32.u64 %0, t; }" : "=r"(a) : "l"(p));
    return a;
}
__device__ __forceinline__ void cp_async16(uint32_t dst, const void* src) {
    asm volatile("cp.async.cg.shared.global [%0], [%1], 16;" :: "r"(dst), "l"(src));
}
#define CP_COMMIT() asm volatile("cp.async.commit_group;" ::: "memory")

__device__ __forceinline__ void mma_bf16(float* d, const uint32_t* a, const uint32_t* b) {
    asm volatile(
        "mma.sync.aligned.m16n8k16.row.col.f32.bf16.bf16.f32 "
        "{%0,%1,%2,%3},{%4,%5,%6,%7},{%8,%9},{%0,%1,%2,%3};"
        : "+f"(d[0]), "+f"(d[1]), "+f"(d[2]), "+f"(d[3])
        : "r"(a[0]), "r"(a[1]), "r"(a[2]), "r"(a[3]), "r"(b[0]), "r"(b[1]));
}
__device__ __forceinline__ void ldsm_x4(uint32_t* r, uint32_t addr) {
    asm volatile("ldmatrix.sync.aligned.m8n8.x4.shared.b16 {%0,%1,%2,%3}, [%4];"
        : "=r"(r[0]), "=r"(r[1]), "=r"(r[2]), "=r"(r[3]) : "r"(addr));
}
__device__ __forceinline__ void ldsm_x2(uint32_t* r, uint32_t addr) {
    asm volatile("ldmatrix.sync.aligned.m8n8.x2.shared.b16 {%0,%1}, [%2];"
        : "=r"(r[0]), "=r"(r[1]) : "r"(addr));
}

// -------- bf16 mma GEMM: C[8192,N] = A[8192,K]bf16 @ W[N,K]bf16^T --------
#define AW 20            // smem row stride in words (40 bf16) — LDSM conflict-free
template <int BM, int BN, int OUTMODE, int NSTAGE>
__global__ __launch_bounds__(256) void gemm_bf16(
    const bf16* __restrict__ A, const bf16* __restrict__ W,
    void* __restrict__ Cv, int N_store, int K, int lda, int ldc) {
    constexpr int MW = BM / 32;
    constexpr int NW = 8 / MW;
    constexpr int WN = BN / NW;
    constexpr int NT = WN / 8;
    constexpr int ASTG = BM * AW, BSTG = BN * AW, STG = ASTG + BSTG;
    extern __shared__ uint32_t sm[];
    const int tid = threadIdx.x, wid = tid >> 5, lane = tid & 31;
    const int warpM = wid % MW, warpN = wid / MW;
    const int quad = lane >> 2, qk = lane & 3;
    const int bm = blockIdx.y * BM, bn = blockIdx.x * BN;
    float acc[2][NT][4];
    #pragma unroll
    for (int i = 0; i < 2; ++i)
        #pragma unroll
        for (int j = 0; j < NT; ++j)
            #pragma unroll
            for (int k = 0; k < 4; ++k) acc[i][j][k] = 0.f;

    const bf16* Ab = A + (size_t)bm * lda;
    const bf16* Wb = W + (size_t)bn * K;
    const int nch = K >> 5;
    const uint32_t sm_u = smem_u32(sm);
    const int l8 = lane & 7, jm = lane >> 3;

    const uint32_t aLM = sm_u +
        (uint32_t)(((warpM * 32 + ((jm & 1) << 3) + l8) * AW + ((jm >> 1) << 2)) * 4);
    const uint32_t bLM4 = sm_u + ASTG * 4 +
        (uint32_t)(((warpN * WN + ((jm >> 1) << 3) + l8) * AW + ((jm & 1) << 2)) * 4);
    const uint32_t bLM2 = sm_u + ASTG * 4 +
        (uint32_t)(((warpN * WN + l8) * AW + (((lane >> 3) & 1) << 2)) * 4);

    auto load_chunk = [&](int c, int st) {
        const bf16* Ac = Ab + c * 32;
        #pragma unroll
        for (int fi = tid; fi < BM * 4; fi += 256) {
            int r = fi >> 2, sg = fi & 3;
            cp_async16(sm_u + (uint32_t)(st * STG + r * AW + sg * 4) * 4,
                       Ac + (size_t)r * lda + sg * 8);
        }
        const bf16* Wc = Wb + c * 32;
        #pragma unroll
        for (int fi = tid; fi < BN * 4; fi += 256) {
            int r = fi >> 2, sg = fi & 3;
            cp_async16(sm_u + (uint32_t)(st * STG + ASTG + r * AW + sg * 4) * 4,
                       Wc + (size_t)r * K + sg * 8);
        }
    };

    #pragma unroll
    for (int p = 0; p < NSTAGE - 1; ++p) {
        if (p < nch) load_chunk(p, p);
        CP_COMMIT();
    }

    for (int c = 0; c < nch; ++c) {
        asm volatile("cp.async.wait_group %0;" :: "n"(NSTAGE - 2) : "memory");
        __syncthreads();
        int nx = c + NSTAGE - 1;
        if (nx < nch) load_chunk(nx, nx % NSTAGE);
        CP_COMMIT();
        const uint32_t stOff = (uint32_t)((c % NSTAGE) * STG * 4);
        #pragma unroll
        for (int ks = 0; ks < 2; ++ks) {
            uint32_t a[2][4], b[NT][2];
            #pragma unroll
            for (int mt = 0; mt < 2; ++mt)
                ldsm_x4(a[mt], aLM + stOff + (uint32_t)(mt * 16 * AW * 4 + ks * 32));
            if (NT == 1) {
                ldsm_x2(b[0], bLM2 + stOff + (uint32_t)(ks * 32));
            } else {
                #pragma unroll
                for (int p = 0; p < NT / 2; ++p) {
                    uint32_t t4[4];
                    ldsm_x4(t4, bLM4 + stOff + (uint32_t)(p * 16 * AW * 4 + ks * 32));
                    b[2*p][0] = t4[0]; b[2*p][1] = t4[1];
                    b[2*p+1][0] = t4[2]; b[2*p+1][1] = t4[3];
                }
            }
            #pragma unroll
            for (int mt = 0; mt < 2; ++mt)
                #pragma unroll
                for (int nt = 0; nt < NT; ++nt)
                    mma_bf16(acc[mt][nt], a[mt], b[nt]);
        }
    }
    __syncthreads();

    #pragma unroll
    for (int mt = 0; mt < 2; ++mt) {
        int r0 = bm + warpM * 32 + mt * 16 + quad;
        #pragma unroll
        for (int nt = 0; nt < NT; ++nt) {
            int gc = bn + warpN * WN + nt * 8 + qk * 2;
            #pragma unroll
            for (int half = 0; half < 2; ++half) {
                int row = r0 + half * 8;
                float v0 = acc[mt][nt][half * 2 + 0];
                float v1 = acc[mt][nt][half * 2 + 1];
                size_t gi = (size_t)row * ldc + gc;
                if (OUTMODE == 2) {
                    bf16* C = (bf16*)Cv;
                    if (gc < N_store) C[gi] = __float2bfloat16(v0);
                    if (gc + 1 < N_store) C[gi + 1] = __float2bfloat16(v1);
                } else {
                    float* C = (float*)Cv;
                    if (gc < N_store) {
                        if (OUTMODE == 1) v0 += C[gi];
                        C[gi] = v0;
                    }
                    if (gc + 1 < N_store) {
                        if (OUTMODE == 1) v1 += C[gi + 1];
                        C[gi + 1] = v1;
                    }
                }
            }
        }
    }
}

// -------- rmsnorm: warp per token, bf16 out --------
__global__ void rmsnorm_kernel(const float* __restrict__ x, const float* __restrict__ w,
                               bf16* __restrict__ o, int ldo) {
    int tok = (blockIdx.x * blockDim.x + threadIdx.x) >> 5;
    int lane = threadIdx.x & 31;
    if (tok >= NTOK) return;
    const float* xr = x + (size_t)tok * D_MODEL;
    float ss = 0.f;
    for (int i = lane; i < D_MODEL; i += 32) { float v = xr[i]; ss += v * v; }
    #pragma unroll
    for (int off = 16; off; off >>= 1) ss += __shfl_xor_sync(~0u, ss, off);
    float inv = rsqrtf(ss * (1.f / D_MODEL) + EPS);
    for (int i = lane; i < D_MODEL; i += 32)
        o[(size_t)tok * ldo + i] = __float2bfloat16(xr[i] * inv * w[i]);
}

__global__ void final_kernel(const float* __restrict__ f, const float* __restrict__ x,
                             const float* __restrict__ w, float* __restrict__ o) {
    int tok = (blockIdx.x * blockDim.x + threadIdx.x) >> 5;
    int lane = threadIdx.x & 31;
    if (tok >= NTOK) return;
    const float* xr = x + (size_t)tok * D_MODEL;
    float ss = 0.f;
    for (int i = lane; i < D_MODEL; i += 32) { float v = xr[i]; ss += v * v; }
    #pragma unroll
    for (int off = 16; off; off >>= 1) ss += __shfl_xor_sync(~0u, ss, off);
    float inv = rsqrtf(ss * (1.f / D_MODEL) + EPS);
    for (int i = lane; i < D_MODEL; i += 32)
        o[(size_t)tok * D_MODEL + i] = f[(size_t)tok * D_MODEL + i] + xr[i] * inv * w[i];
}

// -------- conv(k=4, causal) + silu: register window over 64-token tiles --------
#define CLT 64
__global__ void conv_silu_kernel(const bf16* __restrict__ xz, const float* __restrict__ cw,
                                 const float* __restrict__ cb, bf16* __restrict__ xc) {
    int d = blockIdx.x * 128 + threadIdx.x;
    if (d >= D_INNER) return;
    int l0 = blockIdx.y * CLT, b = blockIdx.z;
    float w0 = cw[d * 4 + 0], w1 = cw[d * 4 + 1], w2 = cw[d * 4 + 2], w3 = cw[d * 4 + 3];
    float bb = cb[d];
    size_t row = (size_t)b * L_SEQ + l0;
    const bf16* src = xz + row * TWO_DI + d;
    bf16* dst = xc + row * KI + d;
    float x0, x1, x2;
    if (l0 == 0) { x0 = x1 = x2 = 0.f; }
    else {
        x0 = __bfloat162float(src[-3 * TWO_DI]);
        x1 = __bfloat162float(src[-2 * TWO_DI]);
        x2 = __bfloat162float(src[-1 * TWO_DI]);
    }
    #pragma unroll 4
    for (int i = 0; i < CLT; ++i) {
        float x3 = __bfloat162float(src[(size_t)i * TWO_DI]);
        float acc = bb + w0 * x0 + w1 * x1 + w2 * x2 + w3 * x3;
        dst[(size_t)i * KI] = __float2bfloat16(acc / (1.f + __expf(-acc)));
        x0 = x1; x1 = x2; x2 = x3;
    }
}

// -------- chunked selective scan (single serial pass + parallel fixup) ----
__device__ __forceinline__ float softplus_f(float a) {
    return (a > 15.f) ? a : log1pf(__expf(a));
}
__device__ __forceinline__ bool a_is_arange(const float* Av) {
    bool ok = Av[0] < 0.f;
    #pragma unroll
    for (int s = 1; s < 16; ++s)
        ok = ok && (fabsf(Av[s] - (float)(s + 1) * Av[0]) <= 1e-4f * fabsf(Av[s]));
    return ok;
}

// scanA: serial pass with h0=0. Emits ylocal, cumdt, chunk summary Lc + sum(dt).
__global__ __launch_bounds__(128) void scanA_kernel(
    const bf16* __restrict__ u, const float* __restrict__ xdbl,
    const float* __restrict__ A_log, const float* __restrict__ dtw,
    const float* __restrict__ dtb, float* __restrict__ Lc, float* __restrict__ sdtc,
    bf16* __restrict__ yloc, float* __restrict__ cum) {
    __shared__ float sDL[SCT][18];
    __shared__ float sB[SCT][16];
    __shared__ float sC[SCT][16];
    __shared__ bf16 s_u[SCT][128];
    int b = blockIdx.z, c = blockIdx.y, d0 = blockIdx.x * 128;
    int tid = threadIdx.x;
    int d = d0 + tid;
    bool act = d < D_INNER;
    int dc = act ? d : (D_INNER - 1);
    size_t rb = (size_t)b * L_SEQ + (size_t)c * SCT;
    float Av[16];
    #pragma unroll
    for (int s = 0; s < 16; s += 4) {
        float4 al = *(const float4*)(A_log + (size_t)dc * 16 + s);
        Av[s + 0] = -__expf(al.x); Av[s + 1] = -__expf(al.y);
        Av[s + 2] = -__expf(al.z); Av[s + 3] = -__expf(al.w);
    }
    const bool fast = a_is_arange(Av);
    const float Av0 = Av[0];
    float wv[DT_RANK];
    #pragma unroll
    for (int r = 0; r < DT_RANK; ++r) wv[r] = dtw[(size_t)dc * DT_RANK + r];
    float bias = dtb[dc];
    for (int i = tid; i < SCT * 16; i += 128) {
        int t = i >> 4, s = i & 15;
        const float* g = xdbl + (rb + t) * XW + DT_RANK;
        sB[t][s] = g[s];
        sC[t][s] = g[16 + s];
    }
    for (int i = tid; i < SCT * DT_RANK; i += 128) {
        int t = i / DT_RANK, r = i - t * DT_RANK;
        sDL[t][r] = xdbl[(rb + t) * XW + r];
    }
    for (int q = tid; q < SCT * 64; q += 128) {
        int tt = q >> 6, dp = (q & 63) * 2;
        *(uint32_t*)&s_u[tt][dp] = *(const uint32_t*)(u + (rb + tt) * KI + d0 + dp);
    }
    __syncthreads();
    float h[16];
    #pragma unroll
    for (int s = 0; s < 16; ++s) h[s] = 0.f;
    float sd = 0.f;
    for (int t = 0; t < SCT; ++t) {
        float dta = bias;
        const float* dl = sDL[t];
        #pragma unroll
        for (int r = 0; r < DT_RANK; ++r) dta = fmaf(dl[r], wv[r], dta);
        float dtv = softplus_f(dta);
        float uv = __bfloat162float(s_u[t][tid]);
        float e = dtv * uv;
        sd += dtv;
        const float4* pB = (const float4*)sB[t];
        const float4* pC = (const float4*)sC[t];
        float y = 0.f;
        if (fast) {
            float q = __expf(dtv * Av0);
            float p = 1.f;
            #pragma unroll
            for (int s4 = 0; s4 < 4; ++s4) {
                float4 Bv = pB[s4];
                float4 Cv = pC[s4];
                p *= q; h[s4*4+0] = fmaf(p, h[s4*4+0], e * Bv.x);
                p *= q; h[s4*4+1] = fmaf(p, h[s4*4+1], e * Bv.y);
                p *= q; h[s4*4+2] = fmaf(p, h[s4*4+2], e * Bv.z);
                p *= q; h[s4*4+3] = fmaf(p, h[s4*4+3], e * Bv.w);
                y += h[s4*4+0] * Cv.x + h[s4*4+1] * Cv.y
                   + h[s4*4+2] * Cv.z + h[s4*4+3] * Cv.w;
            }
        } else {
            #pragma unroll
            for (int s4 = 0; s4 < 4; ++s4) {
                float4 Bv = pB[s4];
                float4 Cv = pC[s4];
                h[s4*4+0] = fmaf(__expf(dtv * Av[s4*4+0]), h[s4*4+0], e * Bv.x);
                h[s4*4+1] = fmaf(__expf(dtv * Av[s4*4+1]), h[s4*4+1], e * Bv.y);
                h[s4*4+2] = fmaf(__expf(dtv * Av[s4*4+2]), h[s4*4+2], e * Bv.z);
                h[s4*4+3] = fmaf(__expf(dtv * Av[s4*4+3]), h[s4*4+3], e * Bv.w);
                y += h[s4*4+0] * Cv.x + h[s4*4+1] * Cv.y
                   + h[s4*4+2] * Cv.z + h[s4*4+3] * Cv.w;
            }
        }
        if (act) {
            yloc[(rb + t) * KI + d] = __float2bfloat16(y);
            cum[(rb + t) * KI + d] = sd;
        }
    }
    if (act) {
        size_t o = ((size_t)b * NCHK + c) * D_INNER + d;
        float4* pL = (float4*)(Lc + o * 16);
        #pragma unroll
        for (int s4 = 0; s4 < 4; ++s4)
            pL[s4] = make_float4(h[s4*4+0], h[s4*4+1], h[s4*4+2], h[s4*4+3]);
        sdtc[o] = sd;
    }
}

// scan2: stitch chunk summaries -> initial state per chunk
__global__ void scan2_kernel(const float* __restrict__ Lc, const float* __restrict__ sdtc,
                             const float* __restrict__ A_log, float* __restrict__ H0) {
    int idx = blockIdx.x * 128 + threadIdx.x;
    if (idx >= B_SZ * D_INNER * D_STATE) return;
    int s = idx & 15, rest = idx >> 4;
    int d = rest % D_INNER, b = rest / D_INNER;
    float Av = -__expf(A_log[(size_t)d * 16 + s]);
    float h = 0.f;
    #pragma unroll 8
    for (int c = 0; c < NCHK; ++c) {
        size_t o = (((size_t)b * NCHK + c) * D_INNER + d);
        H0[o * 16 + s] = h;
        h = __expf(Av * sdtc[o]) * h + Lc[o * 16 + s];
    }
}

// scanC: parallel fixup: y = ylocal + C·(P(cumdt)·H0); then +u*D and gate.
__global__ __launch_bounds__(128) void scanC_kernel(
    const bf16* __restrict__ u, const float* __restrict__ xdbl,
    const bf16* __restrict__ xz, const float* __restrict__ A_log,
    const float* __restrict__ Dp, const float* __restrict__ H0,
    const float* __restrict__ cum, bf16* __restrict__ y2) {
    __shared__ float sC[SCT][16];
    int b = blockIdx.z, c = blockIdx.y, d0 = blockIdx.x * 128;
    int tid = threadIdx.x;
    int d = d0 + tid;
    bool act = d < D_INNER;
    int dc = act ? d : (D_INNER - 1);
    size_t rb = (size_t)b * L_SEQ + (size_t)c * SCT;
    float Av[16];
    #pragma unroll
    for (int s = 0; s < 16; s += 4) {
        float4 al = *(const float4*)(A_log + (size_t)dc * 16 + s);
        Av[s + 0] = -__expf(al.x); Av[s + 1] = -__expf(al.y);
        Av[s + 2] = -__expf(al.z); Av[s + 3] = -__expf(al.w);
    }
    const bool fast = a_is_arange(Av);
    const float Av0 = Av[0];
    float Dv = Dp[dc];
    float h0[16];
    {
        size_t o = ((size_t)b * NCHK + c) * D_INNER + dc;
        const float4* pH = (const float4*)(H0 + o * 16);
        #pragma unroll
        for (int s4 = 0; s4 < 4; ++s4) {
            float4 hv = pH[s4];
            h0[s4*4+0] = hv.x; h0[s4*4+1] = hv.y; h0[s4*4+2] = hv.z; h0[s4*4+3] = hv.w;
        }
    }
    for (int i = tid; i < SCT * 16; i += 128) {
        int t = i >> 4, s = i & 15;
        sC[t][s] = xdbl[(rb + t) * XW + DT_RANK + 16 + s];
    }
    __syncthreads();
    for (int t = 0; t < SCT; ++t) {
        size_t gi = (rb + t) * KI + (size_t)dc;
        float cu = cum[gi];
        float yl = __bfloat162float(y2[gi]);
        float uv = __bfloat162float(u[gi]);
        float z = __bfloat162float(xz[(rb + t) * TWO_DI + D_INNER + dc]);
        const float* Cv = sC[t];
        float corr = 0.f;
        if (fast) {
            float q = __expf(cu * Av0);
            float p = 1.f;
            #pragma unroll
            for (int s = 0; s < 16; ++s) {
                p *= q;
                corr = fmaf(p * h0[s], Cv[s], corr);
            }
        } else {
            #pragma unroll
            for (int s = 0; s < 16; ++s)
                corr = fmaf(__expf(cu * Av[s]) * h0[s], Cv[s], corr);
        }
        if (act) {
            float y = yl + corr;
            y2[gi] = __float2bfloat16((y + uv * Dv) * (z / (1.f + __expf(-z))));
        }
    }
}

// -------- weight packing --------
__global__ void pack1_kernel(const float* __restrict__ ipw, bf16* __restrict__ win) {
    int i = blockIdx.x * 256 + threadIdx.x;
    int total = N_LAYERS * 1032 * 258;
    if (i >= total) return;
    int k = i % 258, nr = i / 258, n = nr % 1032, l = nr / 1032;
    win[((size_t)l * WIN_R + n) * KM + k] = __float2bfloat16(ipw[i]);
}
__global__ void pack2_kernel(const float* __restrict__ opw, const float* __restrict__ xpw,
                             bf16* __restrict__ wout, bf16* __restrict__ wxp) {
    int i = blockIdx.x * 256 + threadIdx.x;
    const int OUT_T = N_LAYERS * 258 * 516, XP_T = N_LAYERS * 49 * 516;
    if (i < OUT_T) {
        int k = i % 516, nr = i / 516, n = nr % 258, l = nr / 258;
        wout[((size_t)l * WOUT_R + n) * KI + k] = __float2bfloat16(opw[i]);
    } else if (i < OUT_T + XP_T) {
        int j = i - OUT_T;
        int k = j % 516, nr = j / 516, n = nr % 49, l = nr / 49;
        wxp[((size_t)l * WXP_R + n) * KI + k] = __float2bfloat16(xpw[j]);
    }
}

// -------- host --------
extern "C" void kernel_launch(void* const* d_in, const int* in_sizes, int n_in,
                              void* d_out, int out_size) {
    const float* fuse  = (const float*)d_in[0];
    const float* nwv   = (const float*)d_in[1];
    const float* ipw   = (const float*)d_in[2];
    const float* cwv   = (const float*)d_in[3];
    const float* cbv   = (const float*)d_in[4];
    const float* xpw   = (const float*)d_in[5];
    const float* dtwv  = (const float*)d_in[6];
    const float* dtbv  = (const float*)d_in[7];
    const float* Alv   = (const float*)d_in[8];
    const float* Dpv   = (const float*)d_in[9];
    const float* opw   = (const float*)d_in[10];
    const float* fw    = (const float*)d_in[11];
    float* out = (float*)d_out;

    float *p_x, *p_xdbl, *p_L, *p_H0, *p_sdt, *p_cum;
    bf16 *p_xn, *p_xz, *p_xc, *p_y2, *p_win, *p_wout, *p_wxp;
    cudaGetSymbolAddress((void**)&p_x, g_x);
    cudaGetSymbolAddress((void**)&p_xn, g_xn);
    cudaGetSymbolAddress((void**)&p_xz, g_xz);
    cudaGetSymbolAddress((void**)&p_xc, g_xc);
    cudaGetSymbolAddress((void**)&p_xdbl, g_xdbl);
    cudaGetSymbolAddress((void**)&p_y2, g_y2);
    cudaGetSymbolAddress((void**)&p_cum, g_cum);
    cudaGetSymbolAddress((void**)&p_win, g_win);
    cudaGetSymbolAddress((void**)&p_wout, g_wout);
    cudaGetSymbolAddress((void**)&p_wxp, g_wxp);
    cudaGetSymbolAddress((void**)&p_L, g_L);
    cudaGetSymbolAddress((void**)&p_H0, g_H0);
    cudaGetSymbolAddress((void**)&p_sdt, g_sdt);

    // smem sizes: NSTAGE * (BM+BN) * AW * 4 bytes
    const int SM_BIG = 3 * (64 + 128) * AW * 4;   // 46080 -> up to 4 CTAs/SM
    const int SM_XP  = 3 * (32 + 64) * AW * 4;    // 23040
    cudaFuncSetAttribute((const void*)gemm_bf16<64, 128, 2, 3>,
                         cudaFuncAttributeMaxDynamicSharedMemorySize, SM_BIG);
    cudaFuncSetAttribute((const void*)gemm_bf16<64, 128, 1, 3>,
                         cudaFuncAttributeMaxDynamicSharedMemorySize, SM_BIG);

    pack1_kernel<<<(N_LAYERS * 1032 * 258 + 255) / 256, 256>>>(ipw, p_win);
    {
        int tot = N_LAYERS * 258 * 516 + N_LAYERS * 49 * 516;
        pack2_kernel<<<(tot + 255) / 256, 256>>>(opw, xpw, p_wout, p_wxp);
    }
    cudaMemcpyAsync(p_x, fuse, (size_t)NTOK * D_MODEL * sizeof(float),
                    cudaMemcpyDeviceToDevice);

    for (int l = 0; l < N_LAYERS; ++l) {
        const float* Al = Alv + (size_t)l * D_INNER * 16;
        const float* dtw = dtwv + (size_t)l * D_INNER * DT_RANK;
        const float* dtb = dtbv + (size_t)l * D_INNER;
        rmsnorm_kernel<<<NTOK / 8, 256>>>(p_x, nwv + (size_t)l * D_MODEL, p_xn, KM);
        gemm_bf16<64, 128, 2, 3><<<dim3(9, 128), 256, SM_BIG>>>(
            p_xn, p_win + (size_t)l * WIN_R * KM, p_xz, TWO_DI, KM, KM, TWO_DI);
        conv_silu_kernel<<<dim3(5, L_SEQ / CLT, B_SZ), 128>>>(
            p_xz, cwv + (size_t)l * D_INNER * 4, cbv + (size_t)l * D_INNER, p_xc);
        gemm_bf16<32, 64, 0, 3><<<dim3(1, 256), 256, SM_XP>>>(
            p_xc, p_wxp + (size_t)l * WXP_R * KI, p_xdbl, 49, KI, KI, XW);
        scanA_kernel<<<dim3(5, NCHK, B_SZ), 128>>>(
            p_xc, p_xdbl, Al, dtw, dtb, p_L, p_sdt, p_y2, p_cum);
        scan2_kernel<<<(B_SZ * D_INNER * D_STATE + 127) / 128, 128>>>(
            p_L, p_sdt, Al, p_H0);
        scanC_kernel<<<dim3(5, NCHK, B_SZ), 128>>>(
            p_xc, p_xdbl, p_xz, Al, Dpv + (size_t)l * D_INNER, p_H0, p_cum, p_y2);
        gemm_bf16<64, 128, 1, 3><<<dim3(3, 128), 256, SM_BIG>>>(
            p_y2, p_wout + (size_t)l * WOUT_R * KI, p_x, D_MODEL, KI, KI, D_MODEL);
    }
    final_kernel<<<NTOK / 8, 256>>>(fuse, p_x, fw, out);
    (void)in_sizes; (void)n_in; (void)out_size;
}

// round 13
// speedup vs baseline: 3.9084x; 1.0431x over previous
#include <cuda_runtime.h>
#include <cuda_bf16.h>
#include <math.h>
#include <stdint.h>

#define B_SZ 4
#define L_SEQ 2048
#define D_MODEL 258
#define N_LAYERS 4
#define D_STATE 16
#define D_INNER 516
#define DT_RANK 17
#define TWO_DI 1032
#define XW 56            // padded xdbl stride (49 real cols)
#define NTOK 8192
#define EPS 1e-5f
#define KM 288           // 258 padded to 32-chunks
#define KI 544           // 516 padded
#define WIN_R 1152       // 9 * 128
#define WOUT_R 320       // 5 * 64
#define WXP_R 64
#define NCHK 128         // scan chunks
#define SCT 16           // tokens per scan chunk

typedef __nv_bfloat16 bf16;

// -------- device scratch (zero-init; +pad for vectorized edge reads) --------
__device__ __align__(256) float g_x[NTOK * D_MODEL];
__device__ __align__(256) bf16  g_xn[NTOK * KM];
__device__ __align__(256) bf16  g_xz[NTOK * TWO_DI + 256];
__device__ __align__(256) bf16  g_xc[NTOK * KI + 256];
__device__ __align__(256) float g_xdbl[NTOK * XW];
__device__ __align__(256) bf16  g_y2[NTOK * KI + 256];
__device__ __align__(256) float g_cum[NTOK * KI + 256];
__device__ __align__(256) bf16  g_win[N_LAYERS * WIN_R * KM];
__device__ __align__(256) bf16  g_wout[N_LAYERS * WOUT_R * KI];
__device__ __align__(256) bf16  g_wxp[N_LAYERS * WXP_R * KI];
__device__ __align__(256) float g_L[B_SZ * NCHK * D_INNER * D_STATE];
__device__ __align__(256) float g_H0[B_SZ * NCHK * D_INNER * D_STATE];
__device__ __align__(256) float g_sdt[B_SZ * NCHK * D_INNER];

// -------- helpers --------
__device__ __forceinline__ uint32_t smem_u32(const void* p) {
    uint32_t a;
    asm("{ .reg .u64 t; cvta.to.shared.u64 t, %1; cvt.u32.u64 %0, t; }" : "=r"(a) : "l"(p));
    return a;
}
__device__ __forceinline__ void cp_async16(uint32_t dst, const void* src) {
    asm volatile("cp.async.cg.shared.global [%0], [%1], 16;" :: "r"(dst), "l"(src));
}
#define CP_COMMIT() asm volatile("cp.async.commit_group;" ::: "memory")

__device__ __forceinline__ void mma_bf16(float* d, const uint32_t* a, const uint32_t* b) {
    asm volatile(
        "mma.sync.aligned.m16n8k16.row.col.f32.bf16.bf16.f32 "
        "{%0,%1,%2,%3},{%4,%5,%6,%7},{%8,%9},{%0,%1,%2,%3};"
        : "+f"(d[0]), "+f"(d[1]), "+f"(d[2]), "+f"(d[3])
        : "r"(a[0]), "r"(a[1]), "r"(a[2]), "r"(a[3]), "r"(b[0]), "r"(b[1]));
}
__device__ __forceinline__ void ldsm_x4(uint32_t* r, uint32_t addr) {
    asm volatile("ldmatrix.sync.aligned.m8n8.x4.shared.b16 {%0,%1,%2,%3}, [%4];"
        : "=r"(r[0]), "=r"(r[1]), "=r"(r[2]), "=r"(r[3]) : "r"(addr));
}
__device__ __forceinline__ void ldsm_x2(uint32_t* r, uint32_t addr) {
    asm volatile("ldmatrix.sync.aligned.m8n8.x2.shared.b16 {%0,%1}, [%2];"
        : "=r"(r[0]), "=r"(r[1]) : "r"(addr));
}

// -------- bf16 mma GEMM: C[8192,N] = A[8192,K]bf16 @ W[N,K]bf16^T --------
#define AW 20            // smem row stride in words (40 bf16) — LDSM conflict-free
template <int BM, int BN, int OUTMODE, int NSTAGE>
__global__ __launch_bounds__(256) void gemm_bf16(
    const bf16* __restrict__ A, const bf16* __restrict__ W,
    void* __restrict__ Cv, int N_store, int K, int lda, int ldc) {
    constexpr int MW = BM / 32;
    constexpr int NW = 8 / MW;
    constexpr int WN = BN / NW;
    constexpr int NT = WN / 8;
    constexpr int ASTG = BM * AW, BSTG = BN * AW, STG = ASTG + BSTG;
    extern __shared__ uint32_t sm[];
    const int tid = threadIdx.x, wid = tid >> 5, lane = tid & 31;
    const int warpM = wid % MW, warpN = wid / MW;
    const int quad = lane >> 2, qk = lane & 3;
    const int bm = blockIdx.y * BM, bn = blockIdx.x * BN;
    float acc[2][NT][4];
    #pragma unroll
    for (int i = 0; i < 2; ++i)
        #pragma unroll
        for (int j = 0; j < NT; ++j)
            #pragma unroll
            for (int k = 0; k < 4; ++k) acc[i][j][k] = 0.f;

    const bf16* Ab = A + (size_t)bm * lda;
    const bf16* Wb = W + (size_t)bn * K;
    const int nch = K >> 5;
    const uint32_t sm_u = smem_u32(sm);
    const int l8 = lane & 7, jm = lane >> 3;

    const uint32_t aLM = sm_u +
        (uint32_t)(((warpM * 32 + ((jm & 1) << 3) + l8) * AW + ((jm >> 1) << 2)) * 4);
    const uint32_t bLM4 = sm_u + ASTG * 4 +
        (uint32_t)(((warpN * WN + ((jm >> 1) << 3) + l8) * AW + ((jm & 1) << 2)) * 4);
    const uint32_t bLM2 = sm_u + ASTG * 4 +
        (uint32_t)(((warpN * WN + l8) * AW + (((lane >> 3) & 1) << 2)) * 4);

    auto load_chunk = [&](int c, int st) {
        const bf16* Ac = Ab + c * 32;
        #pragma unroll
        for (int fi = tid; fi < BM * 4; fi += 256) {
            int r = fi >> 2, sg = fi & 3;
            cp_async16(sm_u + (uint32_t)(st * STG + r * AW + sg * 4) * 4,
                       Ac + (size_t)r * lda + sg * 8);
        }
        const bf16* Wc = Wb + c * 32;
        #pragma unroll
        for (int fi = tid; fi < BN * 4; fi += 256) {
            int r = fi >> 2, sg = fi & 3;
            cp_async16(sm_u + (uint32_t)(st * STG + ASTG + r * AW + sg * 4) * 4,
                       Wc + (size_t)r * K + sg * 8);
        }
    };

    #pragma unroll
    for (int p = 0; p < NSTAGE - 1; ++p) {
        if (p < nch) load_chunk(p, p);
        CP_COMMIT();
    }

    for (int c = 0; c < nch; ++c) {
        asm volatile("cp.async.wait_group %0;" :: "n"(NSTAGE - 2) : "memory");
        __syncthreads();
        int nx = c + NSTAGE - 1;
        if (nx < nch) load_chunk(nx, nx % NSTAGE);
        CP_COMMIT();
        const uint32_t stOff = (uint32_t)((c % NSTAGE) * STG * 4);
        #pragma unroll
        for (int ks = 0; ks < 2; ++ks) {
            uint32_t a[2][4], b[NT][2];
            #pragma unroll
            for (int mt = 0; mt < 2; ++mt)
                ldsm_x4(a[mt], aLM + stOff + (uint32_t)(mt * 16 * AW * 4 + ks * 32));
            if (NT == 1) {
                ldsm_x2(b[0], bLM2 + stOff + (uint32_t)(ks * 32));
            } else {
                #pragma unroll
                for (int p = 0; p < NT / 2; ++p) {
                    uint32_t t4[4];
                    ldsm_x4(t4, bLM4 + stOff + (uint32_t)(p * 16 * AW * 4 + ks * 32));
                    b[2*p][0] = t4[0]; b[2*p][1] = t4[1];
                    b[2*p+1][0] = t4[2]; b[2*p+1][1] = t4[3];
                }
            }
            #pragma unroll
            for (int mt = 0; mt < 2; ++mt)
                #pragma unroll
                for (int nt = 0; nt < NT; ++nt)
                    mma_bf16(acc[mt][nt], a[mt], b[nt]);
        }
    }
    __syncthreads();

    #pragma unroll
    for (int mt = 0; mt < 2; ++mt) {
        int r0 = bm + warpM * 32 + mt * 16 + quad;
        #pragma unroll
        for (int nt = 0; nt < NT; ++nt) {
            int gc = bn + warpN * WN + nt * 8 + qk * 2;
            #pragma unroll
            for (int half = 0; half < 2; ++half) {
                int row = r0 + half * 8;
                float v0 = acc[mt][nt][half * 2 + 0];
                float v1 = acc[mt][nt][half * 2 + 1];
                size_t gi = (size_t)row * ldc + gc;
                if (OUTMODE == 2) {
                    bf16* C = (bf16*)Cv;
                    if (gc < N_store) C[gi] = __float2bfloat16(v0);
                    if (gc + 1 < N_store) C[gi + 1] = __float2bfloat16(v1);
                } else {
                    float* C = (float*)Cv;
                    if (gc < N_store) {
                        if (OUTMODE == 1) v0 += C[gi];
                        C[gi] = v0;
                    }
                    if (gc + 1 < N_store) {
                        if (OUTMODE == 1) v1 += C[gi + 1];
                        C[gi + 1] = v1;
                    }
                }
            }
        }
    }
}

// -------- rmsnorm: warp per token, bf16 out --------
__global__ void rmsnorm_kernel(const float* __restrict__ x, const float* __restrict__ w,
                               bf16* __restrict__ o, int ldo) {
    int tok = (blockIdx.x * blockDim.x + threadIdx.x) >> 5;
    int lane = threadIdx.x & 31;
    if (tok >= NTOK) return;
    const float* xr = x + (size_t)tok * D_MODEL;
    float ss = 0.f;
    for (int i = lane; i < D_MODEL; i += 32) { float v = xr[i]; ss += v * v; }
    #pragma unroll
    for (int off = 16; off; off >>= 1) ss += __shfl_xor_sync(~0u, ss, off);
    float inv = rsqrtf(ss * (1.f / D_MODEL) + EPS);
    for (int i = lane; i < D_MODEL; i += 32)
        o[(size_t)tok * ldo + i] = __float2bfloat16(xr[i] * inv * w[i]);
}

__global__ void final_kernel(const float* __restrict__ f, const float* __restrict__ x,
                             const float* __restrict__ w, float* __restrict__ o) {
    int tok = (blockIdx.x * blockDim.x + threadIdx.x) >> 5;
    int lane = threadIdx.x & 31;
    if (tok >= NTOK) return;
    const float* xr = x + (size_t)tok * D_MODEL;
    float ss = 0.f;
    for (int i = lane; i < D_MODEL; i += 32) { float v = xr[i]; ss += v * v; }
    #pragma unroll
    for (int off = 16; off; off >>= 1) ss += __shfl_xor_sync(~0u, ss, off);
    float inv = rsqrtf(ss * (1.f / D_MODEL) + EPS);
    for (int i = lane; i < D_MODEL; i += 32)
        o[(size_t)tok * D_MODEL + i] = f[(size_t)tok * D_MODEL + i] + xr[i] * inv * w[i];
}

// -------- conv(k=4, causal) + silu: register window over 16-token tiles --------
#define CLT 16
__global__ void conv_silu_kernel(const bf16* __restrict__ xz, const float* __restrict__ cw,
                                 const float* __restrict__ cb, bf16* __restrict__ xc) {
    int d = blockIdx.x * 128 + threadIdx.x;
    if (d >= D_INNER) return;
    int l0 = blockIdx.y * CLT, b = blockIdx.z;
    float w0 = cw[d * 4 + 0], w1 = cw[d * 4 + 1], w2 = cw[d * 4 + 2], w3 = cw[d * 4 + 3];
    float bb = cb[d];
    size_t row = (size_t)b * L_SEQ + l0;
    const bf16* src = xz + row * TWO_DI + d;
    bf16* dst = xc + row * KI + d;
    float x0, x1, x2;
    if (l0 == 0) { x0 = x1 = x2 = 0.f; }
    else {
        x0 = __bfloat162float(src[-3 * TWO_DI]);
        x1 = __bfloat162float(src[-2 * TWO_DI]);
        x2 = __bfloat162float(src[-1 * TWO_DI]);
    }
    #pragma unroll
    for (int i = 0; i < CLT; ++i) {
        float x3 = __bfloat162float(src[(size_t)i * TWO_DI]);
        float acc = bb + w0 * x0 + w1 * x1 + w2 * x2 + w3 * x3;
        dst[(size_t)i * KI] = __float2bfloat16(acc / (1.f + __expf(-acc)));
        x0 = x1; x1 = x2; x2 = x3;
    }
}

// -------- chunked selective scan (single serial pass + parallel fixup) ----
__device__ __forceinline__ float softplus_f(float a) {
    return (a > 15.f) ? a : log1pf(__expf(a));
}
__device__ __forceinline__ bool a_is_arange(const float* Av) {
    bool ok = Av[0] < 0.f;
    #pragma unroll
    for (int s = 1; s < 16; ++s)
        ok = ok && (fabsf(Av[s] - (float)(s + 1) * Av[0]) <= 1e-4f * fabsf(Av[s]));
    return ok;
}

// scanA: serial pass with h0=0. Emits ylocal, cumdt, chunk summary Lc + sum(dt).
__global__ __launch_bounds__(128) void scanA_kernel(
    const bf16* __restrict__ u, const float* __restrict__ xdbl,
    const float* __restrict__ A_log, const float* __restrict__ dtw,
    const float* __restrict__ dtb, float* __restrict__ Lc, float* __restrict__ sdtc,
    bf16* __restrict__ yloc, float* __restrict__ cum) {
    __shared__ float sDL[SCT][18];
    __shared__ float sB[SCT][16];
    __shared__ float sC[SCT][16];
    __shared__ bf16 s_u[SCT][128];
    int b = blockIdx.z, c = blockIdx.y, d0 = blockIdx.x * 128;
    int tid = threadIdx.x;
    int d = d0 + tid;
    bool act = d < D_INNER;
    int dc = act ? d : (D_INNER - 1);
    size_t rb = (size_t)b * L_SEQ + (size_t)c * SCT;
    float Av[16];
    #pragma unroll
    for (int s = 0; s < 16; s += 4) {
        float4 al = *(const float4*)(A_log + (size_t)dc * 16 + s);
        Av[s + 0] = -__expf(al.x); Av[s + 1] = -__expf(al.y);
        Av[s + 2] = -__expf(al.z); Av[s + 3] = -__expf(al.w);
    }
    const bool fast = a_is_arange(Av);
    const float Av0 = Av[0];
    float wv[DT_RANK];
    #pragma unroll
    for (int r = 0; r < DT_RANK; ++r) wv[r] = dtw[(size_t)dc * DT_RANK + r];
    float bias = dtb[dc];
    for (int i = tid; i < SCT * 16; i += 128) {
        int t = i >> 4, s = i & 15;
        const float* g = xdbl + (rb + t) * XW + DT_RANK;
        sB[t][s] = g[s];
        sC[t][s] = g[16 + s];
    }
    for (int i = tid; i < SCT * DT_RANK; i += 128) {
        int t = i / DT_RANK, r = i - t * DT_RANK;
        sDL[t][r] = xdbl[(rb + t) * XW + r];
    }
    for (int q = tid; q < SCT * 64; q += 128) {
        int tt = q >> 6, dp = (q & 63) * 2;
        *(uint32_t*)&s_u[tt][dp] = *(const uint32_t*)(u + (rb + tt) * KI + d0 + dp);
    }
    __syncthreads();
    float h[16];
    #pragma unroll
    for (int s = 0; s < 16; ++s) h[s] = 0.f;
    float sd = 0.f;
    #pragma unroll 4
    for (int t = 0; t < SCT; ++t) {
        float dta = bias;
        const float* dl = sDL[t];
        #pragma unroll
        for (int r = 0; r < DT_RANK; ++r) dta = fmaf(dl[r], wv[r], dta);
        float dtv = softplus_f(dta);
        float uv = __bfloat162float(s_u[t][tid]);
        float e = dtv * uv;
        sd += dtv;
        const float4* pB = (const float4*)sB[t];
        const float4* pC = (const float4*)sC[t];
        float y = 0.f;
        if (fast) {
            float q = __expf(dtv * Av0);
            float p = 1.f;
            #pragma unroll
            for (int s4 = 0; s4 < 4; ++s4) {
                float4 Bv = pB[s4];
                float4 Cv = pC[s4];
                p *= q; h[s4*4+0] = fmaf(p, h[s4*4+0], e * Bv.x);
                p *= q; h[s4*4+1] = fmaf(p, h[s4*4+1], e * Bv.y);
                p *= q; h[s4*4+2] = fmaf(p, h[s4*4+2], e * Bv.z);
                p *= q; h[s4*4+3] = fmaf(p, h[s4*4+3], e * Bv.w);
                y += h[s4*4+0] * Cv.x + h[s4*4+1] * Cv.y
                   + h[s4*4+2] * Cv.z + h[s4*4+3] * Cv.w;
            }
        } else {
            #pragma unroll
            for (int s4 = 0; s4 < 4; ++s4) {
                float4 Bv = pB[s4];
                float4 Cv = pC[s4];
                h[s4*4+0] = fmaf(__expf(dtv * Av[s4*4+0]), h[s4*4+0], e * Bv.x);
                h[s4*4+1] = fmaf(__expf(dtv * Av[s4*4+1]), h[s4*4+1], e * Bv.y);
                h[s4*4+2] = fmaf(__expf(dtv * Av[s4*4+2]), h[s4*4+2], e * Bv.z);
                h[s4*4+3] = fmaf(__expf(dtv * Av[s4*4+3]), h[s4*4+3], e * Bv.w);
                y += h[s4*4+0] * Cv.x + h[s4*4+1] * Cv.y
                   + h[s4*4+2] * Cv.z + h[s4*4+3] * Cv.w;
            }
        }
        if (act) {
            yloc[(rb + t) * KI + d] = __float2bfloat16(y);
            cum[(rb + t) * KI + d] = sd;
        }
    }
    if (act) {
        size_t o = ((size_t)b * NCHK + c) * D_INNER + d;
        float4* pL = (float4*)(Lc + o * 16);
        #pragma unroll
        for (int s4 = 0; s4 < 4; ++s4)
            pL[s4] = make_float4(h[s4*4+0], h[s4*4+1], h[s4*4+2], h[s4*4+3]);
        sdtc[o] = sd;
    }
}

// scan2: stitch chunk summaries -> initial state per chunk
__global__ void scan2_kernel(const float* __restrict__ Lc, const float* __restrict__ sdtc,
                             const float* __restrict__ A_log, float* __restrict__ H0) {
    int idx = blockIdx.x * 128 + threadIdx.x;
    if (idx >= B_SZ * D_INNER * D_STATE) return;
    int s = idx & 15, rest = idx >> 4;
    int d = rest % D_INNER, b = rest / D_INNER;
    float Av = -__expf(A_log[(size_t)d * 16 + s]);
    float h = 0.f;
    #pragma unroll 8
    for (int c = 0; c < NCHK; ++c) {
        size_t o = (((size_t)b * NCHK + c) * D_INNER + d);
        H0[o * 16 + s] = h;
        h = __expf(Av * sdtc[o]) * h + Lc[o * 16 + s];
    }
}

// scanC: parallel fixup: y = ylocal + C·(P(cumdt)·H0); then +u*D and gate.
__global__ __launch_bounds__(128) void scanC_kernel(
    const bf16* __restrict__ u, const float* __restrict__ xdbl,
    const bf16* __restrict__ xz, const float* __restrict__ A_log,
    const float* __restrict__ Dp, const float* __restrict__ H0,
    const float* __restrict__ cum, bf16* __restrict__ y2) {
    __shared__ float sC[SCT][16];
    int b = blockIdx.z, c = blockIdx.y, d0 = blockIdx.x * 128;
    int tid = threadIdx.x;
    int d = d0 + tid;
    bool act = d < D_INNER;
    int dc = act ? d : (D_INNER - 1);
    size_t rb = (size_t)b * L_SEQ + (size_t)c * SCT;
    float Av[16];
    #pragma unroll
    for (int s = 0; s < 16; s += 4) {
        float4 al = *(const float4*)(A_log + (size_t)dc * 16 + s);
        Av[s + 0] = -__expf(al.x); Av[s + 1] = -__expf(al.y);
        Av[s + 2] = -__expf(al.z); Av[s + 3] = -__expf(al.w);
    }
    const bool fast = a_is_arange(Av);
    const float Av0 = Av[0];
    float Dv = Dp[dc];
    float h0[16];
    {
        size_t o = ((size_t)b * NCHK + c) * D_INNER + dc;
        const float4* pH = (const float4*)(H0 + o * 16);
        #pragma unroll
        for (int s4 = 0; s4 < 4; ++s4) {
            float4 hv = pH[s4];
            h0[s4*4+0] = hv.x; h0[s4*4+1] = hv.y; h0[s4*4+2] = hv.z; h0[s4*4+3] = hv.w;
        }
    }
    for (int i = tid; i < SCT * 16; i += 128) {
        int t = i >> 4, s = i & 15;
        sC[t][s] = xdbl[(rb + t) * XW + DT_RANK + 16 + s];
    }
    __syncthreads();
    #pragma unroll 4
    for (int t = 0; t < SCT; ++t) {
        size_t gi = (rb + t) * KI + (size_t)dc;
        float cu = cum[gi];
        float yl = __bfloat162float(y2[gi]);
        float uv = __bfloat162float(u[gi]);
        float z = __bfloat162float(xz[(rb + t) * TWO_DI + D_INNER + dc]);
        const float* Cv = sC[t];
        float corr = 0.f;
        if (fast) {
            float q = __expf(cu * Av0);
            float p = 1.f;
            #pragma unroll
            for (int s = 0; s < 16; ++s) {
                p *= q;
                corr = fmaf(p * h0[s], Cv[s], corr);
            }
        } else {
            #pragma unroll
            for (int s = 0; s < 16; ++s)
                corr = fmaf(__expf(cu * Av[s]) * h0[s], Cv[s], corr);
        }
        if (act) {
            float y = yl + corr;
            y2[gi] = __float2bfloat16((y + uv * Dv) * (z / (1.f + __expf(-z))));
        }
    }
}

// -------- weight packing --------
__global__ void pack1_kernel(const float* __restrict__ ipw, bf16* __restrict__ win) {
    int i = blockIdx.x * 256 + threadIdx.x;
    int total = N_LAYERS * 1032 * 258;
    if (i >= total) return;
    int k = i % 258, nr = i / 258, n = nr % 1032, l = nr / 1032;
    win[((size_t)l * WIN_R + n) * KM + k] = __float2bfloat16(ipw[i]);
}
__global__ void pack2_kernel(const float* __restrict__ opw, const float* __restrict__ xpw,
                             bf16* __restrict__ wout, bf16* __restrict__ wxp) {
    int i = blockIdx.x * 256 + threadIdx.x;
    const int OUT_T = N_LAYERS * 258 * 516, XP_T = N_LAYERS * 49 * 516;
    if (i < OUT_T) {
        int k = i % 516, nr = i / 516, n = nr % 258, l = nr / 258;
        wout[((size_t)l * WOUT_R + n) * KI + k] = __float2bfloat16(opw[i]);
    } else if (i < OUT_T + XP_T) {
        int j = i - OUT_T;
        int k = j % 516, nr = j / 516, n = nr % 49, l = nr / 49;
        wxp[((size_t)l * WXP_R + n) * KI + k] = __float2bfloat16(xpw[j]);
    }
}

// -------- host --------
extern "C" void kernel_launch(void* const* d_in, const int* in_sizes, int n_in,
                              void* d_out, int out_size) {
    const float* fuse  = (const float*)d_in[0];
    const float* nwv   = (const float*)d_in[1];
    const float* ipw   = (const float*)d_in[2];
    const float* cwv   = (const float*)d_in[3];
    const float* cbv   = (const float*)d_in[4];
    const float* xpw   = (const float*)d_in[5];
    const float* dtwv  = (const float*)d_in[6];
    const float* dtbv  = (const float*)d_in[7];
    const float* Alv   = (const float*)d_in[8];
    const float* Dpv   = (const float*)d_in[9];
    const float* opw   = (const float*)d_in[10];
    const float* fw    = (const float*)d_in[11];
    float* out = (float*)d_out;

    float *p_x, *p_xdbl, *p_L, *p_H0, *p_sdt, *p_cum;
    bf16 *p_xn, *p_xz, *p_xc, *p_y2, *p_win, *p_wout, *p_wxp;
    cudaGetSymbolAddress((void**)&p_x, g_x);
    cudaGetSymbolAddress((void**)&p_xn, g_xn);
    cudaGetSymbolAddress((void**)&p_xz, g_xz);
    cudaGetSymbolAddress((void**)&p_xc, g_xc);
    cudaGetSymbolAddress((void**)&p_xdbl, g_xdbl);
    cudaGetSymbolAddress((void**)&p_y2, g_y2);
    cudaGetSymbolAddress((void**)&p_cum, g_cum);
    cudaGetSymbolAddress((void**)&p_win, g_win);
    cudaGetSymbolAddress((void**)&p_wout, g_wout);
    cudaGetSymbolAddress((void**)&p_wxp, g_wxp);
    cudaGetSymbolAddress((void**)&p_L, g_L);
    cudaGetSymbolAddress((void**)&p_H0, g_H0);
    cudaGetSymbolAddress((void**)&p_sdt, g_sdt);

    // smem sizes: NSTAGE * (BM+BN) * AW * 4 bytes
    const int SM_IN  = 3 * (64 + 128) * AW * 4;   // 46080
    const int SM_OUT = 3 * (64 + 64) * AW * 4;    // 30720
    const int SM_XP  = 3 * (32 + 64) * AW * 4;    // 23040
    cudaFuncSetAttribute((const void*)gemm_bf16<64, 128, 2, 3>,
                         cudaFuncAttributeMaxDynamicSharedMemorySize, SM_IN);

    pack1_kernel<<<(N_LAYERS * 1032 * 258 + 255) / 256, 256>>>(ipw, p_win);
    {
        int tot = N_LAYERS * 258 * 516 + N_LAYERS * 49 * 516;
        pack2_kernel<<<(tot + 255) / 256, 256>>>(opw, xpw, p_wout, p_wxp);
    }
    cudaMemcpyAsync(p_x, fuse, (size_t)NTOK * D_MODEL * sizeof(float),
                    cudaMemcpyDeviceToDevice);

    for (int l = 0; l < N_LAYERS; ++l) {
        const float* Al = Alv + (size_t)l * D_INNER * 16;
        const float* dtw = dtwv + (size_t)l * D_INNER * DT_RANK;
        const float* dtb = dtbv + (size_t)l * D_INNER;
        rmsnorm_kernel<<<NTOK / 8, 256>>>(p_x, nwv + (size_t)l * D_MODEL, p_xn, KM);
        gemm_bf16<64, 128, 2, 3><<<dim3(9, 128), 256, SM_IN>>>(
            p_xn, p_win + (size_t)l * WIN_R * KM, p_xz, TWO_DI, KM, KM, TWO_DI);
        conv_silu_kernel<<<dim3(5, L_SEQ / CLT, B_SZ), 128>>>(
            p_xz, cwv + (size_t)l * D_INNER * 4, cbv + (size_t)l * D_INNER, p_xc);
        gemm_bf16<32, 64, 0, 3><<<dim3(1, 256), 256, SM_XP>>>(
            p_xc, p_wxp + (size_t)l * WXP_R * KI, p_xdbl, 49, KI, KI, XW);
        scanA_kernel<<<dim3(5, NCHK, B_SZ), 128>>>(
            p_xc, p_xdbl, Al, dtw, dtb, p_L, p_sdt, p_y2, p_cum);
        scan2_kernel<<<(B_SZ * D_INNER * D_STATE + 127) / 128, 128>>>(
            p_L, p_sdt, Al, p_H0);
        scanC_kernel<<<dim3(5, NCHK, B_SZ), 128>>>(
            p_xc, p_xdbl, p_xz, Al, Dpv + (size_t)l * D_INNER, p_H0, p_cum, p_y2);
        gemm_bf16<64, 64, 1, 3><<<dim3(5, 128), 256, SM_OUT>>>(
            p_y2, p_wout + (size_t)l * WOUT_R * KI, p_x, D_MODEL, KI, KI, D_MODEL);
    }
    final_kernel<<<NTOK / 8, 256>>>(fuse, p_x, fw, out);
    (void)in_sizes; (void)n_in; (void)out_size;
}